// round 11
// baseline (speedup 1.0000x reference)
#include <cuda_runtime.h>
#include <cuda_bf16.h>
#include <cfloat>
#include <cstdint>

#define EPS_S   0.01f
#define INV_EPS 100.0f
#define LOG_MU  -6.93146200f   /* log(1/1024 + 1e-8) */
#define BN_EPS  1e-5f

typedef unsigned short ushort_t;

/* ---------------- scratch (device globals: no allocs allowed) -------------- */
__device__ float g_C[4 * 1024 * 1024];          /* cost matrix; later tblend NCHW */
__device__ float g_u[4096], g_v[4096];
__device__ float g_rnx[4096], g_rny[4096];
__device__ float g_t[4 * 1024 * 512];           /* t NHWC fp32 [pix][512] */
__device__ float g_a1[4 * 1024 * 256];
__device__ float g_a2[4 * 1024 * 256];
__device__ float g_alpha[4 * 1024 * 512];
__device__ float g_cm[2048], g_rs[2048];
__device__ float g_scale[512], g_shift[512];
__device__ float g_ps[256 * 256], g_pq[256 * 256];
/* bf16 split buffers */
__device__ ushort_t g_cTh[4 * 1024 * 512], g_cTl[4 * 1024 * 512];
__device__ ushort_t g_sTh[4 * 1024 * 512], g_sTl[4 * 1024 * 512];
__device__ ushort_t g_sfh[4 * 512 * 1024], g_sfl[4 * 512 * 1024];
__device__ ushort_t g_pih[4 * 1024 * 1024], g_pil[4 * 1024 * 1024];
__device__ ushort_t g_tth[4 * 1024 * 512], g_ttl[4 * 1024 * 512];
__device__ ushort_t g_b1h[4 * 1024 * 256], g_b1l[4 * 1024 * 256];
__device__ ushort_t g_b2h[4 * 1024 * 256], g_b2l[4 * 1024 * 256];
__device__ ushort_t g_w1h[9 * 256 * 1024], g_w1l[9 * 256 * 1024];
__device__ ushort_t g_w2h[9 * 256 * 256],  g_w2l[9 * 256 * 256];
__device__ ushort_t g_w3h[9 * 512 * 256],  g_w3l[9 * 512 * 256];

__device__ __forceinline__ uint32_t smem_u32(const void* p) {
    uint32_t a;
    asm("{ .reg .u64 t; cvta.to.shared.u64 t, %1; cvt.u32.u64 %0, t; }"
        : "=r"(a) : "l"(p));
    return a;
}
__device__ __forceinline__ void ldsm_x4(uint32_t& r0, uint32_t& r1,
                                        uint32_t& r2, uint32_t& r3, uint32_t a) {
    asm volatile("ldmatrix.sync.aligned.m8n8.x4.shared.b16 {%0,%1,%2,%3}, [%4];"
                 : "=r"(r0), "=r"(r1), "=r"(r2), "=r"(r3) : "r"(a));
}
__device__ __forceinline__ void mma_bf16(float& d0, float& d1, float& d2, float& d3,
                                         uint32_t a0, uint32_t a1, uint32_t a2, uint32_t a3,
                                         uint32_t b0, uint32_t b1) {
    asm volatile(
        "mma.sync.aligned.m16n8k16.row.col.f32.bf16.bf16.f32 "
        "{%0,%1,%2,%3}, {%4,%5,%6,%7}, {%8,%9}, {%0,%1,%2,%3};"
        : "+f"(d0), "+f"(d1), "+f"(d2), "+f"(d3)
        : "r"(a0), "r"(a1), "r"(a2), "r"(a3), "r"(b0), "r"(b1));
}
__device__ __forceinline__ void bsplit(float v, ushort_t& h, ushort_t& l) {
    __nv_bfloat16 hh = __float2bfloat16(v);
    float rem = v - __bfloat162float(hh);
    __nv_bfloat16 ll = __float2bfloat16(rem);
    h = __bfloat16_as_ushort(hh);
    l = __bfloat16_as_ushort(ll);
}
__device__ __forceinline__ float bf2f(ushort_t x) {
    return __bfloat162float(__ushort_as_bfloat16(x));
}
__device__ __forceinline__ float warpSum(float v) {
    #pragma unroll
    for (int o = 16; o; o >>= 1) v += __shfl_xor_sync(0xffffffffu, v, o);
    return v;
}

/* ============ HMMA bf16 split GEMM (verified core) ======================== */
template <int EPI>
__global__ __launch_bounds__(256) void hmma_gemm(
    const ushort_t* __restrict__ Ahi, const ushort_t* __restrict__ Alo,
    const ushort_t* __restrict__ Bhi, const ushort_t* __restrict__ Blo,
    int Mtot, int Ktot, int Nrows, int OS,
    const float* __restrict__ rnx, const float* __restrict__ rny,
    float* __restrict__ out, ushort_t* __restrict__ o2h, ushort_t* __restrict__ o2l) {
    __shared__ ushort_t sAh[128 * 40], sAl[128 * 40];
    __shared__ ushort_t sBh[64 * 40], sBl[64 * 40];
    int tid = threadIdx.x, wid = tid >> 5, lid = tid & 31;
    int b = blockIdx.z, m0 = blockIdx.x * 128, n0 = blockIdx.y * 64;
    int wm = wid & 3, wn = wid >> 2;
    size_t abase = (size_t)b * Mtot * Ktot;
    size_t bbase = (size_t)b * Nrows * Ktot;
    uint32_t uAh = smem_u32(sAh), uAl = smem_u32(sAl);
    uint32_t uBh = smem_u32(sBh), uBl = smem_u32(sBl);
    int arow = ((lid >> 3) & 1) * 8 + (lid & 7);
    int akof = (lid >> 4) * 8;
    int brow = (lid & 7) + ((lid >> 4) & 1) * 8;
    int bkof = ((lid >> 3) & 1) * 8;

    float d[2][4][4];
    #pragma unroll
    for (int i = 0; i < 2; i++)
        #pragma unroll
        for (int j = 0; j < 4; j++)
            #pragma unroll
            for (int q = 0; q < 4; q++) d[i][j][q] = 0.f;

    for (int k0 = 0; k0 < Ktot; k0 += 32) {
        #pragma unroll
        for (int l = 0; l < 2; l++) {
            int idx = tid + l * 256;
            int r = idx >> 2, seg = idx & 3;
            *(uint4*)(sAh + r * 40 + seg * 8) =
                *(const uint4*)(Ahi + abase + (size_t)(m0 + r) * Ktot + k0 + seg * 8);
            *(uint4*)(sAl + r * 40 + seg * 8) =
                *(const uint4*)(Alo + abase + (size_t)(m0 + r) * Ktot + k0 + seg * 8);
        }
        {
            int r = tid >> 2, seg = tid & 3;
            *(uint4*)(sBh + r * 40 + seg * 8) =
                *(const uint4*)(Bhi + bbase + (size_t)(n0 + r) * Ktot + k0 + seg * 8);
            *(uint4*)(sBl + r * 40 + seg * 8) =
                *(const uint4*)(Blo + bbase + (size_t)(n0 + r) * Ktot + k0 + seg * 8);
        }
        __syncthreads();
        #pragma unroll
        for (int ks = 0; ks < 2; ks++) {
            int kb = ks * 16;
            uint32_t ah[2][4], al[2][4];
            #pragma unroll
            for (int tm = 0; tm < 2; tm++) {
                uint32_t off = (uint32_t)((wm * 32 + tm * 16 + arow) * 80 + (kb + akof) * 2);
                ldsm_x4(ah[tm][0], ah[tm][1], ah[tm][2], ah[tm][3], uAh + off);
                ldsm_x4(al[tm][0], al[tm][1], al[tm][2], al[tm][3], uAl + off);
            }
            uint32_t bh[4][2], bl[4][2];
            #pragma unroll
            for (int p = 0; p < 2; p++) {
                uint32_t off = (uint32_t)((wn * 32 + p * 16 + brow) * 80 + (kb + bkof) * 2);
                ldsm_x4(bh[2 * p][0], bh[2 * p][1], bh[2 * p + 1][0], bh[2 * p + 1][1], uBh + off);
                ldsm_x4(bl[2 * p][0], bl[2 * p][1], bl[2 * p + 1][0], bl[2 * p + 1][1], uBl + off);
            }
            #pragma unroll
            for (int tm = 0; tm < 2; tm++)
                #pragma unroll
                for (int tn = 0; tn < 4; tn++) {
                    mma_bf16(d[tm][tn][0], d[tm][tn][1], d[tm][tn][2], d[tm][tn][3],
                             ah[tm][0], ah[tm][1], ah[tm][2], ah[tm][3], bh[tn][0], bh[tn][1]);
                    mma_bf16(d[tm][tn][0], d[tm][tn][1], d[tm][tn][2], d[tm][tn][3],
                             ah[tm][0], ah[tm][1], ah[tm][2], ah[tm][3], bl[tn][0], bl[tn][1]);
                    mma_bf16(d[tm][tn][0], d[tm][tn][1], d[tm][tn][2], d[tm][tn][3],
                             al[tm][0], al[tm][1], al[tm][2], al[tm][3], bh[tn][0], bh[tn][1]);
                }
        }
        __syncthreads();
    }
    int tq = lid >> 2, tr = lid & 3;
    #pragma unroll
    for (int tm = 0; tm < 2; tm++) {
        #pragma unroll
        for (int half = 0; half < 2; half++) {
            int r = m0 + wm * 32 + tm * 16 + tq + half * 8;
            #pragma unroll
            for (int tn = 0; tn < 4; tn++) {
                int col = n0 + wn * 32 + tn * 8 + 2 * tr;
                float v0 = d[tm][tn][2 * half], v1 = d[tm][tn][2 * half + 1];
                size_t oidx = ((size_t)b * Mtot + r) * OS + col;
                if (EPI == 1) {
                    float rx = rnx[(b << 10) + r];
                    float2 o;
                    o.x = 1.f - rx * rny[(b << 10) + col] * v0;
                    o.y = 1.f - rx * rny[(b << 10) + col + 1] * v1;
                    *(float2*)(out + oidx) = o;
                } else {
                    float2 o; o.x = v0; o.y = v1;
                    *(float2*)(out + oidx) = o;
                    ushort_t h0, l0, h1, l1;
                    bsplit(v0, h0, l0);
                    bsplit(v1, h1, l1);
                    *(uint32_t*)(o2h + oidx) = ((uint32_t)h1 << 16) | h0;
                    *(uint32_t*)(o2l + oidx) = ((uint32_t)l1 << 16) | l0;
                }
            }
        }
    }
}

/* ============ shifted-GEMM tensor conv (NHWC, split bf16) ================= */
__global__ __launch_bounds__(256) void conv_hmma(
    const ushort_t* __restrict__ Ah0, const ushort_t* __restrict__ Al0,
    const ushort_t* __restrict__ Ah1, const ushort_t* __restrict__ Al1,
    int csplit, int CI,
    const ushort_t* __restrict__ Wh, const ushort_t* __restrict__ Wl,
    int CO, const float* __restrict__ bias, int relu,
    float* __restrict__ out) {
    extern __shared__ unsigned char cs[];
    ushort_t* sIh = (ushort_t*)(cs);
    ushort_t* sIl = (ushort_t*)(cs + 16320);
    ushort_t* sBh = (ushort_t*)(cs + 32640);
    ushort_t* sBl = (ushort_t*)(cs + 48000);
    int tid = threadIdx.x, wid = tid >> 5, lid = tid & 31;
    int mt = blockIdx.x;
    int b = mt >> 3, r0 = (mt & 7) * 4;
    int n0 = blockIdx.y * 64;
    int wm = wid & 3, wn = wid >> 2;
    int arow = ((lid >> 3) & 1) * 8 + (lid & 7);
    int akof = (lid >> 4) * 8;
    int brow = (lid & 7) + ((lid >> 4) & 1) * 8;
    int bkof = ((lid >> 3) & 1) * 8;
    uint32_t uIh = smem_u32(sIh), uIl = smem_u32(sIl);
    uint32_t uBh = smem_u32(sBh), uBl = smem_u32(sBl);
    uint32_t aoff[2];
    #pragma unroll
    for (int tm = 0; tm < 2; tm++) {
        int p = wm * 32 + tm * 16 + arow;
        aoff[tm] = (uint32_t)(((p >> 5) * 34 + (p & 31)) * 80 + akof * 2);
    }
    uint32_t boff = (uint32_t)((wn * 32 + brow) * 80 + bkof * 2);

    float d[2][4][4];
    #pragma unroll
    for (int i = 0; i < 2; i++)
        #pragma unroll
        for (int j = 0; j < 4; j++)
            #pragma unroll
            for (int q = 0; q < 4; q++) d[i][j][q] = 0.f;

    for (int ch = 0; ch < CI; ch += 32) {
        const ushort_t* srcH;
        const ushort_t* srcL;
        int cw, coff;
        if (ch < csplit) { srcH = Ah0; srcL = Al0; cw = csplit; coff = ch; }
        else             { srcH = Ah1; srcL = Al1; cw = CI - csplit; coff = ch - csplit; }
        for (int idx = tid; idx < 816; idx += 256) {
            int sp = idx >> 2, seg = idx & 3;
            int srow = sp / 34, scol = sp - srow * 34;
            int gy = r0 - 1 + srow, gx = scol - 1;
            uint4 vh = make_uint4(0, 0, 0, 0), vl = make_uint4(0, 0, 0, 0);
            if ((unsigned)gy < 32u && (unsigned)gx < 32u) {
                size_t off = (size_t)(b * 1024 + (gy << 5) + gx) * cw + coff + seg * 8;
                vh = *(const uint4*)(srcH + off);
                vl = *(const uint4*)(srcL + off);
            }
            *(uint4*)(sIh + sp * 40 + seg * 8) = vh;
            *(uint4*)(sIl + sp * 40 + seg * 8) = vl;
        }
        #pragma unroll 1
        for (int ky = 0; ky < 3; ky++) {
            for (int idx = tid; idx < 768; idx += 256) {
                int kx = idx >> 8, rem = idx & 255, oc = rem >> 2, seg = rem & 3;
                size_t woff = ((size_t)((ky * 3 + kx) * CO + n0 + oc)) * CI + ch + seg * 8;
                *(uint4*)(sBh + (kx * 64 + oc) * 40 + seg * 8) = *(const uint4*)(Wh + woff);
                *(uint4*)(sBl + (kx * 64 + oc) * 40 + seg * 8) = *(const uint4*)(Wl + woff);
            }
            __syncthreads();
            #pragma unroll
            for (int kx = 0; kx < 3; kx++) {
                uint32_t shoff = (uint32_t)((ky * 34 + kx) * 80);
                #pragma unroll
                for (int ks = 0; ks < 2; ks++) {
                    uint32_t kso = (uint32_t)(ks * 32);
                    uint32_t ah[2][4], al[2][4];
                    #pragma unroll
                    for (int tm = 0; tm < 2; tm++) {
                        ldsm_x4(ah[tm][0], ah[tm][1], ah[tm][2], ah[tm][3],
                                uIh + aoff[tm] + shoff + kso);
                        ldsm_x4(al[tm][0], al[tm][1], al[tm][2], al[tm][3],
                                uIl + aoff[tm] + shoff + kso);
                    }
                    uint32_t bh[4][2], bl[4][2];
                    #pragma unroll
                    for (int p = 0; p < 2; p++) {
                        uint32_t off = boff + (uint32_t)(kx * 64 * 80 + p * 16 * 80) + kso;
                        ldsm_x4(bh[2 * p][0], bh[2 * p][1], bh[2 * p + 1][0], bh[2 * p + 1][1],
                                uBh + off);
                        ldsm_x4(bl[2 * p][0], bl[2 * p][1], bl[2 * p + 1][0], bl[2 * p + 1][1],
                                uBl + off);
                    }
                    #pragma unroll
                    for (int tm = 0; tm < 2; tm++)
                        #pragma unroll
                        for (int tn = 0; tn < 4; tn++) {
                            mma_bf16(d[tm][tn][0], d[tm][tn][1], d[tm][tn][2], d[tm][tn][3],
                                     ah[tm][0], ah[tm][1], ah[tm][2], ah[tm][3],
                                     bh[tn][0], bh[tn][1]);
                            mma_bf16(d[tm][tn][0], d[tm][tn][1], d[tm][tn][2], d[tm][tn][3],
                                     ah[tm][0], ah[tm][1], ah[tm][2], ah[tm][3],
                                     bl[tn][0], bl[tn][1]);
                            mma_bf16(d[tm][tn][0], d[tm][tn][1], d[tm][tn][2], d[tm][tn][3],
                                     al[tm][0], al[tm][1], al[tm][2], al[tm][3],
                                     bh[tn][0], bh[tn][1]);
                        }
                }
            }
            __syncthreads();
        }
    }
    int tq = lid >> 2, tr = lid & 3;
    #pragma unroll
    for (int tm = 0; tm < 2; tm++) {
        #pragma unroll
        for (int half = 0; half < 2; half++) {
            int pt = wm * 32 + tm * 16 + tq + half * 8;
            size_t prow = (size_t)(b * 1024 + r0 * 32 + pt) * CO;
            #pragma unroll
            for (int tn = 0; tn < 4; tn++) {
                int col = n0 + wn * 32 + tn * 8 + 2 * tr;
                float v0 = d[tm][tn][2 * half] + bias[col];
                float v1 = d[tm][tn][2 * half + 1] + bias[col + 1];
                if (relu) { v0 = fmaxf(v0, 0.f); v1 = fmaxf(v1, 0.f); }
                float2 o; o.x = v0; o.y = v1;
                *(float2*)(out + prow + col) = o;
            }
        }
    }
}
static const int CONV_SMEM = 63360;

/* ---------------- prep kernels ---------------- */
__global__ __launch_bounds__(256) void transpose_split(
    const float* __restrict__ x, ushort_t* __restrict__ oh, ushort_t* __restrict__ ol) {
    __shared__ float tb[32][33];
    int b = blockIdx.z;
    int i0 = blockIdx.x * 32, d0 = blockIdx.y * 32;
    int tx = threadIdx.x & 31, ty = threadIdx.x >> 5;
    const float* xb = x + (size_t)b * 512 * 1024;
    #pragma unroll
    for (int k = 0; k < 4; k++)
        tb[ty + k * 8][tx] = xb[(size_t)(d0 + ty + k * 8) * 1024 + i0 + tx];
    __syncthreads();
    #pragma unroll
    for (int k = 0; k < 4; k++) {
        int il = ty + k * 8;
        float v = tb[tx][il];
        ushort_t h, l;
        bsplit(v, h, l);
        size_t o = (size_t)b * 1024 * 512 + (size_t)(i0 + il) * 512 + d0 + tx;
        oh[o] = h; ol[o] = l;
    }
}

__global__ __launch_bounds__(256) void convert_split(
    const float* __restrict__ x, ushort_t* __restrict__ oh,
    ushort_t* __restrict__ ol, int npair) {
    int i = blockIdx.x * 256 + threadIdx.x;
    if (i >= npair) return;
    float2 v = ((const float2*)x)[i];
    ushort_t h0, l0, h1, l1;
    bsplit(v.x, h0, l0);
    bsplit(v.y, h1, l1);
    ((uint32_t*)oh)[i] = ((uint32_t)h1 << 16) | h0;
    ((uint32_t*)ol)[i] = ((uint32_t)l1 << 16) | l0;
}

__global__ __launch_bounds__(256) void rownorm_t(const ushort_t* __restrict__ xh,
                                                 const ushort_t* __restrict__ xl,
                                                 float* __restrict__ rn) {
    int row = blockIdx.x * 8 + (threadIdx.x >> 5);
    int lane = threadIdx.x & 31;
    const uint4* ph = (const uint4*)(xh + (size_t)row * 512);
    const uint4* pl = (const uint4*)(xl + (size_t)row * 512);
    float s = 0.f;
    #pragma unroll
    for (int k = 0; k < 2; k++) {
        uint4 h4 = ph[lane + k * 32], l4 = pl[lane + k * 32];
        const ushort_t* hh = (const ushort_t*)&h4;
        const ushort_t* ll = (const ushort_t*)&l4;
        #pragma unroll
        for (int j = 0; j < 8; j++) {
            float v = bf2f(hh[j]) + bf2f(ll[j]);
            s = fmaf(v, v, s);
        }
    }
    s = warpSum(s);
    if (lane == 0) rn[row] = rsqrtf(s);
}

__global__ __launch_bounds__(256) void wprep(const float* __restrict__ w,
                                             ushort_t* __restrict__ wh,
                                             ushort_t* __restrict__ wl,
                                             int CO, int CI) {
    int i = blockIdx.x * 256 + threadIdx.x;
    if (i >= CO * CI) return;
    int oc = i / CI, ci = i - oc * CI;
    #pragma unroll
    for (int k = 0; k < 9; k++) {
        float v = w[(size_t)i * 9 + k];
        ushort_t h, l;
        bsplit(v, h, l);
        size_t o = ((size_t)k * CO + oc) * CI + ci;
        wh[o] = h; wl[o] = l;
    }
}

/* ---------------- Sinkhorn ---------------- */
__global__ void zero_uv(float* u, float* v) {
    int i = blockIdx.x * blockDim.x + threadIdx.x;
    if (i < 4096) { u[i] = 0.f; v[i] = 0.f; }
}

/* u phase: warp per row (grid 512 x 256 = 4096 warps), online LSE, no bar */
__global__ __launch_bounds__(256) void u_update(const float* __restrict__ C,
                                                const float* __restrict__ v,
                                                float* __restrict__ u) {
    int row = blockIdx.x * 8 + (threadIdx.x >> 5);
    int lane = threadIdx.x & 31;
    const float4* Crow = (const float4*)(C + (size_t)row * 1024);
    const float4* vb = (const float4*)(v + ((row >> 10) << 10));
    float m = -FLT_MAX, s = 0.f;
    #pragma unroll
    for (int k = 0; k < 8; k++) {
        int j4 = lane + k * 32;
        float4 c = Crow[j4], vv = vb[j4];
        float x0 = (vv.x - c.x) * INV_EPS;
        float x1 = (vv.y - c.y) * INV_EPS;
        float x2 = (vv.z - c.z) * INV_EPS;
        float x3 = (vv.w - c.w) * INV_EPS;
        float mx = fmaxf(fmaxf(x0, x1), fmaxf(x2, x3));
        float nm = fmaxf(m, mx);
        s = s * __expf(m - nm) + __expf(x0 - nm) + __expf(x1 - nm)
            + __expf(x2 - nm) + __expf(x3 - nm);
        m = nm;
    }
    #pragma unroll
    for (int o = 16; o; o >>= 1) {
        float m2 = __shfl_xor_sync(0xffffffffu, m, o);
        float s2 = __shfl_xor_sync(0xffffffffu, s, o);
        float nm = fmaxf(m, m2);
        s = s * __expf(m - nm) + s2 * __expf(m2 - nm);
        m = nm;
    }
    if (lane == 0) u[row] = EPS_S * (LOG_MU - (m + __logf(s)));
}

/* v phase: block = 32 j x 16 i-segments (512 threads) */
__global__ __launch_bounds__(512) void v_update(const float* __restrict__ C,
                                                const float* __restrict__ u,
                                                float* __restrict__ v) {
    int b = blockIdx.y;
    int tx = threadIdx.x, ty = threadIdx.y;
    int j = blockIdx.x * 32 + tx;
    const float* p = C + (size_t)b * 1048576 + j;
    const float* ub = u + (b << 10);
    float m0 = -FLT_MAX, s0 = 0.f, m1 = -FLT_MAX, s1 = 0.f;
    for (int i = ty; i < 1024; i += 32) {
        float xa = (ub[i] - p[(size_t)i << 10]) * INV_EPS;
        float xb = (ub[i + 16] - p[(size_t)(i + 16) << 10]) * INV_EPS;
        float n0 = fmaxf(m0, xa);
        s0 = s0 * __expf(m0 - n0) + __expf(xa - n0); m0 = n0;
        float n1 = fmaxf(m1, xb);
        s1 = s1 * __expf(m1 - n1) + __expf(xb - n1); m1 = n1;
    }
    float mm = fmaxf(m0, m1);
    float ss = s0 * __expf(m0 - mm) + s1 * __expf(m1 - mm);
    __shared__ float sm[16][33], sq[16][33];
    sm[ty][tx] = mm; sq[ty][tx] = ss;
    __syncthreads();
    if (ty == 0) {
        float M = mm, S = ss;
        #pragma unroll
        for (int q = 1; q < 16; q++) {
            float m2 = sm[q][tx], s2 = sq[q][tx];
            float nm = fmaxf(M, m2);
            S = S * __expf(M - nm) + s2 * __expf(m2 - nm);
            M = nm;
        }
        v[(b << 10) + j] = EPS_S * (LOG_MU - (M + __logf(S)));
    }
}

/* pi: warp per row, split to bf16 hi/lo */
__global__ __launch_bounds__(256) void pi_gen(
    const float* __restrict__ C, const float* __restrict__ u,
    const float* __restrict__ v, ushort_t* __restrict__ ph,
    ushort_t* __restrict__ pl) {
    int row = blockIdx.x * 8 + (threadIdx.x >> 5);
    int lane = threadIdx.x & 31;
    float ui = u[row];
    const float4* Crow = (const float4*)(C + (size_t)row * 1024);
    const float4* vb = (const float4*)(v + ((row >> 10) << 10));
    uint2* phr = (uint2*)(ph + (size_t)row * 1024);
    uint2* plr = (uint2*)(pl + (size_t)row * 1024);
    #pragma unroll
    for (int k = 0; k < 8; k++) {
        int j4 = lane + k * 32;
        float4 c = Crow[j4], vv = vb[j4];
        float p0 = __expf((ui + vv.x - c.x) * INV_EPS) * 1024.f;
        float p1 = __expf((ui + vv.y - c.y) * INV_EPS) * 1024.f;
        float p2 = __expf((ui + vv.z - c.z) * INV_EPS) * 1024.f;
        float p3 = __expf((ui + vv.w - c.w) * INV_EPS) * 1024.f;
        ushort_t h0, l0, h1, l1, h2, l2, h3, l3;
        bsplit(p0, h0, l0); bsplit(p1, h1, l1);
        bsplit(p2, h2, l2); bsplit(p3, h3, l3);
        uint2 oh, ol;
        oh.x = ((uint32_t)h1 << 16) | h0; oh.y = ((uint32_t)h3 << 16) | h2;
        ol.x = ((uint32_t)l1 << 16) | l0; ol.y = ((uint32_t)l3 << 16) | l2;
        phr[j4] = oh; plr[j4] = ol;
    }
}

/* ---------------- per-(b,c) mean / 1/std of content (NCHW) ---------------- */
__global__ __launch_bounds__(128) void cmstd(const float* __restrict__ x,
                                             float* __restrict__ cm,
                                             float* __restrict__ rs) {
    int bc = blockIdx.x, t = threadIdx.x;
    const float* p = x + ((size_t)bc << 10);
    float s = 0.f, q = 0.f;
    #pragma unroll
    for (int l = 0; l < 8; l++) {
        float v = p[t + l * 128];
        s += v; q = fmaf(v, v, q);
    }
    s = warpSum(s); q = warpSum(q);
    __shared__ float rsm[4], rqm[4];
    if ((t & 31) == 0) { rsm[t >> 5] = s; rqm[t >> 5] = q; }
    __syncthreads();
    if (t == 0) {
        float S = rsm[0] + rsm[1] + rsm[2] + rsm[3];
        float Q = rqm[0] + rqm[1] + rqm[2] + rqm[3];
        float mean = S * (1.f / 1024.f);
        float var = Q * (1.f / 1024.f) - mean * mean;
        cm[bc] = mean;
        rs[bc] = rsqrtf(fmaxf(var, 0.f) + 1e-5f);
    }
}

/* ---------------- BatchNorm (NHWC, two-phase, deterministic) --------------- */
__global__ __launch_bounds__(256) void bnpart(const float* __restrict__ x,
                                              float* __restrict__ ps,
                                              float* __restrict__ pq) {
    int slab = blockIdx.x, t = threadIdx.x;
    float s = 0.f, q = 0.f;
    #pragma unroll
    for (int i = 0; i < 16; i++) {
        float v = x[(size_t)(slab * 16 + i) * 256 + t];
        s += v; q = fmaf(v, v, q);
    }
    ps[slab * 256 + t] = s;
    pq[slab * 256 + t] = q;
}
__global__ void bnfin(const float* __restrict__ ps, const float* __restrict__ pq,
                      const float* __restrict__ g, const float* __restrict__ be,
                      float* __restrict__ scale, float* __restrict__ shift) {
    int c = threadIdx.x;
    float s = 0.f, q = 0.f;
    for (int k = 0; k < 256; k++) { s += ps[k * 256 + c]; q += pq[k * 256 + c]; }
    float mean = s * (1.f / 4096.f);
    float var = q * (1.f / 4096.f) - mean * mean;
    float sc = g[c] * rsqrtf(fmaxf(var, 0.f) + BN_EPS);
    scale[c] = sc;
    shift[c] = be[c] - mean * sc;
}
__global__ __launch_bounds__(256) void bn_split(const float* __restrict__ x,
                                                const float* __restrict__ scale,
                                                const float* __restrict__ shift,
                                                ushort_t* __restrict__ oh,
                                                ushort_t* __restrict__ ol) {
    int i = blockIdx.x * 256 + threadIdx.x;
    int c = i & 255;
    float v = fmaf(x[i], scale[c], shift[c]);
    ushort_t h, l;
    bsplit(v, h, l);
    oh[i] = h; ol[i] = l;
}

/* -------- blend + transpose: tblend NCHW = t + alpha*(content-cm)*rs ------- */
__global__ __launch_bounds__(256) void blend_T(const float* __restrict__ tn,
                                               const float* __restrict__ an,
                                               const float* __restrict__ content,
                                               const float* __restrict__ cm,
                                               const float* __restrict__ rs,
                                               float* __restrict__ outc) {
    __shared__ float ts[32][33], as_[32][33];
    int pix0 = blockIdx.x * 32, ch0 = blockIdx.y * 32;
    int tx = threadIdx.x & 31, ty = threadIdx.x >> 5;
    #pragma unroll
    for (int k = 0; k < 4; k++) {
        int p = pix0 + ty + k * 8;
        ts[ty + k * 8][tx]  = tn[(size_t)p * 512 + ch0 + tx];
        as_[ty + k * 8][tx] = an[(size_t)p * 512 + ch0 + tx];
    }
    __syncthreads();
    int b = pix0 >> 10;
    int pl = pix0 & 1023;
    #pragma unroll
    for (int k = 0; k < 4; k++) {
        int cl = ty + k * 8;
        int gch = b * 512 + ch0 + cl;
        float m = cm[gch], r = rs[gch];
        float c = content[(size_t)gch * 1024 + pl + tx];
        float v = fmaf(as_[tx][cl], (c - m) * r, ts[tx][cl]);
        outc[(size_t)gch * 1024 + pl + tx] = v;
    }
}

/* ---------------- decoder: direct 3x3 conv NCHW ---------------- */
template <int OCT, int SROWS, int NT, int CIT>
__global__ __launch_bounds__(NT) void conv3x3(
    const float* __restrict__ src0, int CI, int CO,
    const float* __restrict__ W, const float* __restrict__ bias,
    float* __restrict__ out) {
    constexpr int NPIX = SROWS * 32;
    constexpr int PXT = NPIX / NT;
    __shared__ float s_in[CIT][SROWS + 2][34];
    __shared__ float s_w[CIT][9][OCT];
    int b = blockIdx.x, oc0 = blockIdx.y * OCT, r0 = blockIdx.z * SROWS;
    int tid = threadIdx.x;
    int rr[PXT], cc[PXT];
    #pragma unroll
    for (int p = 0; p < PXT; p++) {
        int px = tid + p * NT;
        rr[p] = px >> 5; cc[p] = px & 31;
    }
    float acc[OCT][PXT];
    #pragma unroll
    for (int o = 0; o < OCT; o++)
        #pragma unroll
        for (int p = 0; p < PXT; p++) acc[o][p] = 0.f;

    const int TOTIN = CIT * (SROWS + 2) * 34;
    const int TW = CIT * 9 * OCT;
    #pragma unroll 1
    for (int ci0 = 0; ci0 < CI; ci0 += CIT) {
        #pragma unroll 1
        for (int idx = tid; idx < TOTIN; idx += NT) {
            int ci = idx / ((SROWS + 2) * 34);
            int rem = idx - ci * ((SROWS + 2) * 34);
            int r = rem / 34, c = rem - r * 34;
            int gy = r0 + r - 1, gx = c - 1;
            float v = 0.f;
            if ((unsigned)gy < 32u && (unsigned)gx < 32u)
                v = src0[((size_t)(b * CI + ci0 + ci) << 10) + (gy << 5) + gx];
            (&s_in[0][0][0])[idx] = v;
        }
        #pragma unroll 1
        for (int idx = tid; idx < TW; idx += NT) {
            int ci = idx / (9 * OCT);
            int rem = idx - ci * (9 * OCT);
            int k = rem / OCT, oc = rem - k * OCT;
            float wv = 0.f;
            if (oc0 + oc < CO)
                wv = W[((size_t)(oc0 + oc) * CI + ci0 + ci) * 9 + k];
            (&s_w[0][0][0])[idx] = wv;
        }
        __syncthreads();
        #pragma unroll 1
        for (int ci = 0; ci < CIT; ci++) {
            #pragma unroll
            for (int ky = 0; ky < 3; ky++)
                #pragma unroll
                for (int kx = 0; kx < 3; kx++) {
                    float w[OCT];
                    #pragma unroll
                    for (int o4 = 0; o4 < OCT / 4; o4++)
                        *(float4*)&w[o4 * 4] = *(const float4*)&s_w[ci][ky * 3 + kx][o4 * 4];
                    #pragma unroll
                    for (int p = 0; p < PXT; p++) {
                        float v = s_in[ci][rr[p] + ky][cc[p] + kx];
                        #pragma unroll
                        for (int o = 0; o < OCT; o++)
                            acc[o][p] = fmaf(v, w[o], acc[o][p]);
                    }
                }
        }
        __syncthreads();
    }
    #pragma unroll
    for (int o = 0; o < OCT; o++) {
        if (oc0 + o >= CO) break;
        float bi = bias[oc0 + o];
        #pragma unroll
        for (int p = 0; p < PXT; p++)
            out[((size_t)(b * CO + oc0 + o) << 10) + r0 * 32 + tid + p * NT] = acc[o][p] + bi;
    }
}

/* ---------------- host orchestration ---------------- */
extern "C" void kernel_launch(void* const* d_in, const int* in_sizes, int n_in,
                              void* d_out, int out_size) {
    const float* content = (const float*)d_in[0];
    const float* style   = (const float*)d_in[1];
    const float* w1 = (const float*)d_in[2];  const float* b1 = (const float*)d_in[3];
    const float* g1 = (const float*)d_in[4];  const float* be1 = (const float*)d_in[5];
    const float* w2 = (const float*)d_in[6];  const float* b2 = (const float*)d_in[7];
    const float* g2 = (const float*)d_in[8];  const float* be2 = (const float*)d_in[9];
    const float* w3 = (const float*)d_in[10]; const float* b3 = (const float*)d_in[11];
    const float* dw = (const float*)d_in[12]; const float* db = (const float*)d_in[13];
    float* out = (float*)d_out;
    (void)in_sizes; (void)n_in; (void)out_size;

    float *pC, *pu, *pv, *prnx, *prny, *pt, *pa1, *pa2, *palpha, *pcm, *prs,
          *pscale, *pshift, *pps, *ppq;
    ushort_t *pcTh, *pcTl, *psTh, *psTl, *psfh, *psfl, *ppih, *ppil,
             *ptth, *pttl, *pb1h, *pb1l, *pb2h, *pb2l,
             *pw1h, *pw1l, *pw2h, *pw2l, *pw3h, *pw3l;
    cudaGetSymbolAddress((void**)&pC, g_C);
    cudaGetSymbolAddress((void**)&pu, g_u);
    cudaGetSymbolAddress((void**)&pv, g_v);
    cudaGetSymbolAddress((void**)&prnx, g_rnx);
    cudaGetSymbolAddress((void**)&prny, g_rny);
    cudaGetSymbolAddress((void**)&pt, g_t);
    cudaGetSymbolAddress((void**)&pa1, g_a1);
    cudaGetSymbolAddress((void**)&pa2, g_a2);
    cudaGetSymbolAddress((void**)&palpha, g_alpha);
    cudaGetSymbolAddress((void**)&pcm, g_cm);
    cudaGetSymbolAddress((void**)&prs, g_rs);
    cudaGetSymbolAddress((void**)&pscale, g_scale);
    cudaGetSymbolAddress((void**)&pshift, g_shift);
    cudaGetSymbolAddress((void**)&pps, g_ps);
    cudaGetSymbolAddress((void**)&ppq, g_pq);
    cudaGetSymbolAddress((void**)&pcTh, g_cTh);
    cudaGetSymbolAddress((void**)&pcTl, g_cTl);
    cudaGetSymbolAddress((void**)&psTh, g_sTh);
    cudaGetSymbolAddress((void**)&psTl, g_sTl);
    cudaGetSymbolAddress((void**)&psfh, g_sfh);
    cudaGetSymbolAddress((void**)&psfl, g_sfl);
    cudaGetSymbolAddress((void**)&ppih, g_pih);
    cudaGetSymbolAddress((void**)&ppil, g_pil);
    cudaGetSymbolAddress((void**)&ptth, g_tth);
    cudaGetSymbolAddress((void**)&pttl, g_ttl);
    cudaGetSymbolAddress((void**)&pb1h, g_b1h);
    cudaGetSymbolAddress((void**)&pb1l, g_b1l);
    cudaGetSymbolAddress((void**)&pb2h, g_b2h);
    cudaGetSymbolAddress((void**)&pb2l, g_b2l);
    cudaGetSymbolAddress((void**)&pw1h, g_w1h);
    cudaGetSymbolAddress((void**)&pw1l, g_w1l);
    cudaGetSymbolAddress((void**)&pw2h, g_w2h);
    cudaGetSymbolAddress((void**)&pw2l, g_w2l);
    cudaGetSymbolAddress((void**)&pw3h, g_w3h);
    cudaGetSymbolAddress((void**)&pw3l, g_w3l);

    cudaFuncSetAttribute(conv_hmma, cudaFuncAttributeMaxDynamicSharedMemorySize, CONV_SMEM);

    /* operand prep */
    transpose_split<<<dim3(32, 16, 4), 256>>>(content, pcTh, pcTl);
    transpose_split<<<dim3(32, 16, 4), 256>>>(style, psTh, psTl);
    convert_split<<<4096, 256>>>(style, psfh, psfl, 4 * 512 * 512);
    rownorm_t<<<512, 256>>>(pcTh, pcTl, prnx);
    rownorm_t<<<512, 256>>>(psTh, psTl, prny);
    wprep<<<1024, 256>>>(w1, pw1h, pw1l, 256, 1024);
    wprep<<<256, 256>>>(w2, pw2h, pw2l, 256, 256);
    wprep<<<512, 256>>>(w3, pw3h, pw3l, 512, 256);

    /* cosine-cost matrix */
    hmma_gemm<1><<<dim3(8, 16, 4), 256>>>(pcTh, pcTl, psTh, psTl,
        1024, 512, 1024, 1024, prnx, prny, pC, nullptr, nullptr);

    /* Sinkhorn, 20 iterations (bandwidth-optimized passes) */
    zero_uv<<<16, 256>>>(pu, pv);
    for (int it = 0; it < 20; it++) {
        u_update<<<512, 256>>>(pC, pv, pu);
        v_update<<<dim3(32, 4), dim3(32, 16)>>>(pC, pu, pv);
    }

    /* pi, then t = pi @ style^T -> NHWC fp32 + bf16 split */
    pi_gen<<<512, 256>>>(pC, pu, pv, ppih, ppil);
    hmma_gemm<2><<<dim3(8, 8, 4), 256>>>(ppih, ppil, psfh, psfl,
        1024, 1024, 512, 512, nullptr, nullptr, pt, ptth, pttl);

    cmstd<<<2048, 128>>>(content, pcm, prs);

    /* alpha predictor via tensor convs (NHWC) */
    conv_hmma<<<dim3(32, 4), 256, CONV_SMEM>>>(ptth, pttl, pcTh, pcTl, 512, 1024,
        pw1h, pw1l, 256, b1, 1, pa1);
    bnpart<<<256, 256>>>(pa1, pps, ppq);
    bnfin<<<1, 256>>>(pps, ppq, g1, be1, pscale, pshift);
    bn_split<<<4096, 256>>>(pa1, pscale, pshift, pb1h, pb1l);
    conv_hmma<<<dim3(32, 4), 256, CONV_SMEM>>>(pb1h, pb1l, pb1h, pb1l, 256, 256,
        pw2h, pw2l, 256, b2, 1, pa2);
    bnpart<<<256, 256>>>(pa2, pps, ppq);
    bnfin<<<1, 256>>>(pps, ppq, g2, be2, pscale, pshift);
    bn_split<<<4096, 256>>>(pa2, pscale, pshift, pb2h, pb2l);
    conv_hmma<<<dim3(32, 8), 256, CONV_SMEM>>>(pb2h, pb2l, pb2h, pb2l, 256, 256,
        pw3h, pw3l, 512, b3, 0, palpha);

    /* blend (transposed to NCHW), decoder conv */
    blend_T<<<dim3(128, 16), 256>>>(pt, palpha, content, pcm, prs, pC);
    conv3x3<4, 4, 128, 8><<<dim3(4, 1, 8), 128>>>(pC, 512, 3, dw, db, out);
}

// round 12
// speedup vs baseline: 1.6146x; 1.6146x over previous
#include <cuda_runtime.h>
#include <cuda_bf16.h>
#include <cfloat>
#include <cstdint>

#define EPS_S   0.01f
#define INV_EPS 100.0f
#define LOG_MU  -6.93146200f   /* log(1/1024 + 1e-8) */
#define BN_EPS  1e-5f

typedef unsigned short ushort_t;

/* ---------------- scratch (device globals: no allocs allowed) -------------- */
__device__ float g_C[4 * 1024 * 1024];          /* cost matrix; later tblend NCHW */
__device__ float g_u[4096], g_v[4096];
__device__ float g_rnx[4096], g_rny[4096];
__device__ float g_t[4 * 1024 * 512];           /* t NHWC fp32 [pix][512] */
__device__ float g_a1[4 * 1024 * 256];
__device__ float g_a2[4 * 1024 * 256];
__device__ float g_alpha[4 * 1024 * 512];
__device__ float g_cm[2048], g_rs[2048];
__device__ float g_scale[512], g_shift[512];
__device__ float g_ps[256 * 256], g_pq[256 * 256];
/* bf16 split buffers */
__device__ ushort_t g_cTh[4 * 1024 * 512], g_cTl[4 * 1024 * 512];
__device__ ushort_t g_sTh[4 * 1024 * 512], g_sTl[4 * 1024 * 512];
__device__ ushort_t g_sfh[4 * 512 * 1024], g_sfl[4 * 512 * 1024];
__device__ ushort_t g_pih[4 * 1024 * 1024], g_pil[4 * 1024 * 1024];
__device__ ushort_t g_tth[4 * 1024 * 512], g_ttl[4 * 1024 * 512];
__device__ ushort_t g_b1h[4 * 1024 * 256], g_b1l[4 * 1024 * 256];
__device__ ushort_t g_b2h[4 * 1024 * 256], g_b2l[4 * 1024 * 256];
__device__ ushort_t g_w1h[9 * 256 * 1024], g_w1l[9 * 256 * 1024];
__device__ ushort_t g_w2h[9 * 256 * 256],  g_w2l[9 * 256 * 256];
__device__ ushort_t g_w3h[9 * 512 * 256],  g_w3l[9 * 512 * 256];

__device__ __forceinline__ uint32_t smem_u32(const void* p) {
    uint32_t a;
    asm("{ .reg .u64 t; cvta.to.shared.u64 t, %1; cvt.u32.u64 %0, t; }"
        : "=r"(a) : "l"(p));
    return a;
}
__device__ __forceinline__ void ldsm_x4(uint32_t& r0, uint32_t& r1,
                                        uint32_t& r2, uint32_t& r3, uint32_t a) {
    asm volatile("ldmatrix.sync.aligned.m8n8.x4.shared.b16 {%0,%1,%2,%3}, [%4];"
                 : "=r"(r0), "=r"(r1), "=r"(r2), "=r"(r3) : "r"(a));
}
__device__ __forceinline__ void mma_bf16(float& d0, float& d1, float& d2, float& d3,
                                         uint32_t a0, uint32_t a1, uint32_t a2, uint32_t a3,
                                         uint32_t b0, uint32_t b1) {
    asm volatile(
        "mma.sync.aligned.m16n8k16.row.col.f32.bf16.bf16.f32 "
        "{%0,%1,%2,%3}, {%4,%5,%6,%7}, {%8,%9}, {%0,%1,%2,%3};"
        : "+f"(d0), "+f"(d1), "+f"(d2), "+f"(d3)
        : "r"(a0), "r"(a1), "r"(a2), "r"(a3), "r"(b0), "r"(b1));
}
__device__ __forceinline__ void bsplit(float v, ushort_t& h, ushort_t& l) {
    __nv_bfloat16 hh = __float2bfloat16(v);
    float rem = v - __bfloat162float(hh);
    __nv_bfloat16 ll = __float2bfloat16(rem);
    h = __bfloat16_as_ushort(hh);
    l = __bfloat16_as_ushort(ll);
}
__device__ __forceinline__ float bf2f(ushort_t x) {
    return __bfloat162float(__ushort_as_bfloat16(x));
}
__device__ __forceinline__ float warpSum(float v) {
    #pragma unroll
    for (int o = 16; o; o >>= 1) v += __shfl_xor_sync(0xffffffffu, v, o);
    return v;
}
__device__ __forceinline__ float warpMax(float v) {
    #pragma unroll
    for (int o = 16; o; o >>= 1) v = fmaxf(v, __shfl_xor_sync(0xffffffffu, v, o));
    return v;
}

/* ============ HMMA bf16 split GEMM (verified core) ======================== */
template <int EPI>
__global__ __launch_bounds__(256) void hmma_gemm(
    const ushort_t* __restrict__ Ahi, const ushort_t* __restrict__ Alo,
    const ushort_t* __restrict__ Bhi, const ushort_t* __restrict__ Blo,
    int Mtot, int Ktot, int Nrows, int OS,
    const float* __restrict__ rnx, const float* __restrict__ rny,
    float* __restrict__ out, ushort_t* __restrict__ o2h, ushort_t* __restrict__ o2l) {
    __shared__ ushort_t sAh[128 * 40], sAl[128 * 40];
    __shared__ ushort_t sBh[64 * 40], sBl[64 * 40];
    int tid = threadIdx.x, wid = tid >> 5, lid = tid & 31;
    int b = blockIdx.z, m0 = blockIdx.x * 128, n0 = blockIdx.y * 64;
    int wm = wid & 3, wn = wid >> 2;
    size_t abase = (size_t)b * Mtot * Ktot;
    size_t bbase = (size_t)b * Nrows * Ktot;
    uint32_t uAh = smem_u32(sAh), uAl = smem_u32(sAl);
    uint32_t uBh = smem_u32(sBh), uBl = smem_u32(sBl);
    int arow = ((lid >> 3) & 1) * 8 + (lid & 7);
    int akof = (lid >> 4) * 8;
    int brow = (lid & 7) + ((lid >> 4) & 1) * 8;
    int bkof = ((lid >> 3) & 1) * 8;

    float d[2][4][4];
    #pragma unroll
    for (int i = 0; i < 2; i++)
        #pragma unroll
        for (int j = 0; j < 4; j++)
            #pragma unroll
            for (int q = 0; q < 4; q++) d[i][j][q] = 0.f;

    for (int k0 = 0; k0 < Ktot; k0 += 32) {
        #pragma unroll
        for (int l = 0; l < 2; l++) {
            int idx = tid + l * 256;
            int r = idx >> 2, seg = idx & 3;
            *(uint4*)(sAh + r * 40 + seg * 8) =
                *(const uint4*)(Ahi + abase + (size_t)(m0 + r) * Ktot + k0 + seg * 8);
            *(uint4*)(sAl + r * 40 + seg * 8) =
                *(const uint4*)(Alo + abase + (size_t)(m0 + r) * Ktot + k0 + seg * 8);
        }
        {
            int r = tid >> 2, seg = tid & 3;
            *(uint4*)(sBh + r * 40 + seg * 8) =
                *(const uint4*)(Bhi + bbase + (size_t)(n0 + r) * Ktot + k0 + seg * 8);
            *(uint4*)(sBl + r * 40 + seg * 8) =
                *(const uint4*)(Blo + bbase + (size_t)(n0 + r) * Ktot + k0 + seg * 8);
        }
        __syncthreads();
        #pragma unroll
        for (int ks = 0; ks < 2; ks++) {
            int kb = ks * 16;
            uint32_t ah[2][4], al[2][4];
            #pragma unroll
            for (int tm = 0; tm < 2; tm++) {
                uint32_t off = (uint32_t)((wm * 32 + tm * 16 + arow) * 80 + (kb + akof) * 2);
                ldsm_x4(ah[tm][0], ah[tm][1], ah[tm][2], ah[tm][3], uAh + off);
                ldsm_x4(al[tm][0], al[tm][1], al[tm][2], al[tm][3], uAl + off);
            }
            uint32_t bh[4][2], bl[4][2];
            #pragma unroll
            for (int p = 0; p < 2; p++) {
                uint32_t off = (uint32_t)((wn * 32 + p * 16 + brow) * 80 + (kb + bkof) * 2);
                ldsm_x4(bh[2 * p][0], bh[2 * p][1], bh[2 * p + 1][0], bh[2 * p + 1][1], uBh + off);
                ldsm_x4(bl[2 * p][0], bl[2 * p][1], bl[2 * p + 1][0], bl[2 * p + 1][1], uBl + off);
            }
            #pragma unroll
            for (int tm = 0; tm < 2; tm++)
                #pragma unroll
                for (int tn = 0; tn < 4; tn++) {
                    mma_bf16(d[tm][tn][0], d[tm][tn][1], d[tm][tn][2], d[tm][tn][3],
                             ah[tm][0], ah[tm][1], ah[tm][2], ah[tm][3], bh[tn][0], bh[tn][1]);
                    mma_bf16(d[tm][tn][0], d[tm][tn][1], d[tm][tn][2], d[tm][tn][3],
                             ah[tm][0], ah[tm][1], ah[tm][2], ah[tm][3], bl[tn][0], bl[tn][1]);
                    mma_bf16(d[tm][tn][0], d[tm][tn][1], d[tm][tn][2], d[tm][tn][3],
                             al[tm][0], al[tm][1], al[tm][2], al[tm][3], bh[tn][0], bh[tn][1]);
                }
        }
        __syncthreads();
    }
    int tq = lid >> 2, tr = lid & 3;
    #pragma unroll
    for (int tm = 0; tm < 2; tm++) {
        #pragma unroll
        for (int half = 0; half < 2; half++) {
            int r = m0 + wm * 32 + tm * 16 + tq + half * 8;
            #pragma unroll
            for (int tn = 0; tn < 4; tn++) {
                int col = n0 + wn * 32 + tn * 8 + 2 * tr;
                float v0 = d[tm][tn][2 * half], v1 = d[tm][tn][2 * half + 1];
                size_t oidx = ((size_t)b * Mtot + r) * OS + col;
                if (EPI == 1) {
                    float rx = rnx[(b << 10) + r];
                    float2 o;
                    o.x = 1.f - rx * rny[(b << 10) + col] * v0;
                    o.y = 1.f - rx * rny[(b << 10) + col + 1] * v1;
                    *(float2*)(out + oidx) = o;
                } else {
                    float2 o; o.x = v0; o.y = v1;
                    *(float2*)(out + oidx) = o;
                    ushort_t h0, l0, h1, l1;
                    bsplit(v0, h0, l0);
                    bsplit(v1, h1, l1);
                    *(uint32_t*)(o2h + oidx) = ((uint32_t)h1 << 16) | h0;
                    *(uint32_t*)(o2l + oidx) = ((uint32_t)l1 << 16) | l0;
                }
            }
        }
    }
}

/* ============ shifted-GEMM tensor conv (NHWC, split bf16) ================= */
__global__ __launch_bounds__(256) void conv_hmma(
    const ushort_t* __restrict__ Ah0, const ushort_t* __restrict__ Al0,
    const ushort_t* __restrict__ Ah1, const ushort_t* __restrict__ Al1,
    int csplit, int CI,
    const ushort_t* __restrict__ Wh, const ushort_t* __restrict__ Wl,
    int CO, const float* __restrict__ bias, int relu,
    float* __restrict__ out) {
    extern __shared__ unsigned char cs[];
    ushort_t* sIh = (ushort_t*)(cs);
    ushort_t* sIl = (ushort_t*)(cs + 16320);
    ushort_t* sBh = (ushort_t*)(cs + 32640);
    ushort_t* sBl = (ushort_t*)(cs + 48000);
    int tid = threadIdx.x, wid = tid >> 5, lid = tid & 31;
    int mt = blockIdx.x;
    int b = mt >> 3, r0 = (mt & 7) * 4;
    int n0 = blockIdx.y * 64;
    int wm = wid & 3, wn = wid >> 2;
    int arow = ((lid >> 3) & 1) * 8 + (lid & 7);
    int akof = (lid >> 4) * 8;
    int brow = (lid & 7) + ((lid >> 4) & 1) * 8;
    int bkof = ((lid >> 3) & 1) * 8;
    uint32_t uIh = smem_u32(sIh), uIl = smem_u32(sIl);
    uint32_t uBh = smem_u32(sBh), uBl = smem_u32(sBl);
    uint32_t aoff[2];
    #pragma unroll
    for (int tm = 0; tm < 2; tm++) {
        int p = wm * 32 + tm * 16 + arow;
        aoff[tm] = (uint32_t)(((p >> 5) * 34 + (p & 31)) * 80 + akof * 2);
    }
    uint32_t boff = (uint32_t)((wn * 32 + brow) * 80 + bkof * 2);

    float d[2][4][4];
    #pragma unroll
    for (int i = 0; i < 2; i++)
        #pragma unroll
        for (int j = 0; j < 4; j++)
            #pragma unroll
            for (int q = 0; q < 4; q++) d[i][j][q] = 0.f;

    for (int ch = 0; ch < CI; ch += 32) {
        const ushort_t* srcH;
        const ushort_t* srcL;
        int cw, coff;
        if (ch < csplit) { srcH = Ah0; srcL = Al0; cw = csplit; coff = ch; }
        else             { srcH = Ah1; srcL = Al1; cw = CI - csplit; coff = ch - csplit; }
        for (int idx = tid; idx < 816; idx += 256) {
            int sp = idx >> 2, seg = idx & 3;
            int srow = sp / 34, scol = sp - srow * 34;
            int gy = r0 - 1 + srow, gx = scol - 1;
            uint4 vh = make_uint4(0, 0, 0, 0), vl = make_uint4(0, 0, 0, 0);
            if ((unsigned)gy < 32u && (unsigned)gx < 32u) {
                size_t off = (size_t)(b * 1024 + (gy << 5) + gx) * cw + coff + seg * 8;
                vh = *(const uint4*)(srcH + off);
                vl = *(const uint4*)(srcL + off);
            }
            *(uint4*)(sIh + sp * 40 + seg * 8) = vh;
            *(uint4*)(sIl + sp * 40 + seg * 8) = vl;
        }
        #pragma unroll 1
        for (int ky = 0; ky < 3; ky++) {
            for (int idx = tid; idx < 768; idx += 256) {
                int kx = idx >> 8, rem = idx & 255, oc = rem >> 2, seg = rem & 3;
                size_t woff = ((size_t)((ky * 3 + kx) * CO + n0 + oc)) * CI + ch + seg * 8;
                *(uint4*)(sBh + (kx * 64 + oc) * 40 + seg * 8) = *(const uint4*)(Wh + woff);
                *(uint4*)(sBl + (kx * 64 + oc) * 40 + seg * 8) = *(const uint4*)(Wl + woff);
            }
            __syncthreads();
            #pragma unroll
            for (int kx = 0; kx < 3; kx++) {
                uint32_t shoff = (uint32_t)((ky * 34 + kx) * 80);
                #pragma unroll
                for (int ks = 0; ks < 2; ks++) {
                    uint32_t kso = (uint32_t)(ks * 32);
                    uint32_t ah[2][4], al[2][4];
                    #pragma unroll
                    for (int tm = 0; tm < 2; tm++) {
                        ldsm_x4(ah[tm][0], ah[tm][1], ah[tm][2], ah[tm][3],
                                uIh + aoff[tm] + shoff + kso);
                        ldsm_x4(al[tm][0], al[tm][1], al[tm][2], al[tm][3],
                                uIl + aoff[tm] + shoff + kso);
                    }
                    uint32_t bh[4][2], bl[4][2];
                    #pragma unroll
                    for (int p = 0; p < 2; p++) {
                        uint32_t off = boff + (uint32_t)(kx * 64 * 80 + p * 16 * 80) + kso;
                        ldsm_x4(bh[2 * p][0], bh[2 * p][1], bh[2 * p + 1][0], bh[2 * p + 1][1],
                                uBh + off);
                        ldsm_x4(bl[2 * p][0], bl[2 * p][1], bl[2 * p + 1][0], bl[2 * p + 1][1],
                                uBl + off);
                    }
                    #pragma unroll
                    for (int tm = 0; tm < 2; tm++)
                        #pragma unroll
                        for (int tn = 0; tn < 4; tn++) {
                            mma_bf16(d[tm][tn][0], d[tm][tn][1], d[tm][tn][2], d[tm][tn][3],
                                     ah[tm][0], ah[tm][1], ah[tm][2], ah[tm][3],
                                     bh[tn][0], bh[tn][1]);
                            mma_bf16(d[tm][tn][0], d[tm][tn][1], d[tm][tn][2], d[tm][tn][3],
                                     ah[tm][0], ah[tm][1], ah[tm][2], ah[tm][3],
                                     bl[tn][0], bl[tn][1]);
                            mma_bf16(d[tm][tn][0], d[tm][tn][1], d[tm][tn][2], d[tm][tn][3],
                                     al[tm][0], al[tm][1], al[tm][2], al[tm][3],
                                     bh[tn][0], bh[tn][1]);
                        }
                }
            }
            __syncthreads();
        }
    }
    int tq = lid >> 2, tr = lid & 3;
    #pragma unroll
    for (int tm = 0; tm < 2; tm++) {
        #pragma unroll
        for (int half = 0; half < 2; half++) {
            int pt = wm * 32 + tm * 16 + tq + half * 8;
            size_t prow = (size_t)(b * 1024 + r0 * 32 + pt) * CO;
            #pragma unroll
            for (int tn = 0; tn < 4; tn++) {
                int col = n0 + wn * 32 + tn * 8 + 2 * tr;
                float v0 = d[tm][tn][2 * half] + bias[col];
                float v1 = d[tm][tn][2 * half + 1] + bias[col + 1];
                if (relu) { v0 = fmaxf(v0, 0.f); v1 = fmaxf(v1, 0.f); }
                float2 o; o.x = v0; o.y = v1;
                *(float2*)(out + prow + col) = o;
            }
        }
    }
}
static const int CONV_SMEM = 63360;

/* ---------------- prep kernels ---------------- */
/* merged: z 0-3 = content -> cT, z 4-7 = style -> sT */
__global__ __launch_bounds__(256) void transpose_split2(
    const float* __restrict__ xc, const float* __restrict__ xs,
    ushort_t* __restrict__ ohc, ushort_t* __restrict__ olc,
    ushort_t* __restrict__ ohs, ushort_t* __restrict__ ols) {
    __shared__ float tb[32][33];
    int z = blockIdx.z;
    const float* x = (z < 4) ? xc : xs;
    ushort_t* oh = (z < 4) ? ohc : ohs;
    ushort_t* ol = (z < 4) ? olc : ols;
    int b = z & 3;
    int i0 = blockIdx.x * 32, d0 = blockIdx.y * 32;
    int tx = threadIdx.x & 31, ty = threadIdx.x >> 5;
    const float* xb = x + (size_t)b * 512 * 1024;
    #pragma unroll
    for (int k = 0; k < 4; k++)
        tb[ty + k * 8][tx] = xb[(size_t)(d0 + ty + k * 8) * 1024 + i0 + tx];
    __syncthreads();
    #pragma unroll
    for (int k = 0; k < 4; k++) {
        int il = ty + k * 8;
        float v = tb[tx][il];
        ushort_t h, l;
        bsplit(v, h, l);
        size_t o = (size_t)b * 1024 * 512 + (size_t)(i0 + il) * 512 + d0 + tx;
        oh[o] = h; ol[o] = l;
    }
}

__global__ __launch_bounds__(256) void convert_split(
    const float* __restrict__ x, ushort_t* __restrict__ oh,
    ushort_t* __restrict__ ol, int npair) {
    int i = blockIdx.x * 256 + threadIdx.x;
    if (i >= npair) return;
    float2 v = ((const float2*)x)[i];
    ushort_t h0, l0, h1, l1;
    bsplit(v.x, h0, l0);
    bsplit(v.y, h1, l1);
    ((uint32_t*)oh)[i] = ((uint32_t)h1 << 16) | h0;
    ((uint32_t*)ol)[i] = ((uint32_t)l1 << 16) | l0;
}

/* merged rownorm: blocks 0..511 content, 512..1023 style */
__global__ __launch_bounds__(256) void rownorm_t2(
    const ushort_t* __restrict__ xh0, const ushort_t* __restrict__ xl0,
    const ushort_t* __restrict__ xh1, const ushort_t* __restrict__ xl1,
    float* __restrict__ rn0, float* __restrict__ rn1) {
    int big = blockIdx.x >= 512;
    const ushort_t* xh = big ? xh1 : xh0;
    const ushort_t* xl = big ? xl1 : xl0;
    float* rn = big ? rn1 : rn0;
    int row = (blockIdx.x & 511) * 8 + (threadIdx.x >> 5);
    int lane = threadIdx.x & 31;
    const uint4* ph = (const uint4*)(xh + (size_t)row * 512);
    const uint4* pl = (const uint4*)(xl + (size_t)row * 512);
    float s = 0.f;
    #pragma unroll
    for (int k = 0; k < 2; k++) {
        uint4 h4 = ph[lane + k * 32], l4 = pl[lane + k * 32];
        const ushort_t* hh = (const ushort_t*)&h4;
        const ushort_t* ll = (const ushort_t*)&l4;
        #pragma unroll
        for (int j = 0; j < 8; j++) {
            float v = bf2f(hh[j]) + bf2f(ll[j]);
            s = fmaf(v, v, s);
        }
    }
    s = warpSum(s);
    if (lane == 0) rn[row] = rsqrtf(s);
}

__global__ __launch_bounds__(256) void wprep(const float* __restrict__ w,
                                             ushort_t* __restrict__ wh,
                                             ushort_t* __restrict__ wl,
                                             int CO, int CI) {
    int i = blockIdx.x * 256 + threadIdx.x;
    if (i >= CO * CI) return;
    int oc = i / CI, ci = i - oc * CI;
    #pragma unroll
    for (int k = 0; k < 9; k++) {
        float v = w[(size_t)i * 9 + k];
        ushort_t h, l;
        bsplit(v, h, l);
        size_t o = ((size_t)k * CO + oc) * CI + ci;
        wh[o] = h; wl[o] = l;
    }
}

/* ---------------- Sinkhorn (R9-verbatim shapes) ---------------- */
__global__ void zero_v(float* v) {
    int i = blockIdx.x * blockDim.x + threadIdx.x;
    if (i < 4096) v[i] = 0.f;
}

__global__ __launch_bounds__(256) void u_update(const float* __restrict__ C,
                                                const float* __restrict__ v,
                                                float* __restrict__ u) {
    int b = blockIdx.y, i = blockIdx.x, t = threadIdx.x;
    const float4* C4 = (const float4*)(C + ((size_t)(b << 10) + i) * 1024);
    const float4* V4 = (const float4*)(v + (b << 10));
    float4 c = C4[t], vv = V4[t];
    float x0 = (vv.x - c.x) * INV_EPS;
    float x1 = (vv.y - c.y) * INV_EPS;
    float x2 = (vv.z - c.z) * INV_EPS;
    float x3 = (vv.w - c.w) * INV_EPS;
    float mx = fmaxf(fmaxf(x0, x1), fmaxf(x2, x3));
    __shared__ float redm[8], redq[8];
    mx = warpMax(mx);
    if ((t & 31) == 0) redm[t >> 5] = mx;
    __syncthreads();
    if (t < 32) {
        float z = (t < 8) ? redm[t] : -FLT_MAX;
        #pragma unroll
        for (int o = 4; o; o >>= 1) z = fmaxf(z, __shfl_xor_sync(0xffffffffu, z, o));
        if (t == 0) redm[0] = z;
    }
    __syncthreads();
    float bm = redm[0];
    float s = __expf(x0 - bm) + __expf(x1 - bm) + __expf(x2 - bm) + __expf(x3 - bm);
    s = warpSum(s);
    if ((t & 31) == 0) redq[t >> 5] = s;
    __syncthreads();
    if (t == 0) {
        float z = 0.f;
        #pragma unroll
        for (int q = 0; q < 8; q++) z += redq[q];
        u[(b << 10) + i] = EPS_S * (LOG_MU - (bm + __logf(z)));
    }
}

__global__ __launch_bounds__(256) void v_update(const float* __restrict__ C,
                                                const float* __restrict__ u,
                                                float* __restrict__ v) {
    int b = blockIdx.y;
    int tx = threadIdx.x, ty = threadIdx.y;
    int j = blockIdx.x * 32 + tx;
    const float* p = C + (size_t)b * 1048576 + j;
    const float* ub = u + (b << 10);
    float m0 = -FLT_MAX, s0 = 0.f, m1 = -FLT_MAX, s1 = 0.f;
    for (int i = ty; i < 1024; i += 16) {
        float xa = (ub[i] - p[(size_t)i << 10]) * INV_EPS;
        float xb = (ub[i + 8] - p[(size_t)(i + 8) << 10]) * INV_EPS;
        float n0 = fmaxf(m0, xa);
        s0 = s0 * __expf(m0 - n0) + __expf(xa - n0); m0 = n0;
        float n1 = fmaxf(m1, xb);
        s1 = s1 * __expf(m1 - n1) + __expf(xb - n1); m1 = n1;
    }
    float mm = fmaxf(m0, m1);
    float ss = s0 * __expf(m0 - mm) + s1 * __expf(m1 - mm);
    __shared__ float sm[8][32], sq[8][32];
    sm[ty][tx] = mm; sq[ty][tx] = ss;
    __syncthreads();
    if (ty == 0) {
        float M = mm, S = ss;
        #pragma unroll
        for (int q = 1; q < 8; q++) {
            float m2 = sm[q][tx], s2 = sq[q][tx];
            float nm = fmaxf(M, m2);
            S = S * __expf(M - nm) + s2 * __expf(m2 - nm);
            M = nm;
        }
        v[(b << 10) + j] = EPS_S * (LOG_MU - (M + __logf(S)));
    }
}

__global__ __launch_bounds__(256) void pi_gen(
    const float* __restrict__ C, const float* __restrict__ u,
    const float* __restrict__ v, ushort_t* __restrict__ ph,
    ushort_t* __restrict__ pl) {
    int b = blockIdx.y, i = blockIdx.x, t = threadIdx.x;
    float ui = u[(b << 10) + i];
    const float2* Crow = (const float2*)(C + ((size_t)(b << 10) + i) * 1024);
    const float2* vrow = (const float2*)(v + (b << 10));
    uint32_t* phr = (uint32_t*)(ph + ((size_t)(b << 10) + i) * 1024);
    uint32_t* plr = (uint32_t*)(pl + ((size_t)(b << 10) + i) * 1024);
    #pragma unroll
    for (int l = 0; l < 2; l++) {
        int j2 = t + l * 256;
        float2 c2 = Crow[j2], v2 = vrow[j2];
        float p0 = __expf((ui + v2.x - c2.x) * INV_EPS) * 1024.f;
        float p1 = __expf((ui + v2.y - c2.y) * INV_EPS) * 1024.f;
        ushort_t h0, l0, h1, l1;
        bsplit(p0, h0, l0);
        bsplit(p1, h1, l1);
        phr[j2] = ((uint32_t)h1 << 16) | h0;
        plr[j2] = ((uint32_t)l1 << 16) | l0;
    }
}

/* ---------------- per-(b,c) mean / 1/std of content (NCHW) ---------------- */
__global__ __launch_bounds__(128) void cmstd(const float* __restrict__ x,
                                             float* __restrict__ cm,
                                             float* __restrict__ rs) {
    int bc = blockIdx.x, t = threadIdx.x;
    const float* p = x + ((size_t)bc << 10);
    float s = 0.f, q = 0.f;
    #pragma unroll
    for (int l = 0; l < 8; l++) {
        float v = p[t + l * 128];
        s += v; q = fmaf(v, v, q);
    }
    s = warpSum(s); q = warpSum(q);
    __shared__ float rsm[4], rqm[4];
    if ((t & 31) == 0) { rsm[t >> 5] = s; rqm[t >> 5] = q; }
    __syncthreads();
    if (t == 0) {
        float S = rsm[0] + rsm[1] + rsm[2] + rsm[3];
        float Q = rqm[0] + rqm[1] + rqm[2] + rqm[3];
        float mean = S * (1.f / 1024.f);
        float var = Q * (1.f / 1024.f) - mean * mean;
        cm[bc] = mean;
        rs[bc] = rsqrtf(fmaxf(var, 0.f) + 1e-5f);
    }
}

/* ---------------- BatchNorm (NHWC, two-phase, deterministic) --------------- */
__global__ __launch_bounds__(256) void bnpart(const float* __restrict__ x,
                                              float* __restrict__ ps,
                                              float* __restrict__ pq) {
    int slab = blockIdx.x, t = threadIdx.x;
    float s = 0.f, q = 0.f;
    #pragma unroll
    for (int i = 0; i < 16; i++) {
        float v = x[(size_t)(slab * 16 + i) * 256 + t];
        s += v; q = fmaf(v, v, q);
    }
    ps[slab * 256 + t] = s;
    pq[slab * 256 + t] = q;
}
__global__ void bnfin(const float* __restrict__ ps, const float* __restrict__ pq,
                      const float* __restrict__ g, const float* __restrict__ be,
                      float* __restrict__ scale, float* __restrict__ shift) {
    int c = threadIdx.x;
    float s = 0.f, q = 0.f;
    for (int k = 0; k < 256; k++) { s += ps[k * 256 + c]; q += pq[k * 256 + c]; }
    float mean = s * (1.f / 4096.f);
    float var = q * (1.f / 4096.f) - mean * mean;
    float sc = g[c] * rsqrtf(fmaxf(var, 0.f) + BN_EPS);
    scale[c] = sc;
    shift[c] = be[c] - mean * sc;
}
__global__ __launch_bounds__(256) void bn_split(const float* __restrict__ x,
                                                const float* __restrict__ scale,
                                                const float* __restrict__ shift,
                                                ushort_t* __restrict__ oh,
                                                ushort_t* __restrict__ ol) {
    int i = blockIdx.x * 256 + threadIdx.x;
    int c = i & 255;
    float v = fmaf(x[i], scale[c], shift[c]);
    ushort_t h, l;
    bsplit(v, h, l);
    oh[i] = h; ol[i] = l;
}

/* -------- blend + transpose: tblend NCHW = t + alpha*(content-cm)*rs ------- */
__global__ __launch_bounds__(256) void blend_T(const float* __restrict__ tn,
                                               const float* __restrict__ an,
                                               const float* __restrict__ content,
                                               const float* __restrict__ cm,
                                               const float* __restrict__ rs,
                                               float* __restrict__ outc) {
    __shared__ float ts[32][33], as_[32][33];
    int pix0 = blockIdx.x * 32, ch0 = blockIdx.y * 32;
    int tx = threadIdx.x & 31, ty = threadIdx.x >> 5;
    #pragma unroll
    for (int k = 0; k < 4; k++) {
        int p = pix0 + ty + k * 8;
        ts[ty + k * 8][tx]  = tn[(size_t)p * 512 + ch0 + tx];
        as_[ty + k * 8][tx] = an[(size_t)p * 512 + ch0 + tx];
    }
    __syncthreads();
    int b = pix0 >> 10;
    int pl = pix0 & 1023;
    #pragma unroll
    for (int k = 0; k < 4; k++) {
        int cl = ty + k * 8;
        int gch = b * 512 + ch0 + cl;
        float m = cm[gch], r = rs[gch];
        float c = content[(size_t)gch * 1024 + pl + tx];
        float v = fmaf(as_[tx][cl], (c - m) * r, ts[tx][cl]);
        outc[(size_t)gch * 1024 + pl + tx] = v;
    }
}

/* ---------------- decoder conv: bias init + CI-split accumulation ---------- */
__global__ void dec_init(const float* __restrict__ db, float* __restrict__ out) {
    int i = blockIdx.x * 256 + threadIdx.x;      /* 12288 = 4*3*1024 */
    if (i < 4 * 3 * 1024) out[i] = db[(i >> 10) % 3];
}

/* grid (4 batches, 8 ci-groups, 8 row-strips), block 128; atomicAdd epilogue */
__global__ __launch_bounds__(128) void conv3x3_dec(
    const float* __restrict__ src0, const float* __restrict__ W,
    float* __restrict__ out) {
    constexpr int OCT = 4, SROWS = 4, NT = 128, CIT = 8;
    __shared__ float s_in[CIT][SROWS + 2][34];
    __shared__ float s_w[CIT][9][OCT];
    const int CI = 512, CO = 3;
    int b = blockIdx.x, cg0 = blockIdx.y * 64, r0 = blockIdx.z * SROWS;
    int tid = threadIdx.x;
    int row = tid >> 5, col = tid & 31;
    float acc[OCT];
    #pragma unroll
    for (int o = 0; o < OCT; o++) acc[o] = 0.f;

    const int TOTIN = CIT * (SROWS + 2) * 34;
    const int TW = CIT * 9 * OCT;
    #pragma unroll 1
    for (int ci0 = cg0; ci0 < cg0 + 64; ci0 += CIT) {
        #pragma unroll 1
        for (int idx = tid; idx < TOTIN; idx += NT) {
            int ci = idx / ((SROWS + 2) * 34);
            int rem = idx - ci * ((SROWS + 2) * 34);
            int r = rem / 34, c = rem - r * 34;
            int gy = r0 + r - 1, gx = c - 1;
            float v = 0.f;
            if ((unsigned)gy < 32u && (unsigned)gx < 32u)
                v = src0[((size_t)(b * CI + ci0 + ci) << 10) + (gy << 5) + gx];
            (&s_in[0][0][0])[idx] = v;
        }
        #pragma unroll 1
        for (int idx = tid; idx < TW; idx += NT) {
            int ci = idx / (9 * OCT);
            int rem = idx - ci * (9 * OCT);
            int k = rem / OCT, oc = rem - k * OCT;
            float wv = 0.f;
            if (oc < CO)
                wv = W[((size_t)oc * CI + ci0 + ci) * 9 + k];
            (&s_w[0][0][0])[idx] = wv;
        }
        __syncthreads();
        #pragma unroll 1
        for (int ci = 0; ci < CIT; ci++) {
            #pragma unroll
            for (int ky = 0; ky < 3; ky++)
                #pragma unroll
                for (int kx = 0; kx < 3; kx++) {
                    float4 w4 = *(const float4*)&s_w[ci][ky * 3 + kx][0];
                    float v = s_in[ci][row + ky][col + kx];
                    acc[0] = fmaf(v, w4.x, acc[0]);
                    acc[1] = fmaf(v, w4.y, acc[1]);
                    acc[2] = fmaf(v, w4.z, acc[2]);
                    acc[3] = fmaf(v, w4.w, acc[3]);
                }
        }
        __syncthreads();
    }
    #pragma unroll
    for (int o = 0; o < 3; o++)
        atomicAdd(out + ((size_t)(b * 3 + o) << 10) + (r0 + row) * 32 + col, acc[o]);
}

/* ---------------- host orchestration ---------------- */
extern "C" void kernel_launch(void* const* d_in, const int* in_sizes, int n_in,
                              void* d_out, int out_size) {
    const float* content = (const float*)d_in[0];
    const float* style   = (const float*)d_in[1];
    const float* w1 = (const float*)d_in[2];  const float* b1 = (const float*)d_in[3];
    const float* g1 = (const float*)d_in[4];  const float* be1 = (const float*)d_in[5];
    const float* w2 = (const float*)d_in[6];  const float* b2 = (const float*)d_in[7];
    const float* g2 = (const float*)d_in[8];  const float* be2 = (const float*)d_in[9];
    const float* w3 = (const float*)d_in[10]; const float* b3 = (const float*)d_in[11];
    const float* dw = (const float*)d_in[12]; const float* db = (const float*)d_in[13];
    float* out = (float*)d_out;
    (void)in_sizes; (void)n_in; (void)out_size;

    float *pC, *pu, *pv, *prnx, *prny, *pt, *pa1, *pa2, *palpha, *pcm, *prs,
          *pscale, *pshift, *pps, *ppq;
    ushort_t *pcTh, *pcTl, *psTh, *psTl, *psfh, *psfl, *ppih, *ppil,
             *ptth, *pttl, *pb1h, *pb1l, *pb2h, *pb2l,
             *pw1h, *pw1l, *pw2h, *pw2l, *pw3h, *pw3l;
    cudaGetSymbolAddress((void**)&pC, g_C);
    cudaGetSymbolAddress((void**)&pu, g_u);
    cudaGetSymbolAddress((void**)&pv, g_v);
    cudaGetSymbolAddress((void**)&prnx, g_rnx);
    cudaGetSymbolAddress((void**)&prny, g_rny);
    cudaGetSymbolAddress((void**)&pt, g_t);
    cudaGetSymbolAddress((void**)&pa1, g_a1);
    cudaGetSymbolAddress((void**)&pa2, g_a2);
    cudaGetSymbolAddress((void**)&palpha, g_alpha);
    cudaGetSymbolAddress((void**)&pcm, g_cm);
    cudaGetSymbolAddress((void**)&prs, g_rs);
    cudaGetSymbolAddress((void**)&pscale, g_scale);
    cudaGetSymbolAddress((void**)&pshift, g_shift);
    cudaGetSymbolAddress((void**)&pps, g_ps);
    cudaGetSymbolAddress((void**)&ppq, g_pq);
    cudaGetSymbolAddress((void**)&pcTh, g_cTh);
    cudaGetSymbolAddress((void**)&pcTl, g_cTl);
    cudaGetSymbolAddress((void**)&psTh, g_sTh);
    cudaGetSymbolAddress((void**)&psTl, g_sTl);
    cudaGetSymbolAddress((void**)&psfh, g_sfh);
    cudaGetSymbolAddress((void**)&psfl, g_sfl);
    cudaGetSymbolAddress((void**)&ppih, g_pih);
    cudaGetSymbolAddress((void**)&ppil, g_pil);
    cudaGetSymbolAddress((void**)&ptth, g_tth);
    cudaGetSymbolAddress((void**)&pttl, g_ttl);
    cudaGetSymbolAddress((void**)&pb1h, g_b1h);
    cudaGetSymbolAddress((void**)&pb1l, g_b1l);
    cudaGetSymbolAddress((void**)&pb2h, g_b2h);
    cudaGetSymbolAddress((void**)&pb2l, g_b2l);
    cudaGetSymbolAddress((void**)&pw1h, g_w1h);
    cudaGetSymbolAddress((void**)&pw1l, g_w1l);
    cudaGetSymbolAddress((void**)&pw2h, g_w2h);
    cudaGetSymbolAddress((void**)&pw2l, g_w2l);
    cudaGetSymbolAddress((void**)&pw3h, g_w3h);
    cudaGetSymbolAddress((void**)&pw3l, g_w3l);

    cudaFuncSetAttribute(conv_hmma, cudaFuncAttributeMaxDynamicSharedMemorySize, CONV_SMEM);

    /* operand prep (merged launches) */
    transpose_split2<<<dim3(32, 16, 8), 256>>>(content, style, pcTh, pcTl, psTh, psTl);
    convert_split<<<4096, 256>>>(style, psfh, psfl, 4 * 512 * 512);
    rownorm_t2<<<1024, 256>>>(pcTh, pcTl, psTh, psTl, prnx, prny);
    wprep<<<1024, 256>>>(w1, pw1h, pw1l, 256, 1024);
    wprep<<<256, 256>>>(w2, pw2h, pw2l, 256, 256);
    wprep<<<512, 256>>>(w3, pw3h, pw3l, 512, 256);

    /* cosine-cost matrix */
    hmma_gemm<1><<<dim3(8, 16, 4), 256>>>(pcTh, pcTl, psTh, psTl,
        1024, 512, 1024, 1024, prnx, prny, pC, nullptr, nullptr);

    /* Sinkhorn, 20 iterations (R9-verbatim shapes) */
    zero_v<<<16, 256>>>(pv);
    for (int it = 0; it < 20; it++) {
        u_update<<<dim3(1024, 4), 256>>>(pC, pv, pu);
        v_update<<<dim3(32, 4), dim3(32, 8)>>>(pC, pu, pv);
    }

    /* pi, then t = pi @ style^T -> NHWC fp32 + bf16 split */
    pi_gen<<<dim3(1024, 4), 256>>>(pC, pu, pv, ppih, ppil);
    hmma_gemm<2><<<dim3(8, 8, 4), 256>>>(ppih, ppil, psfh, psfl,
        1024, 1024, 512, 512, nullptr, nullptr, pt, ptth, pttl);

    cmstd<<<2048, 128>>>(content, pcm, prs);

    /* alpha predictor via tensor convs (NHWC) */
    conv_hmma<<<dim3(32, 4), 256, CONV_SMEM>>>(ptth, pttl, pcTh, pcTl, 512, 1024,
        pw1h, pw1l, 256, b1, 1, pa1);
    bnpart<<<256, 256>>>(pa1, pps, ppq);
    bnfin<<<1, 256>>>(pps, ppq, g1, be1, pscale, pshift);
    bn_split<<<4096, 256>>>(pa1, pscale, pshift, pb1h, pb1l);
    conv_hmma<<<dim3(32, 4), 256, CONV_SMEM>>>(pb1h, pb1l, pb1h, pb1l, 256, 256,
        pw2h, pw2l, 256, b2, 1, pa2);
    bnpart<<<256, 256>>>(pa2, pps, ppq);
    bnfin<<<1, 256>>>(pps, ppq, g2, be2, pscale, pshift);
    bn_split<<<4096, 256>>>(pa2, pscale, pshift, pb2h, pb2l);
    conv_hmma<<<dim3(32, 8), 256, CONV_SMEM>>>(pb2h, pb2l, pb2h, pb2l, 256, 256,
        pw3h, pw3l, 512, b3, 0, palpha);

    /* blend (transposed to NCHW), decoder conv (CI-split, atomic accum) */
    blend_T<<<dim3(128, 16), 256>>>(pt, palpha, content, pcm, prs, pC);
    dec_init<<<48, 256>>>(db, out);
    conv3x3_dec<<<dim3(4, 8, 8), 128>>>(pC, dw, out);
}

// round 13
// speedup vs baseline: 1.8693x; 1.1577x over previous
#include <cuda_runtime.h>
#include <cuda_bf16.h>
#include <cfloat>
#include <cstdint>

#define EPS_S   0.01f
#define INV_EPS 100.0f
#define LOG_MU  -6.93146200f   /* log(1/1024 + 1e-8) */
#define BN_EPS  1e-5f

typedef unsigned short ushort_t;

/* ---------------- scratch (device globals: no allocs allowed) -------------- */
__device__ float g_C[4 * 1024 * 1024];          /* cost matrix; later tblend NCHW */
__device__ float g_u[4096], g_v[4096];
__device__ float g_rnx[4096], g_rny[4096];
__device__ float g_t[4 * 1024 * 512];           /* t NHWC fp32 [pix][512] */
__device__ float g_a1[4 * 1024 * 256];
__device__ float g_a2[4 * 1024 * 256];
__device__ float g_alpha[4 * 1024 * 512];
__device__ float g_cm[2048], g_rs[2048];
__device__ float g_scale[512], g_shift[512];
__device__ float g_ps[256 * 256], g_pq[256 * 256];
/* bf16 split buffers */
__device__ ushort_t g_cTh[4 * 1024 * 512], g_cTl[4 * 1024 * 512];
__device__ ushort_t g_sTh[4 * 1024 * 512], g_sTl[4 * 1024 * 512];
__device__ ushort_t g_sfh[4 * 512 * 1024], g_sfl[4 * 512 * 1024];
__device__ ushort_t g_pih[4 * 1024 * 1024], g_pil[4 * 1024 * 1024];
__device__ ushort_t g_tth[4 * 1024 * 512], g_ttl[4 * 1024 * 512];
__device__ ushort_t g_b1h[4 * 1024 * 256], g_b1l[4 * 1024 * 256];
__device__ ushort_t g_b2h[4 * 1024 * 256], g_b2l[4 * 1024 * 256];
__device__ ushort_t g_w1h[9 * 256 * 1024], g_w1l[9 * 256 * 1024];
__device__ ushort_t g_w2h[9 * 256 * 256],  g_w2l[9 * 256 * 256];
__device__ ushort_t g_w3h[9 * 512 * 256],  g_w3l[9 * 512 * 256];

__device__ __forceinline__ uint32_t smem_u32(const void* p) {
    uint32_t a;
    asm("{ .reg .u64 t; cvta.to.shared.u64 t, %1; cvt.u32.u64 %0, t; }"
        : "=r"(a) : "l"(p));
    return a;
}
__device__ __forceinline__ void ldsm_x4(uint32_t& r0, uint32_t& r1,
                                        uint32_t& r2, uint32_t& r3, uint32_t a) {
    asm volatile("ldmatrix.sync.aligned.m8n8.x4.shared.b16 {%0,%1,%2,%3}, [%4];"
                 : "=r"(r0), "=r"(r1), "=r"(r2), "=r"(r3) : "r"(a));
}
__device__ __forceinline__ void mma_bf16(float& d0, float& d1, float& d2, float& d3,
                                         uint32_t a0, uint32_t a1, uint32_t a2, uint32_t a3,
                                         uint32_t b0, uint32_t b1) {
    asm volatile(
        "mma.sync.aligned.m16n8k16.row.col.f32.bf16.bf16.f32 "
        "{%0,%1,%2,%3}, {%4,%5,%6,%7}, {%8,%9}, {%0,%1,%2,%3};"
        : "+f"(d0), "+f"(d1), "+f"(d2), "+f"(d3)
        : "r"(a0), "r"(a1), "r"(a2), "r"(a3), "r"(b0), "r"(b1));
}
__device__ __forceinline__ void bsplit(float v, ushort_t& h, ushort_t& l) {
    __nv_bfloat16 hh = __float2bfloat16(v);
    float rem = v - __bfloat162float(hh);
    __nv_bfloat16 ll = __float2bfloat16(rem);
    h = __bfloat16_as_ushort(hh);
    l = __bfloat16_as_ushort(ll);
}
__device__ __forceinline__ float bf2f(ushort_t x) {
    return __bfloat162float(__ushort_as_bfloat16(x));
}
__device__ __forceinline__ float warpSum(float v) {
    #pragma unroll
    for (int o = 16; o; o >>= 1) v += __shfl_xor_sync(0xffffffffu, v, o);
    return v;
}
__device__ __forceinline__ float warpMax(float v) {
    #pragma unroll
    for (int o = 16; o; o >>= 1) v = fmaxf(v, __shfl_xor_sync(0xffffffffu, v, o));
    return v;
}

/* ============ HMMA bf16 split GEMM (verified core) ======================== */
template <int EPI>
__global__ __launch_bounds__(256) void hmma_gemm(
    const ushort_t* __restrict__ Ahi, const ushort_t* __restrict__ Alo,
    const ushort_t* __restrict__ Bhi, const ushort_t* __restrict__ Blo,
    int Mtot, int Ktot, int Nrows, int OS,
    const float* __restrict__ rnx, const float* __restrict__ rny,
    float* __restrict__ out, ushort_t* __restrict__ o2h, ushort_t* __restrict__ o2l) {
    __shared__ ushort_t sAh[128 * 40], sAl[128 * 40];
    __shared__ ushort_t sBh[64 * 40], sBl[64 * 40];
    int tid = threadIdx.x, wid = tid >> 5, lid = tid & 31;
    int b = blockIdx.z, m0 = blockIdx.x * 128, n0 = blockIdx.y * 64;
    int wm = wid & 3, wn = wid >> 2;
    size_t abase = (size_t)b * Mtot * Ktot;
    size_t bbase = (size_t)b * Nrows * Ktot;
    uint32_t uAh = smem_u32(sAh), uAl = smem_u32(sAl);
    uint32_t uBh = smem_u32(sBh), uBl = smem_u32(sBl);
    int arow = ((lid >> 3) & 1) * 8 + (lid & 7);
    int akof = (lid >> 4) * 8;
    int brow = (lid & 7) + ((lid >> 4) & 1) * 8;
    int bkof = ((lid >> 3) & 1) * 8;

    float d[2][4][4];
    #pragma unroll
    for (int i = 0; i < 2; i++)
        #pragma unroll
        for (int j = 0; j < 4; j++)
            #pragma unroll
            for (int q = 0; q < 4; q++) d[i][j][q] = 0.f;

    for (int k0 = 0; k0 < Ktot; k0 += 32) {
        #pragma unroll
        for (int l = 0; l < 2; l++) {
            int idx = tid + l * 256;
            int r = idx >> 2, seg = idx & 3;
            *(uint4*)(sAh + r * 40 + seg * 8) =
                *(const uint4*)(Ahi + abase + (size_t)(m0 + r) * Ktot + k0 + seg * 8);
            *(uint4*)(sAl + r * 40 + seg * 8) =
                *(const uint4*)(Alo + abase + (size_t)(m0 + r) * Ktot + k0 + seg * 8);
        }
        {
            int r = tid >> 2, seg = tid & 3;
            *(uint4*)(sBh + r * 40 + seg * 8) =
                *(const uint4*)(Bhi + bbase + (size_t)(n0 + r) * Ktot + k0 + seg * 8);
            *(uint4*)(sBl + r * 40 + seg * 8) =
                *(const uint4*)(Blo + bbase + (size_t)(n0 + r) * Ktot + k0 + seg * 8);
        }
        __syncthreads();
        #pragma unroll
        for (int ks = 0; ks < 2; ks++) {
            int kb = ks * 16;
            uint32_t ah[2][4], al[2][4];
            #pragma unroll
            for (int tm = 0; tm < 2; tm++) {
                uint32_t off = (uint32_t)((wm * 32 + tm * 16 + arow) * 80 + (kb + akof) * 2);
                ldsm_x4(ah[tm][0], ah[tm][1], ah[tm][2], ah[tm][3], uAh + off);
                ldsm_x4(al[tm][0], al[tm][1], al[tm][2], al[tm][3], uAl + off);
            }
            uint32_t bh[4][2], bl[4][2];
            #pragma unroll
            for (int p = 0; p < 2; p++) {
                uint32_t off = (uint32_t)((wn * 32 + p * 16 + brow) * 80 + (kb + bkof) * 2);
                ldsm_x4(bh[2 * p][0], bh[2 * p][1], bh[2 * p + 1][0], bh[2 * p + 1][1], uBh + off);
                ldsm_x4(bl[2 * p][0], bl[2 * p][1], bl[2 * p + 1][0], bl[2 * p + 1][1], uBl + off);
            }
            #pragma unroll
            for (int tm = 0; tm < 2; tm++)
                #pragma unroll
                for (int tn = 0; tn < 4; tn++) {
                    mma_bf16(d[tm][tn][0], d[tm][tn][1], d[tm][tn][2], d[tm][tn][3],
                             ah[tm][0], ah[tm][1], ah[tm][2], ah[tm][3], bh[tn][0], bh[tn][1]);
                    mma_bf16(d[tm][tn][0], d[tm][tn][1], d[tm][tn][2], d[tm][tn][3],
                             ah[tm][0], ah[tm][1], ah[tm][2], ah[tm][3], bl[tn][0], bl[tn][1]);
                    mma_bf16(d[tm][tn][0], d[tm][tn][1], d[tm][tn][2], d[tm][tn][3],
                             al[tm][0], al[tm][1], al[tm][2], al[tm][3], bh[tn][0], bh[tn][1]);
                }
        }
        __syncthreads();
    }
    int tq = lid >> 2, tr = lid & 3;
    #pragma unroll
    for (int tm = 0; tm < 2; tm++) {
        #pragma unroll
        for (int half = 0; half < 2; half++) {
            int r = m0 + wm * 32 + tm * 16 + tq + half * 8;
            #pragma unroll
            for (int tn = 0; tn < 4; tn++) {
                int col = n0 + wn * 32 + tn * 8 + 2 * tr;
                float v0 = d[tm][tn][2 * half], v1 = d[tm][tn][2 * half + 1];
                size_t oidx = ((size_t)b * Mtot + r) * OS + col;
                if (EPI == 1) {
                    float rx = rnx[(b << 10) + r];
                    float2 o;
                    o.x = 1.f - rx * rny[(b << 10) + col] * v0;
                    o.y = 1.f - rx * rny[(b << 10) + col + 1] * v1;
                    *(float2*)(out + oidx) = o;
                } else {
                    float2 o; o.x = v0; o.y = v1;
                    *(float2*)(out + oidx) = o;
                    ushort_t h0, l0, h1, l1;
                    bsplit(v0, h0, l0);
                    bsplit(v1, h1, l1);
                    *(uint32_t*)(o2h + oidx) = ((uint32_t)h1 << 16) | h0;
                    *(uint32_t*)(o2l + oidx) = ((uint32_t)l1 << 16) | l0;
                }
            }
        }
    }
}

/* ============ shifted-GEMM tensor conv (NHWC, split bf16) ==================
   All 9 weight taps resident in smem; ONE fill + sync per ci-chunk.        */
__global__ __launch_bounds__(256) void conv_hmma(
    const ushort_t* __restrict__ Ah0, const ushort_t* __restrict__ Al0,
    const ushort_t* __restrict__ Ah1, const ushort_t* __restrict__ Al1,
    int csplit, int CI,
    const ushort_t* __restrict__ Wh, const ushort_t* __restrict__ Wl,
    int CO, const float* __restrict__ bias, int relu,
    float* __restrict__ out) {
    extern __shared__ unsigned char cs[];
    ushort_t* sIh = (ushort_t*)(cs);                 /* 204 x 40      = 16320 B */
    ushort_t* sIl = (ushort_t*)(cs + 16320);
    ushort_t* sBh = (ushort_t*)(cs + 32640);         /* 9 x 64 x 40   = 46080 B */
    ushort_t* sBl = (ushort_t*)(cs + 78720);
    int tid = threadIdx.x, wid = tid >> 5, lid = tid & 31;
    int mt = blockIdx.x;
    int b = mt >> 3, r0 = (mt & 7) * 4;
    int n0 = blockIdx.y * 64;
    int wm = wid & 3, wn = wid >> 2;
    int arow = ((lid >> 3) & 1) * 8 + (lid & 7);
    int akof = (lid >> 4) * 8;
    int brow = (lid & 7) + ((lid >> 4) & 1) * 8;
    int bkof = ((lid >> 3) & 1) * 8;
    uint32_t uIh = smem_u32(sIh), uIl = smem_u32(sIl);
    uint32_t uBh = smem_u32(sBh), uBl = smem_u32(sBl);
    uint32_t aoff[2];
    #pragma unroll
    for (int tm = 0; tm < 2; tm++) {
        int p = wm * 32 + tm * 16 + arow;
        aoff[tm] = (uint32_t)(((p >> 5) * 34 + (p & 31)) * 80 + akof * 2);
    }
    uint32_t boff = (uint32_t)((wn * 32 + brow) * 80 + bkof * 2);

    float d[2][4][4];
    #pragma unroll
    for (int i = 0; i < 2; i++)
        #pragma unroll
        for (int j = 0; j < 4; j++)
            #pragma unroll
            for (int q = 0; q < 4; q++) d[i][j][q] = 0.f;

    for (int ch = 0; ch < CI; ch += 32) {
        const ushort_t* srcH;
        const ushort_t* srcL;
        int cw, coff;
        if (ch < csplit) { srcH = Ah0; srcL = Al0; cw = csplit; coff = ch; }
        else             { srcH = Ah1; srcL = Al1; cw = CI - csplit; coff = ch - csplit; }
        /* fill input tile */
        for (int idx = tid; idx < 816; idx += 256) {
            int sp = idx >> 2, seg = idx & 3;
            int srow = sp / 34, scol = sp - srow * 34;
            int gy = r0 - 1 + srow, gx = scol - 1;
            uint4 vh = make_uint4(0, 0, 0, 0), vl = make_uint4(0, 0, 0, 0);
            if ((unsigned)gy < 32u && (unsigned)gx < 32u) {
                size_t off = (size_t)(b * 1024 + (gy << 5) + gx) * cw + coff + seg * 8;
                vh = *(const uint4*)(srcH + off);
                vl = *(const uint4*)(srcL + off);
            }
            *(uint4*)(sIh + sp * 40 + seg * 8) = vh;
            *(uint4*)(sIl + sp * 40 + seg * 8) = vl;
        }
        /* fill ALL 9 weight taps: 9 x 64 oc x 32 ci */
        for (int idx = tid; idx < 2304; idx += 256) {
            int tap = idx >> 8, rem = idx & 255, oc = rem >> 2, seg = rem & 3;
            size_t woff = ((size_t)(tap * CO + n0 + oc)) * CI + ch + seg * 8;
            *(uint4*)(sBh + (tap * 64 + oc) * 40 + seg * 8) = *(const uint4*)(Wh + woff);
            *(uint4*)(sBl + (tap * 64 + oc) * 40 + seg * 8) = *(const uint4*)(Wl + woff);
        }
        __syncthreads();
        #pragma unroll 1
        for (int ky = 0; ky < 3; ky++) {
            #pragma unroll
            for (int kx = 0; kx < 3; kx++) {
                uint32_t shoff = (uint32_t)((ky * 34 + kx) * 80);
                uint32_t tapoff = (uint32_t)((ky * 3 + kx) * 5120);
                #pragma unroll
                for (int ks = 0; ks < 2; ks++) {
                    uint32_t kso = (uint32_t)(ks * 32);
                    uint32_t ah[2][4], al[2][4];
                    #pragma unroll
                    for (int tm = 0; tm < 2; tm++) {
                        ldsm_x4(ah[tm][0], ah[tm][1], ah[tm][2], ah[tm][3],
                                uIh + aoff[tm] + shoff + kso);
                        ldsm_x4(al[tm][0], al[tm][1], al[tm][2], al[tm][3],
                                uIl + aoff[tm] + shoff + kso);
                    }
                    uint32_t bh[4][2], bl[4][2];
                    #pragma unroll
                    for (int p = 0; p < 2; p++) {
                        uint32_t off = boff + tapoff + (uint32_t)(p * 1280) + kso;
                        ldsm_x4(bh[2 * p][0], bh[2 * p][1], bh[2 * p + 1][0], bh[2 * p + 1][1],
                                uBh + off);
                        ldsm_x4(bl[2 * p][0], bl[2 * p][1], bl[2 * p + 1][0], bl[2 * p + 1][1],
                                uBl + off);
                    }
                    #pragma unroll
                    for (int tm = 0; tm < 2; tm++)
                        #pragma unroll
                        for (int tn = 0; tn < 4; tn++) {
                            mma_bf16(d[tm][tn][0], d[tm][tn][1], d[tm][tn][2], d[tm][tn][3],
                                     ah[tm][0], ah[tm][1], ah[tm][2], ah[tm][3],
                                     bh[tn][0], bh[tn][1]);
                            mma_bf16(d[tm][tn][0], d[tm][tn][1], d[tm][tn][2], d[tm][tn][3],
                                     ah[tm][0], ah[tm][1], ah[tm][2], ah[tm][3],
                                     bl[tn][0], bl[tn][1]);
                            mma_bf16(d[tm][tn][0], d[tm][tn][1], d[tm][tn][2], d[tm][tn][3],
                                     al[tm][0], al[tm][1], al[tm][2], al[tm][3],
                                     bh[tn][0], bh[tn][1]);
                        }
                }
            }
        }
        __syncthreads();
    }
    int tq = lid >> 2, tr = lid & 3;
    #pragma unroll
    for (int tm = 0; tm < 2; tm++) {
        #pragma unroll
        for (int half = 0; half < 2; half++) {
            int pt = wm * 32 + tm * 16 + tq + half * 8;
            size_t prow = (size_t)(b * 1024 + r0 * 32 + pt) * CO;
            #pragma unroll
            for (int tn = 0; tn < 4; tn++) {
                int col = n0 + wn * 32 + tn * 8 + 2 * tr;
                float v0 = d[tm][tn][2 * half] + bias[col];
                float v1 = d[tm][tn][2 * half + 1] + bias[col + 1];
                if (relu) { v0 = fmaxf(v0, 0.f); v1 = fmaxf(v1, 0.f); }
                float2 o; o.x = v0; o.y = v1;
                *(float2*)(out + prow + col) = o;
            }
        }
    }
}
static const int CONV_SMEM = 124800;

/* ---------------- prep kernels ---------------- */
__global__ __launch_bounds__(256) void transpose_split2(
    const float* __restrict__ xc, const float* __restrict__ xs,
    ushort_t* __restrict__ ohc, ushort_t* __restrict__ olc,
    ushort_t* __restrict__ ohs, ushort_t* __restrict__ ols) {
    __shared__ float tb[32][33];
    int z = blockIdx.z;
    const float* x = (z < 4) ? xc : xs;
    ushort_t* oh = (z < 4) ? ohc : ohs;
    ushort_t* ol = (z < 4) ? olc : ols;
    int b = z & 3;
    int i0 = blockIdx.x * 32, d0 = blockIdx.y * 32;
    int tx = threadIdx.x & 31, ty = threadIdx.x >> 5;
    const float* xb = x + (size_t)b * 512 * 1024;
    #pragma unroll
    for (int k = 0; k < 4; k++)
        tb[ty + k * 8][tx] = xb[(size_t)(d0 + ty + k * 8) * 1024 + i0 + tx];
    __syncthreads();
    #pragma unroll
    for (int k = 0; k < 4; k++) {
        int il = ty + k * 8;
        float v = tb[tx][il];
        ushort_t h, l;
        bsplit(v, h, l);
        size_t o = (size_t)b * 1024 * 512 + (size_t)(i0 + il) * 512 + d0 + tx;
        oh[o] = h; ol[o] = l;
    }
}

/* merged rownorm: blocks 0..511 content, 512..1023 style */
__global__ __launch_bounds__(256) void rownorm_t2(
    const ushort_t* __restrict__ xh0, const ushort_t* __restrict__ xl0,
    const ushort_t* __restrict__ xh1, const ushort_t* __restrict__ xl1,
    float* __restrict__ rn0, float* __restrict__ rn1) {
    int big = blockIdx.x >= 512;
    const ushort_t* xh = big ? xh1 : xh0;
    const ushort_t* xl = big ? xl1 : xl0;
    float* rn = big ? rn1 : rn0;
    int row = (blockIdx.x & 511) * 8 + (threadIdx.x >> 5);
    int lane = threadIdx.x & 31;
    const uint4* ph = (const uint4*)(xh + (size_t)row * 512);
    const uint4* pl = (const uint4*)(xl + (size_t)row * 512);
    float s = 0.f;
    #pragma unroll
    for (int k = 0; k < 2; k++) {
        uint4 h4 = ph[lane + k * 32], l4 = pl[lane + k * 32];
        const ushort_t* hh = (const ushort_t*)&h4;
        const ushort_t* ll = (const ushort_t*)&l4;
        #pragma unroll
        for (int j = 0; j < 8; j++) {
            float v = bf2f(hh[j]) + bf2f(ll[j]);
            s = fmaf(v, v, s);
        }
    }
    s = warpSum(s);
    if (lane == 0) rn[row] = rsqrtf(s);
}

/* mega-prep: convert_split(style) | cmstd(content) | wprep x3 | zero_v */
__global__ __launch_bounds__(256) void megaprep(
    const float* __restrict__ style, ushort_t* __restrict__ sfh,
    ushort_t* __restrict__ sfl,
    const float* __restrict__ content, float* __restrict__ cm,
    float* __restrict__ rs,
    const float* __restrict__ w1, ushort_t* __restrict__ w1h, ushort_t* __restrict__ w1l,
    const float* __restrict__ w2, ushort_t* __restrict__ w2h, ushort_t* __restrict__ w2l,
    const float* __restrict__ w3, ushort_t* __restrict__ w3h, ushort_t* __restrict__ w3l,
    float* __restrict__ v) {
    __shared__ float rsm[8], rqm[8];
    int blk = blockIdx.x, t = threadIdx.x;
    if (blk < 4096) {
        /* convert_split: style fp32 -> bf16 hi/lo pairs */
        int i = blk * 256 + t;
        float2 vv = ((const float2*)style)[i];
        ushort_t h0, l0, h1, l1;
        bsplit(vv.x, h0, l0);
        bsplit(vv.y, h1, l1);
        ((uint32_t*)sfh)[i] = ((uint32_t)h1 << 16) | h0;
        ((uint32_t*)sfl)[i] = ((uint32_t)l1 << 16) | l0;
    } else if (blk < 6144) {
        /* cmstd: one (b,c) channel per block, 256 threads */
        int bc = blk - 4096;
        const float* p = content + ((size_t)bc << 10);
        float s = 0.f, q = 0.f;
        #pragma unroll
        for (int l = 0; l < 4; l++) {
            float x = p[t + l * 256];
            s += x; q = fmaf(x, x, q);
        }
        s = warpSum(s); q = warpSum(q);
        if ((t & 31) == 0) { rsm[t >> 5] = s; rqm[t >> 5] = q; }
        __syncthreads();
        if (t == 0) {
            float S = 0.f, Q = 0.f;
            #pragma unroll
            for (int w = 0; w < 8; w++) { S += rsm[w]; Q += rqm[w]; }
            float mean = S * (1.f / 1024.f);
            float var = Q * (1.f / 1024.f) - mean * mean;
            cm[bc] = mean;
            rs[bc] = rsqrtf(fmaxf(var, 0.f) + 1e-5f);
        }
    } else if (blk < 7936) {
        /* wprep ranges */
        const float* w; ushort_t* wh; ushort_t* wl; int CO, CI, i;
        if (blk < 7168)      { w = w1; wh = w1h; wl = w1l; CO = 256; CI = 1024; i = (blk - 6144) * 256 + t; }
        else if (blk < 7424) { w = w2; wh = w2h; wl = w2l; CO = 256; CI = 256;  i = (blk - 7168) * 256 + t; }
        else                 { w = w3; wh = w3h; wl = w3l; CO = 512; CI = 256;  i = (blk - 7424) * 256 + t; }
        if (i < CO * CI) {
            int oc = i / CI, ci = i - oc * CI;
            #pragma unroll
            for (int k = 0; k < 9; k++) {
                float x = w[(size_t)i * 9 + k];
                ushort_t h, l;
                bsplit(x, h, l);
                size_t o = ((size_t)k * CO + oc) * CI + ci;
                wh[o] = h; wl[o] = l;
            }
        }
    } else {
        int i = (blk - 7936) * 256 + t;
        if (i < 4096) v[i] = 0.f;
    }
}

/* ---------------- Sinkhorn ---------------- */
__global__ __launch_bounds__(256) void u_update(const float* __restrict__ C,
                                                const float* __restrict__ v,
                                                float* __restrict__ u) {
    int b = blockIdx.y, i = blockIdx.x, t = threadIdx.x;
    const float4* C4 = (const float4*)(C + ((size_t)(b << 10) + i) * 1024);
    const float4* V4 = (const float4*)(v + (b << 10));
    float4 c = C4[t], vv = V4[t];
    float x0 = (vv.x - c.x) * INV_EPS;
    float x1 = (vv.y - c.y) * INV_EPS;
    float x2 = (vv.z - c.z) * INV_EPS;
    float x3 = (vv.w - c.w) * INV_EPS;
    float mx = fmaxf(fmaxf(x0, x1), fmaxf(x2, x3));
    __shared__ float redm[8], redq[8];
    mx = warpMax(mx);
    if ((t & 31) == 0) redm[t >> 5] = mx;
    __syncthreads();
    if (t < 32) {
        float z = (t < 8) ? redm[t] : -FLT_MAX;
        #pragma unroll
        for (int o = 4; o; o >>= 1) z = fmaxf(z, __shfl_xor_sync(0xffffffffu, z, o));
        if (t == 0) redm[0] = z;
    }
    __syncthreads();
    float bm = redm[0];
    float s = __expf(x0 - bm) + __expf(x1 - bm) + __expf(x2 - bm) + __expf(x3 - bm);
    s = warpSum(s);
    if ((t & 31) == 0) redq[t >> 5] = s;
    __syncthreads();
    if (t == 0) {
        float z = 0.f;
        #pragma unroll
        for (int q = 0; q < 8; q++) z += redq[q];
        u[(b << 10) + i] = EPS_S * (LOG_MU - (bm + __logf(z)));
    }
}

/* v phase: 4 independent online-LSE chains per thread (halved chain depth) */
__global__ __launch_bounds__(256) void v_update(const float* __restrict__ C,
                                                const float* __restrict__ u,
                                                float* __restrict__ v) {
    int b = blockIdx.y;
    int tx = threadIdx.x, ty = threadIdx.y;
    int j = blockIdx.x * 32 + tx;
    const float* p = C + (size_t)b * 1048576 + j;
    const float* ub = u + (b << 10);
    float m0 = -FLT_MAX, s0 = 0.f, m1 = -FLT_MAX, s1 = 0.f;
    float m2 = -FLT_MAX, s2 = 0.f, m3 = -FLT_MAX, s3 = 0.f;
    for (int i = ty; i < 1024; i += 32) {
        float xa = (ub[i] - p[(size_t)i << 10]) * INV_EPS;
        float xb = (ub[i + 8] - p[(size_t)(i + 8) << 10]) * INV_EPS;
        float xc = (ub[i + 16] - p[(size_t)(i + 16) << 10]) * INV_EPS;
        float xd = (ub[i + 24] - p[(size_t)(i + 24) << 10]) * INV_EPS;
        float n0 = fmaxf(m0, xa);
        s0 = s0 * __expf(m0 - n0) + __expf(xa - n0); m0 = n0;
        float n1 = fmaxf(m1, xb);
        s1 = s1 * __expf(m1 - n1) + __expf(xb - n1); m1 = n1;
        float n2 = fmaxf(m2, xc);
        s2 = s2 * __expf(m2 - n2) + __expf(xc - n2); m2 = n2;
        float n3 = fmaxf(m3, xd);
        s3 = s3 * __expf(m3 - n3) + __expf(xd - n3); m3 = n3;
    }
    float ma = fmaxf(fmaxf(m0, m1), fmaxf(m2, m3));
    float ss = s0 * __expf(m0 - ma) + s1 * __expf(m1 - ma)
             + s2 * __expf(m2 - ma) + s3 * __expf(m3 - ma);
    __shared__ float sm[8][32], sq[8][32];
    sm[ty][tx] = ma; sq[ty][tx] = ss;
    __syncthreads();
    if (ty == 0) {
        float M = ma, S = ss;
        #pragma unroll
        for (int q = 1; q < 8; q++) {
            float m2_ = sm[q][tx], s2_ = sq[q][tx];
            float nm = fmaxf(M, m2_);
            S = S * __expf(M - nm) + s2_ * __expf(m2_ - nm);
            M = nm;
        }
        v[(b << 10) + j] = EPS_S * (LOG_MU - (M + __logf(S)));
    }
}

__global__ __launch_bounds__(256) void pi_gen(
    const float* __restrict__ C, const float* __restrict__ u,
    const float* __restrict__ v, ushort_t* __restrict__ ph,
    ushort_t* __restrict__ pl) {
    int b = blockIdx.y, i = blockIdx.x, t = threadIdx.x;
    float ui = u[(b << 10) + i];
    const float2* Crow = (const float2*)(C + ((size_t)(b << 10) + i) * 1024);
    const float2* vrow = (const float2*)(v + (b << 10));
    uint32_t* phr = (uint32_t*)(ph + ((size_t)(b << 10) + i) * 1024);
    uint32_t* plr = (uint32_t*)(pl + ((size_t)(b << 10) + i) * 1024);
    #pragma unroll
    for (int l = 0; l < 2; l++) {
        int j2 = t + l * 256;
        float2 c2 = Crow[j2], v2 = vrow[j2];
        float p0 = __expf((ui + v2.x - c2.x) * INV_EPS) * 1024.f;
        float p1 = __expf((ui + v2.y - c2.y) * INV_EPS) * 1024.f;
        ushort_t h0, l0, h1, l1;
        bsplit(p0, h0, l0);
        bsplit(p1, h1, l1);
        phr[j2] = ((uint32_t)h1 << 16) | h0;
        plr[j2] = ((uint32_t)l1 << 16) | l0;
    }
}

/* ---------------- BatchNorm (NHWC, two-phase, deterministic) --------------- */
__global__ __launch_bounds__(256) void bnpart(const float* __restrict__ x,
                                              float* __restrict__ ps,
                                              float* __restrict__ pq) {
    int slab = blockIdx.x, t = threadIdx.x;
    float s = 0.f, q = 0.f;
    #pragma unroll
    for (int i = 0; i < 16; i++) {
        float v = x[(size_t)(slab * 16 + i) * 256 + t];
        s += v; q = fmaf(v, v, q);
    }
    ps[slab * 256 + t] = s;
    pq[slab * 256 + t] = q;
}
__global__ void bnfin(const float* __restrict__ ps, const float* __restrict__ pq,
                      const float* __restrict__ g, const float* __restrict__ be,
                      float* __restrict__ scale, float* __restrict__ shift) {
    int c = threadIdx.x;
    float s = 0.f, q = 0.f;
    for (int k = 0; k < 256; k++) { s += ps[k * 256 + c]; q += pq[k * 256 + c]; }
    float mean = s * (1.f / 4096.f);
    float var = q * (1.f / 4096.f) - mean * mean;
    float sc = g[c] * rsqrtf(fmaxf(var, 0.f) + BN_EPS);
    scale[c] = sc;
    shift[c] = be[c] - mean * sc;
}
__global__ __launch_bounds__(256) void bn_split(const float* __restrict__ x,
                                                const float* __restrict__ scale,
                                                const float* __restrict__ shift,
                                                ushort_t* __restrict__ oh,
                                                ushort_t* __restrict__ ol) {
    int i = blockIdx.x * 256 + threadIdx.x;
    int c = i & 255;
    float v = fmaf(x[i], scale[c], shift[c]);
    ushort_t h, l;
    bsplit(v, h, l);
    oh[i] = h; ol[i] = l;
}

/* ---- blend+transpose (blocks 0..2047) merged with dec bias init (2048+) -- */
__global__ __launch_bounds__(256) void blend_T(const float* __restrict__ tn,
                                               const float* __restrict__ an,
                                               const float* __restrict__ content,
                                               const float* __restrict__ cm,
                                               const float* __restrict__ rs,
                                               float* __restrict__ outc,
                                               const float* __restrict__ db,
                                               float* __restrict__ decout) {
    __shared__ float ts[32][33], as_[32][33];
    int bx = blockIdx.x;
    if (bx >= 2048) {
        int i = (bx - 2048) * 256 + threadIdx.x;
        if (i < 4 * 3 * 1024) decout[i] = db[(i >> 10) % 3];
        return;
    }
    int pix0 = (bx & 127) * 32, ch0 = (bx >> 7) * 32;
    int tx = threadIdx.x & 31, ty = threadIdx.x >> 5;
    #pragma unroll
    for (int k = 0; k < 4; k++) {
        int p = pix0 + ty + k * 8;
        ts[ty + k * 8][tx]  = tn[(size_t)p * 512 + ch0 + tx];
        as_[ty + k * 8][tx] = an[(size_t)p * 512 + ch0 + tx];
    }
    __syncthreads();
    int b = pix0 >> 10;
    int pl = pix0 & 1023;
    #pragma unroll
    for (int k = 0; k < 4; k++) {
        int cl = ty + k * 8;
        int gch = b * 512 + ch0 + cl;
        float m = cm[gch], r = rs[gch];
        float c = content[(size_t)gch * 1024 + pl + tx];
        float v = fmaf(as_[tx][cl], (c - m) * r, ts[tx][cl]);
        outc[(size_t)gch * 1024 + pl + tx] = v;
    }
}

/* ---------------- decoder conv: CI-split accumulation ---------------- */
__global__ __launch_bounds__(128) void conv3x3_dec(
    const float* __restrict__ src0, const float* __restrict__ W,
    float* __restrict__ out) {
    constexpr int OCT = 4, SROWS = 4, NT = 128, CIT = 8;
    __shared__ float s_in[CIT][SROWS + 2][34];
    __shared__ float s_w[CIT][9][OCT];
    const int CI = 512, CO = 3;
    int b = blockIdx.x, cg0 = blockIdx.y * 64, r0 = blockIdx.z * SROWS;
    int tid = threadIdx.x;
    int row = tid >> 5, col = tid & 31;
    float acc[OCT];
    #pragma unroll
    for (int o = 0; o < OCT; o++) acc[o] = 0.f;

    const int TOTIN = CIT * (SROWS + 2) * 34;
    const int TW = CIT * 9 * OCT;
    #pragma unroll 1
    for (int ci0 = cg0; ci0 < cg0 + 64; ci0 += CIT) {
        #pragma unroll 1
        for (int idx = tid; idx < TOTIN; idx += NT) {
            int ci = idx / ((SROWS + 2) * 34);
            int rem = idx - ci * ((SROWS + 2) * 34);
            int r = rem / 34, c = rem - r * 34;
            int gy = r0 + r - 1, gx = c - 1;
            float v = 0.f;
            if ((unsigned)gy < 32u && (unsigned)gx < 32u)
                v = src0[((size_t)(b * CI + ci0 + ci) << 10) + (gy << 5) + gx];
            (&s_in[0][0][0])[idx] = v;
        }
        #pragma unroll 1
        for (int idx = tid; idx < TW; idx += NT) {
            int ci = idx / (9 * OCT);
            int rem = idx - ci * (9 * OCT);
            int k = rem / OCT, oc = rem - k * OCT;
            float wv = 0.f;
            if (oc < CO)
                wv = W[((size_t)oc * CI + ci0 + ci) * 9 + k];
            (&s_w[0][0][0])[idx] = wv;
        }
        __syncthreads();
        #pragma unroll 1
        for (int ci = 0; ci < CIT; ci++) {
            #pragma unroll
            for (int ky = 0; ky < 3; ky++)
                #pragma unroll
                for (int kx = 0; kx < 3; kx++) {
                    float4 w4 = *(const float4*)&s_w[ci][ky * 3 + kx][0];
                    float v = s_in[ci][row + ky][col + kx];
                    acc[0] = fmaf(v, w4.x, acc[0]);
                    acc[1] = fmaf(v, w4.y, acc[1]);
                    acc[2] = fmaf(v, w4.z, acc[2]);
                    acc[3] = fmaf(v, w4.w, acc[3]);
                }
        }
        __syncthreads();
    }
    #pragma unroll
    for (int o = 0; o < 3; o++)
        atomicAdd(out + ((size_t)(b * 3 + o) << 10) + (r0 + row) * 32 + col, acc[o]);
}

/* ---------------- host orchestration ---------------- */
extern "C" void kernel_launch(void* const* d_in, const int* in_sizes, int n_in,
                              void* d_out, int out_size) {
    const float* content = (const float*)d_in[0];
    const float* style   = (const float*)d_in[1];
    const float* w1 = (const float*)d_in[2];  const float* b1 = (const float*)d_in[3];
    const float* g1 = (const float*)d_in[4];  const float* be1 = (const float*)d_in[5];
    const float* w2 = (const float*)d_in[6];  const float* b2 = (const float*)d_in[7];
    const float* g2 = (const float*)d_in[8];  const float* be2 = (const float*)d_in[9];
    const float* w3 = (const float*)d_in[10]; const float* b3 = (const float*)d_in[11];
    const float* dw = (const float*)d_in[12]; const float* db = (const float*)d_in[13];
    float* out = (float*)d_out;
    (void)in_sizes; (void)n_in; (void)out_size;

    float *pC, *pu, *pv, *prnx, *prny, *pt, *pa1, *pa2, *palpha, *pcm, *prs,
          *pscale, *pshift, *pps, *ppq;
    ushort_t *pcTh, *pcTl, *psTh, *psTl, *psfh, *psfl, *ppih, *ppil,
             *ptth, *pttl, *pb1h, *pb1l, *pb2h, *pb2l,
             *pw1h, *pw1l, *pw2h, *pw2l, *pw3h, *pw3l;
    cudaGetSymbolAddress((void**)&pC, g_C);
    cudaGetSymbolAddress((void**)&pu, g_u);
    cudaGetSymbolAddress((void**)&pv, g_v);
    cudaGetSymbolAddress((void**)&prnx, g_rnx);
    cudaGetSymbolAddress((void**)&prny, g_rny);
    cudaGetSymbolAddress((void**)&pt, g_t);
    cudaGetSymbolAddress((void**)&pa1, g_a1);
    cudaGetSymbolAddress((void**)&pa2, g_a2);
    cudaGetSymbolAddress((void**)&palpha, g_alpha);
    cudaGetSymbolAddress((void**)&pcm, g_cm);
    cudaGetSymbolAddress((void**)&prs, g_rs);
    cudaGetSymbolAddress((void**)&pscale, g_scale);
    cudaGetSymbolAddress((void**)&pshift, g_shift);
    cudaGetSymbolAddress((void**)&pps, g_ps);
    cudaGetSymbolAddress((void**)&ppq, g_pq);
    cudaGetSymbolAddress((void**)&pcTh, g_cTh);
    cudaGetSymbolAddress((void**)&pcTl, g_cTl);
    cudaGetSymbolAddress((void**)&psTh, g_sTh);
    cudaGetSymbolAddress((void**)&psTl, g_sTl);
    cudaGetSymbolAddress((void**)&psfh, g_sfh);
    cudaGetSymbolAddress((void**)&psfl, g_sfl);
    cudaGetSymbolAddress((void**)&ppih, g_pih);
    cudaGetSymbolAddress((void**)&ppil, g_pil);
    cudaGetSymbolAddress((void**)&ptth, g_tth);
    cudaGetSymbolAddress((void**)&pttl, g_ttl);
    cudaGetSymbolAddress((void**)&pb1h, g_b1h);
    cudaGetSymbolAddress((void**)&pb1l, g_b1l);
    cudaGetSymbolAddress((void**)&pb2h, g_b2h);
    cudaGetSymbolAddress((void**)&pb2l, g_b2l);
    cudaGetSymbolAddress((void**)&pw1h, g_w1h);
    cudaGetSymbolAddress((void**)&pw1l, g_w1l);
    cudaGetSymbolAddress((void**)&pw2h, g_w2h);
    cudaGetSymbolAddress((void**)&pw2l, g_w2l);
    cudaGetSymbolAddress((void**)&pw3h, g_w3h);
    cudaGetSymbolAddress((void**)&pw3l, g_w3l);

    cudaFuncSetAttribute(conv_hmma, cudaFuncAttributeMaxDynamicSharedMemorySize, CONV_SMEM);

    /* operand prep */
    transpose_split2<<<dim3(32, 16, 8), 256>>>(content, style, pcTh, pcTl, psTh, psTl);
    megaprep<<<7952, 256>>>(style, psfh, psfl, content, pcm, prs,
                            w1, pw1h, pw1l, w2, pw2h, pw2l, w3, pw3h, pw3l, pv);
    rownorm_t2<<<1024, 256>>>(pcTh, pcTl, psTh, psTl, prnx, prny);

    /* cosine-cost matrix */
    hmma_gemm<1><<<dim3(8, 16, 4), 256>>>(pcTh, pcTl, psTh, psTl,
        1024, 512, 1024, 1024, prnx, prny, pC, nullptr, nullptr);

    /* Sinkhorn, 20 iterations */
    for (int it = 0; it < 20; it++) {
        u_update<<<dim3(1024, 4), 256>>>(pC, pv, pu);
        v_update<<<dim3(32, 4), dim3(32, 8)>>>(pC, pu, pv);
    }

    /* pi, then t = pi @ style^T -> NHWC fp32 + bf16 split */
    pi_gen<<<dim3(1024, 4), 256>>>(pC, pu, pv, ppih, ppil);
    hmma_gemm<2><<<dim3(8, 8, 4), 256>>>(ppih, ppil, psfh, psfl,
        1024, 1024, 512, 512, nullptr, nullptr, pt, ptth, pttl);

    /* alpha predictor via tensor convs (NHWC) */
    conv_hmma<<<dim3(32, 4), 256, CONV_SMEM>>>(ptth, pttl, pcTh, pcTl, 512, 1024,
        pw1h, pw1l, 256, b1, 1, pa1);
    bnpart<<<256, 256>>>(pa1, pps, ppq);
    bnfin<<<1, 256>>>(pps, ppq, g1, be1, pscale, pshift);
    bn_split<<<4096, 256>>>(pa1, pscale, pshift, pb1h, pb1l);
    conv_hmma<<<dim3(32, 4), 256, CONV_SMEM>>>(pb1h, pb1l, pb1h, pb1l, 256, 256,
        pw2h, pw2l, 256, b2, 1, pa2);
    bnpart<<<256, 256>>>(pa2, pps, ppq);
    bnfin<<<1, 256>>>(pps, ppq, g2, be2, pscale, pshift);
    bn_split<<<4096, 256>>>(pa2, pscale, pshift, pb2h, pb2l);
    conv_hmma<<<dim3(32, 8), 256, CONV_SMEM>>>(pb2h, pb2l, pb2h, pb2l, 256, 256,
        pw3h, pw3l, 512, b3, 0, palpha);

    /* blend (transposed to NCHW) + decoder bias init, then decoder conv */
    blend_T<<<2096, 256>>>(pt, palpha, content, pcm, prs, pC, db, out);
    conv3x3_dec<<<dim3(4, 8, 8), 128>>>(pC, dw, out);
}

// round 14
// speedup vs baseline: 2.0484x; 1.0958x over previous
#include <cuda_runtime.h>
#include <cuda_bf16.h>
#include <cfloat>
#include <cstdint>

#define EPS_S   0.01f
#define INV_EPS 100.0f
#define LOG_MU  -6.93146200f   /* log(1/1024 + 1e-8) */
#define BN_EPS  1e-5f

typedef unsigned short ushort_t;

/* ---------------- scratch (device globals: no allocs allowed) -------------- */
__device__ float g_C[4 * 1024 * 1024];          /* cost matrix; later tblend NCHW */
__device__ float g_u[4096], g_v[4096];
__device__ float g_rnx[4096], g_rny[4096];
__device__ float g_t[4 * 1024 * 512];           /* t NHWC fp32 [pix][512] */
__device__ float g_a1[4 * 1024 * 256];
__device__ float g_a2[4 * 1024 * 256];
__device__ float g_alpha[4 * 1024 * 512];
__device__ float g_cm[2048], g_rs[2048];
__device__ float g_scale[512], g_shift[512];
__device__ float g_ps[256 * 256], g_pq[256 * 256];
/* bf16 split buffers */
__device__ ushort_t g_cTh[4 * 1024 * 512], g_cTl[4 * 1024 * 512];
__device__ ushort_t g_sTh[4 * 1024 * 512], g_sTl[4 * 1024 * 512];
__device__ ushort_t g_sfh[4 * 512 * 1024], g_sfl[4 * 512 * 1024];
__device__ ushort_t g_pih[4 * 1024 * 1024], g_pil[4 * 1024 * 1024];
__device__ ushort_t g_tth[4 * 1024 * 512], g_ttl[4 * 1024 * 512];
__device__ ushort_t g_b1h[4 * 1024 * 256], g_b1l[4 * 1024 * 256];
__device__ ushort_t g_b2h[4 * 1024 * 256], g_b2l[4 * 1024 * 256];
__device__ ushort_t g_w1h[9 * 256 * 1024], g_w1l[9 * 256 * 1024];
__device__ ushort_t g_w2h[9 * 256 * 256],  g_w2l[9 * 256 * 256];
__device__ ushort_t g_w3h[9 * 512 * 256],  g_w3l[9 * 512 * 256];

__device__ __forceinline__ uint32_t smem_u32(const void* p) {
    uint32_t a;
    asm("{ .reg .u64 t; cvta.to.shared.u64 t, %1; cvt.u32.u64 %0, t; }"
        : "=r"(a) : "l"(p));
    return a;
}
__device__ __forceinline__ void cp16(uint32_t s, const void* g) {
    asm volatile("cp.async.cg.shared.global [%0], [%1], 16;" :: "r"(s), "l"(g));
}
__device__ __forceinline__ void cp16p(uint32_t s, const void* g, bool ok) {
    int sz = ok ? 16 : 0;
    asm volatile("cp.async.cg.shared.global [%0], [%1], 16, %2;"
                 :: "r"(s), "l"(g), "r"(sz));
}
#define CP_COMMIT() asm volatile("cp.async.commit_group;" ::: "memory")
#define CP_WAIT0()  asm volatile("cp.async.wait_group 0;" ::: "memory")
#define CP_WAIT1()  asm volatile("cp.async.wait_group 1;" ::: "memory")

__device__ __forceinline__ void ldsm_x4(uint32_t& r0, uint32_t& r1,
                                        uint32_t& r2, uint32_t& r3, uint32_t a) {
    asm volatile("ldmatrix.sync.aligned.m8n8.x4.shared.b16 {%0,%1,%2,%3}, [%4];"
                 : "=r"(r0), "=r"(r1), "=r"(r2), "=r"(r3) : "r"(a));
}
__device__ __forceinline__ void mma_bf16(float& d0, float& d1, float& d2, float& d3,
                                         uint32_t a0, uint32_t a1, uint32_t a2, uint32_t a3,
                                         uint32_t b0, uint32_t b1) {
    asm volatile(
        "mma.sync.aligned.m16n8k16.row.col.f32.bf16.bf16.f32 "
        "{%0,%1,%2,%3}, {%4,%5,%6,%7}, {%8,%9}, {%0,%1,%2,%3};"
        : "+f"(d0), "+f"(d1), "+f"(d2), "+f"(d3)
        : "r"(a0), "r"(a1), "r"(a2), "r"(a3), "r"(b0), "r"(b1));
}
__device__ __forceinline__ void bsplit(float v, ushort_t& h, ushort_t& l) {
    __nv_bfloat16 hh = __float2bfloat16(v);
    float rem = v - __bfloat162float(hh);
    __nv_bfloat16 ll = __float2bfloat16(rem);
    h = __bfloat16_as_ushort(hh);
    l = __bfloat16_as_ushort(ll);
}
__device__ __forceinline__ float bf2f(ushort_t x) {
    return __bfloat162float(__ushort_as_bfloat16(x));
}
__device__ __forceinline__ float warpSum(float v) {
    #pragma unroll
    for (int o = 16; o; o >>= 1) v += __shfl_xor_sync(0xffffffffu, v, o);
    return v;
}
__device__ __forceinline__ float warpMax(float v) {
    #pragma unroll
    for (int o = 16; o; o >>= 1) v = fmaxf(v, __shfl_xor_sync(0xffffffffu, v, o));
    return v;
}

/* ============ HMMA bf16 split GEMM, cp.async double-buffered ==============
   dyn smem: Ah[2]@0, Al[2]@20480, Bh[2]@40960, Bl[2]@51200; total 61440 B. */
static const int GEMM_SMEM = 61440;
template <int EPI>
__global__ __launch_bounds__(256) void hmma_gemm(
    const ushort_t* __restrict__ Ahi, const ushort_t* __restrict__ Alo,
    const ushort_t* __restrict__ Bhi, const ushort_t* __restrict__ Blo,
    int Mtot, int Ktot, int Nrows, int OS,
    const float* __restrict__ rnx, const float* __restrict__ rny,
    float* __restrict__ out, ushort_t* __restrict__ o2h, ushort_t* __restrict__ o2l) {
    extern __shared__ unsigned char gs[];
    uint32_t sb = smem_u32(gs);
    int tid = threadIdx.x, wid = tid >> 5, lid = tid & 31;
    int b = blockIdx.z, m0 = blockIdx.x * 128, n0 = blockIdx.y * 64;
    int wm = wid & 3, wn = wid >> 2;
    size_t abase = (size_t)b * Mtot * Ktot;
    size_t bbase = (size_t)b * Nrows * Ktot;
    int arow = ((lid >> 3) & 1) * 8 + (lid & 7);
    int akof = (lid >> 4) * 8;
    int brow = (lid & 7) + ((lid >> 4) & 1) * 8;
    int bkof = ((lid >> 3) & 1) * 8;

    float d[2][4][4];
    #pragma unroll
    for (int i = 0; i < 2; i++)
        #pragma unroll
        for (int j = 0; j < 4; j++)
            #pragma unroll
            for (int q = 0; q < 4; q++) d[i][j][q] = 0.f;

#define FILLG(K0, BUF) do {                                                    \
    int k0_ = (K0);                                                            \
    uint32_t aB = sb + (BUF) * 10240;                                          \
    uint32_t alB = sb + 20480 + (BUF) * 10240;                                 \
    uint32_t bB = sb + 40960 + (BUF) * 5120;                                   \
    uint32_t blB = sb + 51200 + (BUF) * 5120;                                  \
    _Pragma("unroll")                                                          \
    for (int l = 0; l < 2; l++) {                                              \
        int idx = tid + l * 256;                                               \
        int r = idx >> 2, seg = idx & 3;                                       \
        cp16(aB + r * 80 + seg * 16,                                           \
             Ahi + abase + (size_t)(m0 + r) * Ktot + k0_ + seg * 8);           \
        cp16(alB + r * 80 + seg * 16,                                          \
             Alo + abase + (size_t)(m0 + r) * Ktot + k0_ + seg * 8);           \
    }                                                                          \
    {                                                                          \
        int r = tid >> 2, seg = tid & 3;                                       \
        cp16(bB + r * 80 + seg * 16,                                           \
             Bhi + bbase + (size_t)(n0 + r) * Ktot + k0_ + seg * 8);           \
        cp16(blB + r * 80 + seg * 16,                                          \
             Blo + bbase + (size_t)(n0 + r) * Ktot + k0_ + seg * 8);           \
    }                                                                          \
} while (0)

    int nch = Ktot >> 5;
    FILLG(0, 0);
    CP_COMMIT();
    for (int c = 0; c < nch; c++) {
        int buf = c & 1;
        if (c + 1 < nch) {
            FILLG((c + 1) << 5, (c + 1) & 1);
            CP_COMMIT();
            CP_WAIT1();
        } else {
            CP_WAIT0();
        }
        __syncthreads();
        uint32_t uAh = sb + buf * 10240;
        uint32_t uAl = sb + 20480 + buf * 10240;
        uint32_t uBh = sb + 40960 + buf * 5120;
        uint32_t uBl = sb + 51200 + buf * 5120;
        #pragma unroll
        for (int ks = 0; ks < 2; ks++) {
            int kb = ks * 16;
            uint32_t ah[2][4], al[2][4];
            #pragma unroll
            for (int tm = 0; tm < 2; tm++) {
                uint32_t off = (uint32_t)((wm * 32 + tm * 16 + arow) * 80 + (kb + akof) * 2);
                ldsm_x4(ah[tm][0], ah[tm][1], ah[tm][2], ah[tm][3], uAh + off);
                ldsm_x4(al[tm][0], al[tm][1], al[tm][2], al[tm][3], uAl + off);
            }
            uint32_t bh[4][2], bl[4][2];
            #pragma unroll
            for (int p = 0; p < 2; p++) {
                uint32_t off = (uint32_t)((wn * 32 + p * 16 + brow) * 80 + (kb + bkof) * 2);
                ldsm_x4(bh[2 * p][0], bh[2 * p][1], bh[2 * p + 1][0], bh[2 * p + 1][1], uBh + off);
                ldsm_x4(bl[2 * p][0], bl[2 * p][1], bl[2 * p + 1][0], bl[2 * p + 1][1], uBl + off);
            }
            #pragma unroll
            for (int tm = 0; tm < 2; tm++)
                #pragma unroll
                for (int tn = 0; tn < 4; tn++) {
                    mma_bf16(d[tm][tn][0], d[tm][tn][1], d[tm][tn][2], d[tm][tn][3],
                             ah[tm][0], ah[tm][1], ah[tm][2], ah[tm][3], bh[tn][0], bh[tn][1]);
                    mma_bf16(d[tm][tn][0], d[tm][tn][1], d[tm][tn][2], d[tm][tn][3],
                             ah[tm][0], ah[tm][1], ah[tm][2], ah[tm][3], bl[tn][0], bl[tn][1]);
                    mma_bf16(d[tm][tn][0], d[tm][tn][1], d[tm][tn][2], d[tm][tn][3],
                             al[tm][0], al[tm][1], al[tm][2], al[tm][3], bh[tn][0], bh[tn][1]);
                }
        }
        __syncthreads();
    }
#undef FILLG
    int tq = lid >> 2, tr = lid & 3;
    #pragma unroll
    for (int tm = 0; tm < 2; tm++) {
        #pragma unroll
        for (int half = 0; half < 2; half++) {
            int r = m0 + wm * 32 + tm * 16 + tq + half * 8;
            #pragma unroll
            for (int tn = 0; tn < 4; tn++) {
                int col = n0 + wn * 32 + tn * 8 + 2 * tr;
                float v0 = d[tm][tn][2 * half], v1 = d[tm][tn][2 * half + 1];
                size_t oidx = ((size_t)b * Mtot + r) * OS + col;
                if (EPI == 1) {
                    float rx = rnx[(b << 10) + r];
                    float2 o;
                    o.x = 1.f - rx * rny[(b << 10) + col] * v0;
                    o.y = 1.f - rx * rny[(b << 10) + col + 1] * v1;
                    *(float2*)(out + oidx) = o;
                } else {
                    float2 o; o.x = v0; o.y = v1;
                    *(float2*)(out + oidx) = o;
                    ushort_t h0, l0, h1, l1;
                    bsplit(v0, h0, l0);
                    bsplit(v1, h1, l1);
                    *(uint32_t*)(o2h + oidx) = ((uint32_t)h1 << 16) | h0;
                    *(uint32_t*)(o2l + oidx) = ((uint32_t)l1 << 16) | l0;
                }
            }
        }
    }
}

/* ============ shifted-GEMM tensor conv (NHWC, split bf16, cp.async fills) == */
__global__ __launch_bounds__(256) void conv_hmma(
    const ushort_t* __restrict__ Ah0, const ushort_t* __restrict__ Al0,
    const ushort_t* __restrict__ Ah1, const ushort_t* __restrict__ Al1,
    int csplit, int CI,
    const ushort_t* __restrict__ Wh, const ushort_t* __restrict__ Wl,
    int CO, const float* __restrict__ bias, int relu,
    float* __restrict__ out) {
    extern __shared__ unsigned char cs[];
    uint32_t uIh = smem_u32(cs);
    uint32_t uIl = uIh + 16320;
    uint32_t uBh = uIh + 32640;
    uint32_t uBl = uIh + 78720;
    int tid = threadIdx.x, wid = tid >> 5, lid = tid & 31;
    int mt = blockIdx.x;
    int b = mt >> 3, r0 = (mt & 7) * 4;
    int n0 = blockIdx.y * 64;
    int wm = wid & 3, wn = wid >> 2;
    int arow = ((lid >> 3) & 1) * 8 + (lid & 7);
    int akof = (lid >> 4) * 8;
    int brow = (lid & 7) + ((lid >> 4) & 1) * 8;
    int bkof = ((lid >> 3) & 1) * 8;
    uint32_t aoff[2];
    #pragma unroll
    for (int tm = 0; tm < 2; tm++) {
        int p = wm * 32 + tm * 16 + arow;
        aoff[tm] = (uint32_t)(((p >> 5) * 34 + (p & 31)) * 80 + akof * 2);
    }
    uint32_t boff = (uint32_t)((wn * 32 + brow) * 80 + bkof * 2);

    float d[2][4][4];
    #pragma unroll
    for (int i = 0; i < 2; i++)
        #pragma unroll
        for (int j = 0; j < 4; j++)
            #pragma unroll
            for (int q = 0; q < 4; q++) d[i][j][q] = 0.f;

    for (int ch = 0; ch < CI; ch += 32) {
        const ushort_t* srcH;
        const ushort_t* srcL;
        int cw, coff;
        if (ch < csplit) { srcH = Ah0; srcL = Al0; cw = csplit; coff = ch; }
        else             { srcH = Ah1; srcL = Al1; cw = CI - csplit; coff = ch - csplit; }
        /* input tile fill via cp.async (zfill for halo) */
        #pragma unroll
        for (int l = 0; l < 4; l++) {
            int idx = tid + l * 256;
            if (idx < 816) {
                int sp = idx >> 2, seg = idx & 3;
                int srow = sp / 34, scol = sp - srow * 34;
                int gy = r0 - 1 + srow, gx = scol - 1;
                bool ok = ((unsigned)gy < 32u) && ((unsigned)gx < 32u);
                size_t off = ok ? ((size_t)(b * 1024 + (gy << 5) + gx) * cw + coff + seg * 8)
                               : 0;
                cp16p(uIh + sp * 80 + seg * 16, srcH + off, ok);
                cp16p(uIl + sp * 80 + seg * 16, srcL + off, ok);
            }
        }
        /* all 9 weight taps via cp.async */
        #pragma unroll
        for (int l = 0; l < 9; l++) {
            int idx = tid + l * 256;
            int tap = idx >> 8, rem = idx & 255, oc = rem >> 2, seg = rem & 3;
            size_t woff = ((size_t)(tap * CO + n0 + oc)) * CI + ch + seg * 8;
            cp16(uBh + (tap * 64 + oc) * 80 + seg * 16, Wh + woff);
            cp16(uBl + (tap * 64 + oc) * 80 + seg * 16, Wl + woff);
        }
        CP_COMMIT();
        CP_WAIT0();
        __syncthreads();
        #pragma unroll 1
        for (int ky = 0; ky < 3; ky++) {
            #pragma unroll
            for (int kx = 0; kx < 3; kx++) {
                uint32_t shoff = (uint32_t)((ky * 34 + kx) * 80);
                uint32_t tapoff = (uint32_t)((ky * 3 + kx) * 5120);
                #pragma unroll
                for (int ks = 0; ks < 2; ks++) {
                    uint32_t kso = (uint32_t)(ks * 32);
                    uint32_t ah[2][4], al[2][4];
                    #pragma unroll
                    for (int tm = 0; tm < 2; tm++) {
                        ldsm_x4(ah[tm][0], ah[tm][1], ah[tm][2], ah[tm][3],
                                uIh + aoff[tm] + shoff + kso);
                        ldsm_x4(al[tm][0], al[tm][1], al[tm][2], al[tm][3],
                                uIl + aoff[tm] + shoff + kso);
                    }
                    uint32_t bh[4][2], bl[4][2];
                    #pragma unroll
                    for (int p = 0; p < 2; p++) {
                        uint32_t off = boff + tapoff + (uint32_t)(p * 1280) + kso;
                        ldsm_x4(bh[2 * p][0], bh[2 * p][1], bh[2 * p + 1][0], bh[2 * p + 1][1],
                                uBh + off);
                        ldsm_x4(bl[2 * p][0], bl[2 * p][1], bl[2 * p + 1][0], bl[2 * p + 1][1],
                                uBl + off);
                    }
                    #pragma unroll
                    for (int tm = 0; tm < 2; tm++)
                        #pragma unroll
                        for (int tn = 0; tn < 4; tn++) {
                            mma_bf16(d[tm][tn][0], d[tm][tn][1], d[tm][tn][2], d[tm][tn][3],
                                     ah[tm][0], ah[tm][1], ah[tm][2], ah[tm][3],
                                     bh[tn][0], bh[tn][1]);
                            mma_bf16(d[tm][tn][0], d[tm][tn][1], d[tm][tn][2], d[tm][tn][3],
                                     ah[tm][0], ah[tm][1], ah[tm][2], ah[tm][3],
                                     bl[tn][0], bl[tn][1]);
                            mma_bf16(d[tm][tn][0], d[tm][tn][1], d[tm][tn][2], d[tm][tn][3],
                                     al[tm][0], al[tm][1], al[tm][2], al[tm][3],
                                     bh[tn][0], bh[tn][1]);
                        }
                }
            }
        }
        __syncthreads();
    }
    int tq = lid >> 2, tr = lid & 3;
    #pragma unroll
    for (int tm = 0; tm < 2; tm++) {
        #pragma unroll
        for (int half = 0; half < 2; half++) {
            int pt = wm * 32 + tm * 16 + tq + half * 8;
            size_t prow = (size_t)(b * 1024 + r0 * 32 + pt) * CO;
            #pragma unroll
            for (int tn = 0; tn < 4; tn++) {
                int col = n0 + wn * 32 + tn * 8 + 2 * tr;
                float v0 = d[tm][tn][2 * half] + bias[col];
                float v1 = d[tm][tn][2 * half + 1] + bias[col + 1];
                if (relu) { v0 = fmaxf(v0, 0.f); v1 = fmaxf(v1, 0.f); }
                float2 o; o.x = v0; o.y = v1;
                *(float2*)(out + prow + col) = o;
            }
        }
    }
}
static const int CONV_SMEM = 124800;

/* ---------------- prep kernels ---------------- */
__global__ __launch_bounds__(256) void transpose_split2(
    const float* __restrict__ xc, const float* __restrict__ xs,
    ushort_t* __restrict__ ohc, ushort_t* __restrict__ olc,
    ushort_t* __restrict__ ohs, ushort_t* __restrict__ ols) {
    __shared__ float tb[32][33];
    int z = blockIdx.z;
    const float* x = (z < 4) ? xc : xs;
    ushort_t* oh = (z < 4) ? ohc : ohs;
    ushort_t* ol = (z < 4) ? olc : ols;
    int b = z & 3;
    int i0 = blockIdx.x * 32, d0 = blockIdx.y * 32;
    int tx = threadIdx.x & 31, ty = threadIdx.x >> 5;
    const float* xb = x + (size_t)b * 512 * 1024;
    #pragma unroll
    for (int k = 0; k < 4; k++)
        tb[ty + k * 8][tx] = xb[(size_t)(d0 + ty + k * 8) * 1024 + i0 + tx];
    __syncthreads();
    #pragma unroll
    for (int k = 0; k < 4; k++) {
        int il = ty + k * 8;
        float v = tb[tx][il];
        ushort_t h, l;
        bsplit(v, h, l);
        size_t o = (size_t)b * 1024 * 512 + (size_t)(i0 + il) * 512 + d0 + tx;
        oh[o] = h; ol[o] = l;
    }
}

__global__ __launch_bounds__(256) void rownorm_t2(
    const ushort_t* __restrict__ xh0, const ushort_t* __restrict__ xl0,
    const ushort_t* __restrict__ xh1, const ushort_t* __restrict__ xl1,
    float* __restrict__ rn0, float* __restrict__ rn1) {
    int big = blockIdx.x >= 512;
    const ushort_t* xh = big ? xh1 : xh0;
    const ushort_t* xl = big ? xl1 : xl0;
    float* rn = big ? rn1 : rn0;
    int row = (blockIdx.x & 511) * 8 + (threadIdx.x >> 5);
    int lane = threadIdx.x & 31;
    const uint4* ph = (const uint4*)(xh + (size_t)row * 512);
    const uint4* pl = (const uint4*)(xl + (size_t)row * 512);
    float s = 0.f;
    #pragma unroll
    for (int k = 0; k < 2; k++) {
        uint4 h4 = ph[lane + k * 32], l4 = pl[lane + k * 32];
        const ushort_t* hh = (const ushort_t*)&h4;
        const ushort_t* ll = (const ushort_t*)&l4;
        #pragma unroll
        for (int j = 0; j < 8; j++) {
            float v = bf2f(hh[j]) + bf2f(ll[j]);
            s = fmaf(v, v, s);
        }
    }
    s = warpSum(s);
    if (lane == 0) rn[row] = rsqrtf(s);
}

/* mega-prep: convert_split(style) | cmstd(content) | wprep x3 | zero_v */
__global__ __launch_bounds__(256) void megaprep(
    const float* __restrict__ style, ushort_t* __restrict__ sfh,
    ushort_t* __restrict__ sfl,
    const float* __restrict__ content, float* __restrict__ cm,
    float* __restrict__ rs,
    const float* __restrict__ w1, ushort_t* __restrict__ w1h, ushort_t* __restrict__ w1l,
    const float* __restrict__ w2, ushort_t* __restrict__ w2h, ushort_t* __restrict__ w2l,
    const float* __restrict__ w3, ushort_t* __restrict__ w3h, ushort_t* __restrict__ w3l,
    float* __restrict__ v) {
    __shared__ float rsm[8], rqm[8];
    int blk = blockIdx.x, t = threadIdx.x;
    if (blk < 4096) {
        int i = blk * 256 + t;
        float2 vv = ((const float2*)style)[i];
        ushort_t h0, l0, h1, l1;
        bsplit(vv.x, h0, l0);
        bsplit(vv.y, h1, l1);
        ((uint32_t*)sfh)[i] = ((uint32_t)h1 << 16) | h0;
        ((uint32_t*)sfl)[i] = ((uint32_t)l1 << 16) | l0;
    } else if (blk < 6144) {
        int bc = blk - 4096;
        const float* p = content + ((size_t)bc << 10);
        float s = 0.f, q = 0.f;
        #pragma unroll
        for (int l = 0; l < 4; l++) {
            float x = p[t + l * 256];
            s += x; q = fmaf(x, x, q);
        }
        s = warpSum(s); q = warpSum(q);
        if ((t & 31) == 0) { rsm[t >> 5] = s; rqm[t >> 5] = q; }
        __syncthreads();
        if (t == 0) {
            float S = 0.f, Q = 0.f;
            #pragma unroll
            for (int w = 0; w < 8; w++) { S += rsm[w]; Q += rqm[w]; }
            float mean = S * (1.f / 1024.f);
            float var = Q * (1.f / 1024.f) - mean * mean;
            cm[bc] = mean;
            rs[bc] = rsqrtf(fmaxf(var, 0.f) + 1e-5f);
        }
    } else if (blk < 7936) {
        const float* w; ushort_t* wh; ushort_t* wl; int CO, CI, i;
        if (blk < 7168)      { w = w1; wh = w1h; wl = w1l; CO = 256; CI = 1024; i = (blk - 6144) * 256 + t; }
        else if (blk < 7424) { w = w2; wh = w2h; wl = w2l; CO = 256; CI = 256;  i = (blk - 7168) * 256 + t; }
        else                 { w = w3; wh = w3h; wl = w3l; CO = 512; CI = 256;  i = (blk - 7424) * 256 + t; }
        if (i < CO * CI) {
            int oc = i / CI, ci = i - oc * CI;
            #pragma unroll
            for (int k = 0; k < 9; k++) {
                float x = w[(size_t)i * 9 + k];
                ushort_t h, l;
                bsplit(x, h, l);
                size_t o = ((size_t)k * CO + oc) * CI + ci;
                wh[o] = h; wl[o] = l;
            }
        }
    } else {
        int i = (blk - 7936) * 256 + t;
        if (i < 4096) v[i] = 0.f;
    }
}

/* ---------------- Sinkhorn ---------------- */
__global__ __launch_bounds__(256) void u_update(const float* __restrict__ C,
                                                const float* __restrict__ v,
                                                float* __restrict__ u) {
    int b = blockIdx.y, i = blockIdx.x, t = threadIdx.x;
    const float4* C4 = (const float4*)(C + ((size_t)(b << 10) + i) * 1024);
    const float4* V4 = (const float4*)(v + (b << 10));
    float4 c = C4[t], vv = V4[t];
    float x0 = (vv.x - c.x) * INV_EPS;
    float x1 = (vv.y - c.y) * INV_EPS;
    float x2 = (vv.z - c.z) * INV_EPS;
    float x3 = (vv.w - c.w) * INV_EPS;
    float mx = fmaxf(fmaxf(x0, x1), fmaxf(x2, x3));
    __shared__ float redm[8], redq[8];
    mx = warpMax(mx);
    if ((t & 31) == 0) redm[t >> 5] = mx;
    __syncthreads();
    if (t < 32) {
        float z = (t < 8) ? redm[t] : -FLT_MAX;
        #pragma unroll
        for (int o = 4; o; o >>= 1) z = fmaxf(z, __shfl_xor_sync(0xffffffffu, z, o));
        if (t == 0) redm[0] = z;
    }
    __syncthreads();
    float bm = redm[0];
    float s = __expf(x0 - bm) + __expf(x1 - bm) + __expf(x2 - bm) + __expf(x3 - bm);
    s = warpSum(s);
    if ((t & 31) == 0) redq[t >> 5] = s;
    __syncthreads();
    if (t == 0) {
        float z = 0.f;
        #pragma unroll
        for (int q = 0; q < 8; q++) z += redq[q];
        u[(b << 10) + i] = EPS_S * (LOG_MU - (bm + __logf(z)));
    }
}

__global__ __launch_bounds__(256) void v_update(const float* __restrict__ C,
                                                const float* __restrict__ u,
                                                float* __restrict__ v) {
    int b = blockIdx.y;
    int tx = threadIdx.x, ty = threadIdx.y;
    int j = blockIdx.x * 32 + tx;
    const float* p = C + (size_t)b * 1048576 + j;
    const float* ub = u + (b << 10);
    float m0 = -FLT_MAX, s0 = 0.f, m1 = -FLT_MAX, s1 = 0.f;
    float m2 = -FLT_MAX, s2 = 0.f, m3 = -FLT_MAX, s3 = 0.f;
    for (int i = ty; i < 1024; i += 32) {
        float xa = (ub[i] - p[(size_t)i << 10]) * INV_EPS;
        float xb = (ub[i + 8] - p[(size_t)(i + 8) << 10]) * INV_EPS;
        float xc = (ub[i + 16] - p[(size_t)(i + 16) << 10]) * INV_EPS;
        float xd = (ub[i + 24] - p[(size_t)(i + 24) << 10]) * INV_EPS;
        float n0 = fmaxf(m0, xa);
        s0 = s0 * __expf(m0 - n0) + __expf(xa - n0); m0 = n0;
        float n1 = fmaxf(m1, xb);
        s1 = s1 * __expf(m1 - n1) + __expf(xb - n1); m1 = n1;
        float n2 = fmaxf(m2, xc);
        s2 = s2 * __expf(m2 - n2) + __expf(xc - n2); m2 = n2;
        float n3 = fmaxf(m3, xd);
        s3 = s3 * __expf(m3 - n3) + __expf(xd - n3); m3 = n3;
    }
    float ma = fmaxf(fmaxf(m0, m1), fmaxf(m2, m3));
    float ss = s0 * __expf(m0 - ma) + s1 * __expf(m1 - ma)
             + s2 * __expf(m2 - ma) + s3 * __expf(m3 - ma);
    __shared__ float sm[8][32], sq[8][32];
    sm[ty][tx] = ma; sq[ty][tx] = ss;
    __syncthreads();
    if (ty == 0) {
        float M = ma, S = ss;
        #pragma unroll
        for (int q = 1; q < 8; q++) {
            float m2_ = sm[q][tx], s2_ = sq[q][tx];
            float nm = fmaxf(M, m2_);
            S = S * __expf(M - nm) + s2_ * __expf(m2_ - nm);
            M = nm;
        }
        v[(b << 10) + j] = EPS_S * (LOG_MU - (M + __logf(S)));
    }
}

__global__ __launch_bounds__(256) void pi_gen(
    const float* __restrict__ C, const float* __restrict__ u,
    const float* __restrict__ v, ushort_t* __restrict__ ph,
    ushort_t* __restrict__ pl) {
    int b = blockIdx.y, i = blockIdx.x, t = threadIdx.x;
    float ui = u[(b << 10) + i];
    const float2* Crow = (const float2*)(C + ((size_t)(b << 10) + i) * 1024);
    const float2* vrow = (const float2*)(v + (b << 10));
    uint32_t* phr = (uint32_t*)(ph + ((size_t)(b << 10) + i) * 1024);
    uint32_t* plr = (uint32_t*)(pl + ((size_t)(b << 10) + i) * 1024);
    #pragma unroll
    for (int l = 0; l < 2; l++) {
        int j2 = t + l * 256;
        float2 c2 = Crow[j2], v2 = vrow[j2];
        float p0 = __expf((ui + v2.x - c2.x) * INV_EPS) * 1024.f;
        float p1 = __expf((ui + v2.y - c2.y) * INV_EPS) * 1024.f;
        ushort_t h0, l0, h1, l1;
        bsplit(p0, h0, l0);
        bsplit(p1, h1, l1);
        phr[j2] = ((uint32_t)h1 << 16) | h0;
        plr[j2] = ((uint32_t)l1 << 16) | l0;
    }
}

/* ---------------- BatchNorm (NHWC, two-phase, deterministic) --------------- */
__global__ __launch_bounds__(256) void bnpart(const float* __restrict__ x,
                                              float* __restrict__ ps,
                                              float* __restrict__ pq) {
    int slab = blockIdx.x, t = threadIdx.x;
    float s = 0.f, q = 0.f;
    #pragma unroll
    for (int i = 0; i < 16; i++) {
        float v = x[(size_t)(slab * 16 + i) * 256 + t];
        s += v; q = fmaf(v, v, q);
    }
    ps[slab * 256 + t] = s;
    pq[slab * 256 + t] = q;
}
__global__ void bnfin(const float* __restrict__ ps, const float* __restrict__ pq,
                      const float* __restrict__ g, const float* __restrict__ be,
                      float* __restrict__ scale, float* __restrict__ shift) {
    int c = threadIdx.x;
    float s = 0.f, q = 0.f;
    for (int k = 0; k < 256; k++) { s += ps[k * 256 + c]; q += pq[k * 256 + c]; }
    float mean = s * (1.f / 4096.f);
    float var = q * (1.f / 4096.f) - mean * mean;
    float sc = g[c] * rsqrtf(fmaxf(var, 0.f) + BN_EPS);
    scale[c] = sc;
    shift[c] = be[c] - mean * sc;
}
__global__ __launch_bounds__(256) void bn_split(const float* __restrict__ x,
                                                const float* __restrict__ scale,
                                                const float* __restrict__ shift,
                                                ushort_t* __restrict__ oh,
                                                ushort_t* __restrict__ ol) {
    int i = blockIdx.x * 256 + threadIdx.x;
    int c = i & 255;
    float v = fmaf(x[i], scale[c], shift[c]);
    ushort_t h, l;
    bsplit(v, h, l);
    oh[i] = h; ol[i] = l;
}

/* ---- blend+transpose (blocks 0..2047) merged with dec bias init (2048+) -- */
__global__ __launch_bounds__(256) void blend_T(const float* __restrict__ tn,
                                               const float* __restrict__ an,
                                               const float* __restrict__ content,
                                               const float* __restrict__ cm,
                                               const float* __restrict__ rs,
                                               float* __restrict__ outc,
                                               const float* __restrict__ db,
                                               float* __restrict__ decout) {
    __shared__ float ts[32][33], as_[32][33];
    int bx = blockIdx.x;
    if (bx >= 2048) {
        int i = (bx - 2048) * 256 + threadIdx.x;
        if (i < 4 * 3 * 1024) decout[i] = db[(i >> 10) % 3];
        return;
    }
    int pix0 = (bx & 127) * 32, ch0 = (bx >> 7) * 32;
    int tx = threadIdx.x & 31, ty = threadIdx.x >> 5;
    #pragma unroll
    for (int k = 0; k < 4; k++) {
        int p = pix0 + ty + k * 8;
        ts[ty + k * 8][tx]  = tn[(size_t)p * 512 + ch0 + tx];
        as_[ty + k * 8][tx] = an[(size_t)p * 512 + ch0 + tx];
    }
    __syncthreads();
    int b = pix0 >> 10;
    int pl = pix0 & 1023;
    #pragma unroll
    for (int k = 0; k < 4; k++) {
        int cl = ty + k * 8;
        int gch = b * 512 + ch0 + cl;
        float m = cm[gch], r = rs[gch];
        float c = content[(size_t)gch * 1024 + pl + tx];
        float v = fmaf(as_[tx][cl], (c - m) * r, ts[tx][cl]);
        outc[(size_t)gch * 1024 + pl + tx] = v;
    }
}

/* ---------------- decoder conv: CI-split accumulation ---------------- */
__global__ __launch_bounds__(128) void conv3x3_dec(
    const float* __restrict__ src0, const float* __restrict__ W,
    float* __restrict__ out) {
    constexpr int OCT = 4, SROWS = 4, NT = 128, CIT = 8;
    __shared__ float s_in[CIT][SROWS + 2][34];
    __shared__ float s_w[CIT][9][OCT];
    const int CI = 512, CO = 3;
    int b = blockIdx.x, cg0 = blockIdx.y * 64, r0 = blockIdx.z * SROWS;
    int tid = threadIdx.x;
    int row = tid >> 5, col = tid & 31;
    float acc[OCT];
    #pragma unroll
    for (int o = 0; o < OCT; o++) acc[o] = 0.f;

    const int TOTIN = CIT * (SROWS + 2) * 34;
    const int TW = CIT * 9 * OCT;
    #pragma unroll 1
    for (int ci0 = cg0; ci0 < cg0 + 64; ci0 += CIT) {
        #pragma unroll 1
        for (int idx = tid; idx < TOTIN; idx += NT) {
            int ci = idx / ((SROWS + 2) * 34);
            int rem = idx - ci * ((SROWS + 2) * 34);
            int r = rem / 34, c = rem - r * 34;
            int gy = r0 + r - 1, gx = c - 1;
            float v = 0.f;
            if ((unsigned)gy < 32u && (unsigned)gx < 32u)
                v = src0[((size_t)(b * CI + ci0 + ci) << 10) + (gy << 5) + gx];
            (&s_in[0][0][0])[idx] = v;
        }
        #pragma unroll 1
        for (int idx = tid; idx < TW; idx += NT) {
            int ci = idx / (9 * OCT);
            int rem = idx - ci * (9 * OCT);
            int k = rem / OCT, oc = rem - k * OCT;
            float wv = 0.f;
            if (oc < CO)
                wv = W[((size_t)oc * CI + ci0 + ci) * 9 + k];
            (&s_w[0][0][0])[idx] = wv;
        }
        __syncthreads();
        #pragma unroll 1
        for (int ci = 0; ci < CIT; ci++) {
            #pragma unroll
            for (int ky = 0; ky < 3; ky++)
                #pragma unroll
                for (int kx = 0; kx < 3; kx++) {
                    float4 w4 = *(const float4*)&s_w[ci][ky * 3 + kx][0];
                    float v = s_in[ci][row + ky][col + kx];
                    acc[0] = fmaf(v, w4.x, acc[0]);
                    acc[1] = fmaf(v, w4.y, acc[1]);
                    acc[2] = fmaf(v, w4.z, acc[2]);
                    acc[3] = fmaf(v, w4.w, acc[3]);
                }
        }
        __syncthreads();
    }
    #pragma unroll
    for (int o = 0; o < 3; o++)
        atomicAdd(out + ((size_t)(b * 3 + o) << 10) + (r0 + row) * 32 + col, acc[o]);
}

/* ---------------- host orchestration ---------------- */
extern "C" void kernel_launch(void* const* d_in, const int* in_sizes, int n_in,
                              void* d_out, int out_size) {
    const float* content = (const float*)d_in[0];
    const float* style   = (const float*)d_in[1];
    const float* w1 = (const float*)d_in[2];  const float* b1 = (const float*)d_in[3];
    const float* g1 = (const float*)d_in[4];  const float* be1 = (const float*)d_in[5];
    const float* w2 = (const float*)d_in[6];  const float* b2 = (const float*)d_in[7];
    const float* g2 = (const float*)d_in[8];  const float* be2 = (const float*)d_in[9];
    const float* w3 = (const float*)d_in[10]; const float* b3 = (const float*)d_in[11];
    const float* dw = (const float*)d_in[12]; const float* db = (const float*)d_in[13];
    float* out = (float*)d_out;
    (void)in_sizes; (void)n_in; (void)out_size;

    float *pC, *pu, *pv, *prnx, *prny, *pt, *pa1, *pa2, *palpha, *pcm, *prs,
          *pscale, *pshift, *pps, *ppq;
    ushort_t *pcTh, *pcTl, *psTh, *psTl, *psfh, *psfl, *ppih, *ppil,
             *ptth, *pttl, *pb1h, *pb1l, *pb2h, *pb2l,
             *pw1h, *pw1l, *pw2h, *pw2l, *pw3h, *pw3l;
    cudaGetSymbolAddress((void**)&pC, g_C);
    cudaGetSymbolAddress((void**)&pu, g_u);
    cudaGetSymbolAddress((void**)&pv, g_v);
    cudaGetSymbolAddress((void**)&prnx, g_rnx);
    cudaGetSymbolAddress((void**)&prny, g_rny);
    cudaGetSymbolAddress((void**)&pt, g_t);
    cudaGetSymbolAddress((void**)&pa1, g_a1);
    cudaGetSymbolAddress((void**)&pa2, g_a2);
    cudaGetSymbolAddress((void**)&palpha, g_alpha);
    cudaGetSymbolAddress((void**)&pcm, g_cm);
    cudaGetSymbolAddress((void**)&prs, g_rs);
    cudaGetSymbolAddress((void**)&pscale, g_scale);
    cudaGetSymbolAddress((void**)&pshift, g_shift);
    cudaGetSymbolAddress((void**)&pps, g_ps);
    cudaGetSymbolAddress((void**)&ppq, g_pq);
    cudaGetSymbolAddress((void**)&pcTh, g_cTh);
    cudaGetSymbolAddress((void**)&pcTl, g_cTl);
    cudaGetSymbolAddress((void**)&psTh, g_sTh);
    cudaGetSymbolAddress((void**)&psTl, g_sTl);
    cudaGetSymbolAddress((void**)&psfh, g_sfh);
    cudaGetSymbolAddress((void**)&psfl, g_sfl);
    cudaGetSymbolAddress((void**)&ppih, g_pih);
    cudaGetSymbolAddress((void**)&ppil, g_pil);
    cudaGetSymbolAddress((void**)&ptth, g_tth);
    cudaGetSymbolAddress((void**)&pttl, g_ttl);
    cudaGetSymbolAddress((void**)&pb1h, g_b1h);
    cudaGetSymbolAddress((void**)&pb1l, g_b1l);
    cudaGetSymbolAddress((void**)&pb2h, g_b2h);
    cudaGetSymbolAddress((void**)&pb2l, g_b2l);
    cudaGetSymbolAddress((void**)&pw1h, g_w1h);
    cudaGetSymbolAddress((void**)&pw1l, g_w1l);
    cudaGetSymbolAddress((void**)&pw2h, g_w2h);
    cudaGetSymbolAddress((void**)&pw2l, g_w2l);
    cudaGetSymbolAddress((void**)&pw3h, g_w3h);
    cudaGetSymbolAddress((void**)&pw3l, g_w3l);

    cudaFuncSetAttribute(conv_hmma, cudaFuncAttributeMaxDynamicSharedMemorySize, CONV_SMEM);
    cudaFuncSetAttribute(hmma_gemm<1>, cudaFuncAttributeMaxDynamicSharedMemorySize, GEMM_SMEM);
    cudaFuncSetAttribute(hmma_gemm<2>, cudaFuncAttributeMaxDynamicSharedMemorySize, GEMM_SMEM);

    /* operand prep */
    transpose_split2<<<dim3(32, 16, 8), 256>>>(content, style, pcTh, pcTl, psTh, psTl);
    megaprep<<<7952, 256>>>(style, psfh, psfl, content, pcm, prs,
                            w1, pw1h, pw1l, w2, pw2h, pw2l, w3, pw3h, pw3l, pv);
    rownorm_t2<<<1024, 256>>>(pcTh, pcTl, psTh, psTl, prnx, prny);

    /* cosine-cost matrix */
    hmma_gemm<1><<<dim3(8, 16, 4), 256, GEMM_SMEM>>>(pcTh, pcTl, psTh, psTl,
        1024, 512, 1024, 1024, prnx, prny, pC, nullptr, nullptr);

    /* Sinkhorn, 20 iterations */
    for (int it = 0; it < 20; it++) {
        u_update<<<dim3(1024, 4), 256>>>(pC, pv, pu);
        v_update<<<dim3(32, 4), dim3(32, 8)>>>(pC, pu, pv);
    }

    /* pi, then t = pi @ style^T -> NHWC fp32 + bf16 split */
    pi_gen<<<dim3(1024, 4), 256>>>(pC, pu, pv, ppih, ppil);
    hmma_gemm<2><<<dim3(8, 8, 4), 256, GEMM_SMEM>>>(ppih, ppil, psfh, psfl,
        1024, 1024, 512, 512, nullptr, nullptr, pt, ptth, pttl);

    /* alpha predictor via tensor convs (NHWC) */
    conv_hmma<<<dim3(32, 4), 256, CONV_SMEM>>>(ptth, pttl, pcTh, pcTl, 512, 1024,
        pw1h, pw1l, 256, b1, 1, pa1);
    bnpart<<<256, 256>>>(pa1, pps, ppq);
    bnfin<<<1, 256>>>(pps, ppq, g1, be1, pscale, pshift);
    bn_split<<<4096, 256>>>(pa1, pscale, pshift, pb1h, pb1l);
    conv_hmma<<<dim3(32, 4), 256, CONV_SMEM>>>(pb1h, pb1l, pb1h, pb1l, 256, 256,
        pw2h, pw2l, 256, b2, 1, pa2);
    bnpart<<<256, 256>>>(pa2, pps, ppq);
    bnfin<<<1, 256>>>(pps, ppq, g2, be2, pscale, pshift);
    bn_split<<<4096, 256>>>(pa2, pscale, pshift, pb2h, pb2l);
    conv_hmma<<<dim3(32, 8), 256, CONV_SMEM>>>(pb2h, pb2l, pb2h, pb2l, 256, 256,
        pw3h, pw3l, 512, b3, 0, palpha);

    /* blend (transposed to NCHW) + decoder bias init, then decoder conv */
    blend_T<<<2096, 256>>>(pt, palpha, content, pcm, prs, pC, db, out);
    conv3x3_dec<<<dim3(4, 8, 8), 128>>>(pC, dw, out);
}

// round 15
// speedup vs baseline: 2.1350x; 1.0423x over previous
#include <cuda_runtime.h>
#include <cuda_bf16.h>
#include <cfloat>
#include <cstdint>

#define EPS_S   0.01f
#define INV_EPS 100.0f
#define LOG_MU  -6.93146200f   /* log(1/1024 + 1e-8) */
#define BN_EPS  1e-5f

typedef unsigned short ushort_t;

/* ---------------- scratch (device globals: no allocs allowed) -------------- */
__device__ float g_C[4 * 1024 * 1024];          /* cost matrix; later tblend NCHW */
__device__ float g_u[4096], g_v[4096];
__device__ float g_rnx[4096], g_rny[4096];
__device__ float g_t[4 * 1024 * 512];           /* t NHWC fp32 [pix][512] */
__device__ float g_a1[4 * 1024 * 256];
__device__ float g_a2[4 * 1024 * 256];
__device__ float g_alpha[4 * 1024 * 512];
__device__ float g_cm[2048], g_rs[2048];
__device__ float g_scale[512], g_shift[512];
__device__ float g_ps[64 * 256], g_pq[64 * 256];
/* bf16 split buffers */
__device__ ushort_t g_cTh[4 * 1024 * 512], g_cTl[4 * 1024 * 512];
__device__ ushort_t g_sTh[4 * 1024 * 512], g_sTl[4 * 1024 * 512];
__device__ ushort_t g_sfh[4 * 512 * 1024], g_sfl[4 * 512 * 1024];
__device__ ushort_t g_pih[4 * 1024 * 1024], g_pil[4 * 1024 * 1024];
__device__ ushort_t g_tth[4 * 1024 * 512], g_ttl[4 * 1024 * 512];
__device__ ushort_t g_b1h[4 * 1024 * 256], g_b1l[4 * 1024 * 256];
__device__ ushort_t g_b2h[4 * 1024 * 256], g_b2l[4 * 1024 * 256];
__device__ ushort_t g_w1h[9 * 256 * 1024], g_w1l[9 * 256 * 1024];
__device__ ushort_t g_w2h[9 * 256 * 256],  g_w2l[9 * 256 * 256];
__device__ ushort_t g_w3h[9 * 512 * 256],  g_w3l[9 * 512 * 256];

__device__ __forceinline__ uint32_t smem_u32(const void* p) {
    uint32_t a;
    asm("{ .reg .u64 t; cvta.to.shared.u64 t, %1; cvt.u32.u64 %0, t; }"
        : "=r"(a) : "l"(p));
    return a;
}
__device__ __forceinline__ void cp16(uint32_t s, const void* g) {
    asm volatile("cp.async.cg.shared.global [%0], [%1], 16;" :: "r"(s), "l"(g));
}
__device__ __forceinline__ void cp16p(uint32_t s, const void* g, bool ok) {
    int sz = ok ? 16 : 0;
    asm volatile("cp.async.cg.shared.global [%0], [%1], 16, %2;"
                 :: "r"(s), "l"(g), "r"(sz));
}
#define CP_COMMIT() asm volatile("cp.async.commit_group;" ::: "memory")
#define CP_WAIT0()  asm volatile("cp.async.wait_group 0;" ::: "memory")
#define CP_WAIT1()  asm volatile("cp.async.wait_group 1;" ::: "memory")

__device__ __forceinline__ void ldsm_x4(uint32_t& r0, uint32_t& r1,
                                        uint32_t& r2, uint32_t& r3, uint32_t a) {
    asm volatile("ldmatrix.sync.aligned.m8n8.x4.shared.b16 {%0,%1,%2,%3}, [%4];"
                 : "=r"(r0), "=r"(r1), "=r"(r2), "=r"(r3) : "r"(a));
}
__device__ __forceinline__ void mma_bf16(float& d0, float& d1, float& d2, float& d3,
                                         uint32_t a0, uint32_t a1, uint32_t a2, uint32_t a3,
                                         uint32_t b0, uint32_t b1) {
    asm volatile(
        "mma.sync.aligned.m16n8k16.row.col.f32.bf16.bf16.f32 "
        "{%0,%1,%2,%3}, {%4,%5,%6,%7}, {%8,%9}, {%0,%1,%2,%3};"
        : "+f"(d0), "+f"(d1), "+f"(d2), "+f"(d3)
        : "r"(a0), "r"(a1), "r"(a2), "r"(a3), "r"(b0), "r"(b1));
}
__device__ __forceinline__ void bsplit(float v, ushort_t& h, ushort_t& l) {
    __nv_bfloat16 hh = __float2bfloat16(v);
    float rem = v - __bfloat162float(hh);
    __nv_bfloat16 ll = __float2bfloat16(rem);
    h = __bfloat16_as_ushort(hh);
    l = __bfloat16_as_ushort(ll);
}
__device__ __forceinline__ float bf2f(ushort_t x) {
    return __bfloat162float(__ushort_as_bfloat16(x));
}
__device__ __forceinline__ float warpSum(float v) {
    #pragma unroll
    for (int o = 16; o; o >>= 1) v += __shfl_xor_sync(0xffffffffu, v, o);
    return v;
}
__device__ __forceinline__ float warpMax(float v) {
    #pragma unroll
    for (int o = 16; o; o >>= 1) v = fmaxf(v, __shfl_xor_sync(0xffffffffu, v, o));
    return v;
}

/* ============ HMMA bf16 split GEMM, 128x128 tile, cp.async dbuf ===========
   8 warps (4 wm x 2 wn), warp tile 32x64. dyn smem:
   Ah[2]@0, Al[2]@20480, Bh[2]@40960, Bl[2]@61440; total 81920 B.           */
static const int GEMM_SMEM = 81920;
template <int EPI>
__global__ __launch_bounds__(256) void hmma_gemm(
    const ushort_t* __restrict__ Ahi, const ushort_t* __restrict__ Alo,
    const ushort_t* __restrict__ Bhi, const ushort_t* __restrict__ Blo,
    int Mtot, int Ktot, int Nrows, int OS,
    const float* __restrict__ rnx, const float* __restrict__ rny,
    float* __restrict__ out, ushort_t* __restrict__ o2h, ushort_t* __restrict__ o2l) {
    extern __shared__ unsigned char gs[];
    uint32_t sb = smem_u32(gs);
    int tid = threadIdx.x, wid = tid >> 5, lid = tid & 31;
    int b = blockIdx.z, m0 = blockIdx.x * 128, n0 = blockIdx.y * 128;
    int wm = wid & 3, wn = wid >> 2;
    size_t abase = (size_t)b * Mtot * Ktot;
    size_t bbase = (size_t)b * Nrows * Ktot;
    int arow = ((lid >> 3) & 1) * 8 + (lid & 7);
    int akof = (lid >> 4) * 8;
    int brow = (lid & 7) + ((lid >> 4) & 1) * 8;
    int bkof = ((lid >> 3) & 1) * 8;

    float d[2][8][4];
    #pragma unroll
    for (int i = 0; i < 2; i++)
        #pragma unroll
        for (int j = 0; j < 8; j++)
            #pragma unroll
            for (int q = 0; q < 4; q++) d[i][j][q] = 0.f;

#define FILLG(K0, BUF) do {                                                    \
    int k0_ = (K0);                                                            \
    uint32_t aB = sb + (BUF) * 10240;                                          \
    uint32_t alB = sb + 20480 + (BUF) * 10240;                                 \
    uint32_t bB = sb + 40960 + (BUF) * 10240;                                  \
    uint32_t blB = sb + 61440 + (BUF) * 10240;                                 \
    _Pragma("unroll")                                                          \
    for (int l = 0; l < 2; l++) {                                              \
        int idx = tid + l * 256;                                               \
        int r = idx >> 2, seg = idx & 3;                                       \
        cp16(aB + r * 80 + seg * 16,                                           \
             Ahi + abase + (size_t)(m0 + r) * Ktot + k0_ + seg * 8);           \
        cp16(alB + r * 80 + seg * 16,                                          \
             Alo + abase + (size_t)(m0 + r) * Ktot + k0_ + seg * 8);           \
        cp16(bB + r * 80 + seg * 16,                                           \
             Bhi + bbase + (size_t)(n0 + r) * Ktot + k0_ + seg * 8);           \
        cp16(blB + r * 80 + seg * 16,                                          \
             Blo + bbase + (size_t)(n0 + r) * Ktot + k0_ + seg * 8);           \
    }                                                                          \
} while (0)

    int nch = Ktot >> 5;
    FILLG(0, 0);
    CP_COMMIT();
    for (int c = 0; c < nch; c++) {
        int buf = c & 1;
        if (c + 1 < nch) {
            FILLG((c + 1) << 5, (c + 1) & 1);
            CP_COMMIT();
            CP_WAIT1();
        } else {
            CP_WAIT0();
        }
        __syncthreads();
        uint32_t uAh = sb + buf * 10240;
        uint32_t uAl = sb + 20480 + buf * 10240;
        uint32_t uBh = sb + 40960 + buf * 10240;
        uint32_t uBl = sb + 61440 + buf * 10240;
        #pragma unroll
        for (int ks = 0; ks < 2; ks++) {
            int kb = ks * 16;
            uint32_t ah[2][4], al[2][4];
            #pragma unroll
            for (int tm = 0; tm < 2; tm++) {
                uint32_t off = (uint32_t)((wm * 32 + tm * 16 + arow) * 80 + (kb + akof) * 2);
                ldsm_x4(ah[tm][0], ah[tm][1], ah[tm][2], ah[tm][3], uAh + off);
                ldsm_x4(al[tm][0], al[tm][1], al[tm][2], al[tm][3], uAl + off);
            }
            uint32_t bh[8][2], bl[8][2];
            #pragma unroll
            for (int p = 0; p < 4; p++) {
                uint32_t off = (uint32_t)((wn * 64 + p * 16 + brow) * 80 + (kb + bkof) * 2);
                ldsm_x4(bh[2 * p][0], bh[2 * p][1], bh[2 * p + 1][0], bh[2 * p + 1][1], uBh + off);
                ldsm_x4(bl[2 * p][0], bl[2 * p][1], bl[2 * p + 1][0], bl[2 * p + 1][1], uBl + off);
            }
            #pragma unroll
            for (int tm = 0; tm < 2; tm++)
                #pragma unroll
                for (int tn = 0; tn < 8; tn++) {
                    mma_bf16(d[tm][tn][0], d[tm][tn][1], d[tm][tn][2], d[tm][tn][3],
                             ah[tm][0], ah[tm][1], ah[tm][2], ah[tm][3], bh[tn][0], bh[tn][1]);
                    mma_bf16(d[tm][tn][0], d[tm][tn][1], d[tm][tn][2], d[tm][tn][3],
                             ah[tm][0], ah[tm][1], ah[tm][2], ah[tm][3], bl[tn][0], bl[tn][1]);
                    mma_bf16(d[tm][tn][0], d[tm][tn][1], d[tm][tn][2], d[tm][tn][3],
                             al[tm][0], al[tm][1], al[tm][2], al[tm][3], bh[tn][0], bh[tn][1]);
                }
        }
        __syncthreads();
    }
#undef FILLG
    int tq = lid >> 2, tr = lid & 3;
    #pragma unroll
    for (int tm = 0; tm < 2; tm++) {
        #pragma unroll
        for (int half = 0; half < 2; half++) {
            int r = m0 + wm * 32 + tm * 16 + tq + half * 8;
            #pragma unroll
            for (int tn = 0; tn < 8; tn++) {
                int col = n0 + wn * 64 + tn * 8 + 2 * tr;
                float v0 = d[tm][tn][2 * half], v1 = d[tm][tn][2 * half + 1];
                size_t oidx = ((size_t)b * Mtot + r) * OS + col;
                if (EPI == 1) {
                    float rx = rnx[(b << 10) + r];
                    float2 o;
                    o.x = 1.f - rx * rny[(b << 10) + col] * v0;
                    o.y = 1.f - rx * rny[(b << 10) + col + 1] * v1;
                    *(float2*)(out + oidx) = o;
                } else {
                    float2 o; o.x = v0; o.y = v1;
                    *(float2*)(out + oidx) = o;
                    ushort_t h0, l0, h1, l1;
                    bsplit(v0, h0, l0);
                    bsplit(v1, h1, l1);
                    *(uint32_t*)(o2h + oidx) = ((uint32_t)h1 << 16) | h0;
                    *(uint32_t*)(o2l + oidx) = ((uint32_t)l1 << 16) | l0;
                }
            }
        }
    }
}

/* ============ shifted-GEMM tensor conv: weights double-buffered ===========
   smem: Ih@0(16320), Il@16320, Wh[2]@32640(46080 ea), Wl[2]@124800.        */
static const int CONV_SMEM = 216960;
__global__ __launch_bounds__(256) void conv_hmma(
    const ushort_t* __restrict__ Ah0, const ushort_t* __restrict__ Al0,
    const ushort_t* __restrict__ Ah1, const ushort_t* __restrict__ Al1,
    int csplit, int CI,
    const ushort_t* __restrict__ Wh, const ushort_t* __restrict__ Wl,
    int CO, const float* __restrict__ bias, int relu,
    float* __restrict__ out) {
    extern __shared__ unsigned char cs[];
    uint32_t sbc = smem_u32(cs);
    uint32_t uIh = sbc;
    uint32_t uIl = sbc + 16320;
    int tid = threadIdx.x, wid = tid >> 5, lid = tid & 31;
    int mt = blockIdx.x;
    int b = mt >> 3, r0 = (mt & 7) * 4;
    int n0 = blockIdx.y * 64;
    int wm = wid & 3, wn = wid >> 2;
    int arow = ((lid >> 3) & 1) * 8 + (lid & 7);
    int akof = (lid >> 4) * 8;
    int brow = (lid & 7) + ((lid >> 4) & 1) * 8;
    int bkof = ((lid >> 3) & 1) * 8;
    uint32_t aoff[2];
    #pragma unroll
    for (int tm = 0; tm < 2; tm++) {
        int p = wm * 32 + tm * 16 + arow;
        aoff[tm] = (uint32_t)(((p >> 5) * 34 + (p & 31)) * 80 + akof * 2);
    }
    uint32_t boff = (uint32_t)((wn * 32 + brow) * 80 + bkof * 2);

    float d[2][4][4];
    #pragma unroll
    for (int i = 0; i < 2; i++)
        #pragma unroll
        for (int j = 0; j < 4; j++)
            #pragma unroll
            for (int q = 0; q < 4; q++) d[i][j][q] = 0.f;

#define FILLW(CH, BUF) do {                                                    \
    int ch_ = (CH);                                                            \
    uint32_t wB = sbc + 32640 + (BUF) * 46080;                                 \
    uint32_t wlB = sbc + 124800 + (BUF) * 46080;                               \
    _Pragma("unroll")                                                          \
    for (int l = 0; l < 9; l++) {                                              \
        int idx = tid + l * 256;                                               \
        int tap = idx >> 8, rem = idx & 255, oc = rem >> 2, seg = rem & 3;     \
        size_t woff = ((size_t)(tap * CO + n0 + oc)) * CI + ch_ + seg * 8;     \
        cp16(wB + (tap * 64 + oc) * 80 + seg * 16, Wh + woff);                 \
        cp16(wlB + (tap * 64 + oc) * 80 + seg * 16, Wl + woff);                \
    }                                                                          \
} while (0)

#define FILLI(CH) do {                                                         \
    int ch_ = (CH);                                                            \
    const ushort_t* srcH;                                                      \
    const ushort_t* srcL;                                                      \
    int cw, coff;                                                              \
    if (ch_ < csplit) { srcH = Ah0; srcL = Al0; cw = csplit; coff = ch_; }     \
    else { srcH = Ah1; srcL = Al1; cw = CI - csplit; coff = ch_ - csplit; }    \
    _Pragma("unroll")                                                          \
    for (int l = 0; l < 4; l++) {                                              \
        int idx = tid + l * 256;                                               \
        if (idx < 816) {                                                       \
            int sp = idx >> 2, seg = idx & 3;                                  \
            int srow = sp / 34, scol = sp - srow * 34;                         \
            int gy = r0 - 1 + srow, gx = scol - 1;                             \
            bool ok = ((unsigned)gy < 32u) && ((unsigned)gx < 32u);            \
            size_t off = ok                                                    \
                ? ((size_t)(b * 1024 + (gy << 5) + gx) * cw + coff + seg * 8)  \
                : 0;                                                           \
            cp16p(uIh + sp * 80 + seg * 16, srcH + off, ok);                   \
            cp16p(uIl + sp * 80 + seg * 16, srcL + off, ok);                   \
        }                                                                      \
    }                                                                          \
} while (0)

    int nch = CI >> 5;
    FILLW(0, 0);
    FILLI(0);
    CP_COMMIT();
    CP_WAIT0();
    __syncthreads();
    for (int c = 0; c < nch; c++) {
        int buf = c & 1;
        if (c + 1 < nch) {
            FILLW((c + 1) << 5, (c + 1) & 1);   /* overlaps with compute */
            CP_COMMIT();
        }
        uint32_t uBh = sbc + 32640 + buf * 46080;
        uint32_t uBl = sbc + 124800 + buf * 46080;
        #pragma unroll 1
        for (int ky = 0; ky < 3; ky++) {
            #pragma unroll
            for (int kx = 0; kx < 3; kx++) {
                uint32_t shoff = (uint32_t)((ky * 34 + kx) * 80);
                uint32_t tapoff = (uint32_t)((ky * 3 + kx) * 5120);
                #pragma unroll
                for (int ks = 0; ks < 2; ks++) {
                    uint32_t kso = (uint32_t)(ks * 32);
                    uint32_t ah[2][4], al[2][4];
                    #pragma unroll
                    for (int tm = 0; tm < 2; tm++) {
                        ldsm_x4(ah[tm][0], ah[tm][1], ah[tm][2], ah[tm][3],
                                uIh + aoff[tm] + shoff + kso);
                        ldsm_x4(al[tm][0], al[tm][1], al[tm][2], al[tm][3],
                                uIl + aoff[tm] + shoff + kso);
                    }
                    uint32_t bh[4][2], bl[4][2];
                    #pragma unroll
                    for (int p = 0; p < 2; p++) {
                        uint32_t off = boff + tapoff + (uint32_t)(p * 1280) + kso;
                        ldsm_x4(bh[2 * p][0], bh[2 * p][1], bh[2 * p + 1][0], bh[2 * p + 1][1],
                                uBh + off);
                        ldsm_x4(bl[2 * p][0], bl[2 * p][1], bl[2 * p + 1][0], bl[2 * p + 1][1],
                                uBl + off);
                    }
                    #pragma unroll
                    for (int tm = 0; tm < 2; tm++)
                        #pragma unroll
                        for (int tn = 0; tn < 4; tn++) {
                            mma_bf16(d[tm][tn][0], d[tm][tn][1], d[tm][tn][2], d[tm][tn][3],
                                     ah[tm][0], ah[tm][1], ah[tm][2], ah[tm][3],
                                     bh[tn][0], bh[tn][1]);
                            mma_bf16(d[tm][tn][0], d[tm][tn][1], d[tm][tn][2], d[tm][tn][3],
                                     ah[tm][0], ah[tm][1], ah[tm][2], ah[tm][3],
                                     bl[tn][0], bl[tn][1]);
                            mma_bf16(d[tm][tn][0], d[tm][tn][1], d[tm][tn][2], d[tm][tn][3],
                                     al[tm][0], al[tm][1], al[tm][2], al[tm][3],
                                     bh[tn][0], bh[tn][1]);
                        }
                }
            }
        }
        __syncthreads();                         /* all warps done with input */
        if (c + 1 < nch) {
            FILLI((c + 1) << 5);                 /* refill single input buffer */
            CP_COMMIT();
            CP_WAIT0();                          /* weights + input both ready */
        }
        __syncthreads();
    }
#undef FILLW
#undef FILLI
    int tq = lid >> 2, tr = lid & 3;
    #pragma unroll
    for (int tm = 0; tm < 2; tm++) {
        #pragma unroll
        for (int half = 0; half < 2; half++) {
            int pt = wm * 32 + tm * 16 + tq + half * 8;
            size_t prow = (size_t)(b * 1024 + r0 * 32 + pt) * CO;
            #pragma unroll
            for (int tn = 0; tn < 4; tn++) {
                int col = n0 + wn * 32 + tn * 8 + 2 * tr;
                float v0 = d[tm][tn][2 * half] + bias[col];
                float v1 = d[tm][tn][2 * half + 1] + bias[col + 1];
                if (relu) { v0 = fmaxf(v0, 0.f); v1 = fmaxf(v1, 0.f); }
                float2 o; o.x = v0; o.y = v1;
                *(float2*)(out + prow + col) = o;
            }
        }
    }
}

/* ---------------- prep kernels ---------------- */
__global__ __launch_bounds__(256) void transpose_split2(
    const float* __restrict__ xc, const float* __restrict__ xs,
    ushort_t* __restrict__ ohc, ushort_t* __restrict__ olc,
    ushort_t* __restrict__ ohs, ushort_t* __restrict__ ols) {
    __shared__ float tb[32][33];
    int z = blockIdx.z;
    const float* x = (z < 4) ? xc : xs;
    ushort_t* oh = (z < 4) ? ohc : ohs;
    ushort_t* ol = (z < 4) ? olc : ols;
    int b = z & 3;
    int i0 = blockIdx.x * 32, d0 = blockIdx.y * 32;
    int tx = threadIdx.x & 31, ty = threadIdx.x >> 5;
    const float* xb = x + (size_t)b * 512 * 1024;
    #pragma unroll
    for (int k = 0; k < 4; k++)
        tb[ty + k * 8][tx] = xb[(size_t)(d0 + ty + k * 8) * 1024 + i0 + tx];
    __syncthreads();
    #pragma unroll
    for (int k = 0; k < 4; k++) {
        int il = ty + k * 8;
        float v = tb[tx][il];
        ushort_t h, l;
        bsplit(v, h, l);
        size_t o = (size_t)b * 1024 * 512 + (size_t)(i0 + il) * 512 + d0 + tx;
        oh[o] = h; ol[o] = l;
    }
}

__global__ __launch_bounds__(256) void rownorm_t2(
    const ushort_t* __restrict__ xh0, const ushort_t* __restrict__ xl0,
    const ushort_t* __restrict__ xh1, const ushort_t* __restrict__ xl1,
    float* __restrict__ rn0, float* __restrict__ rn1) {
    int big = blockIdx.x >= 512;
    const ushort_t* xh = big ? xh1 : xh0;
    const ushort_t* xl = big ? xl1 : xl0;
    float* rn = big ? rn1 : rn0;
    int row = (blockIdx.x & 511) * 8 + (threadIdx.x >> 5);
    int lane = threadIdx.x & 31;
    const uint4* ph = (const uint4*)(xh + (size_t)row * 512);
    const uint4* pl = (const uint4*)(xl + (size_t)row * 512);
    float s = 0.f;
    #pragma unroll
    for (int k = 0; k < 2; k++) {
        uint4 h4 = ph[lane + k * 32], l4 = pl[lane + k * 32];
        const ushort_t* hh = (const ushort_t*)&h4;
        const ushort_t* ll = (const ushort_t*)&l4;
        #pragma unroll
        for (int j = 0; j < 8; j++) {
            float v = bf2f(hh[j]) + bf2f(ll[j]);
            s = fmaf(v, v, s);
        }
    }
    s = warpSum(s);
    if (lane == 0) rn[row] = rsqrtf(s);
}

/* mega-prep: convert_split(style) | cmstd(content) | wprep x3 | zero_v */
__global__ __launch_bounds__(256) void megaprep(
    const float* __restrict__ style, ushort_t* __restrict__ sfh,
    ushort_t* __restrict__ sfl,
    const float* __restrict__ content, float* __restrict__ cm,
    float* __restrict__ rs,
    const float* __restrict__ w1, ushort_t* __restrict__ w1h, ushort_t* __restrict__ w1l,
    const float* __restrict__ w2, ushort_t* __restrict__ w2h, ushort_t* __restrict__ w2l,
    const float* __restrict__ w3, ushort_t* __restrict__ w3h, ushort_t* __restrict__ w3l,
    float* __restrict__ v) {
    __shared__ float rsm[8], rqm[8];
    int blk = blockIdx.x, t = threadIdx.x;
    if (blk < 4096) {
        int i = blk * 256 + t;
        float2 vv = ((const float2*)style)[i];
        ushort_t h0, l0, h1, l1;
        bsplit(vv.x, h0, l0);
        bsplit(vv.y, h1, l1);
        ((uint32_t*)sfh)[i] = ((uint32_t)h1 << 16) | h0;
        ((uint32_t*)sfl)[i] = ((uint32_t)l1 << 16) | l0;
    } else if (blk < 6144) {
        int bc = blk - 4096;
        const float* p = content + ((size_t)bc << 10);
        float s = 0.f, q = 0.f;
        #pragma unroll
        for (int l = 0; l < 4; l++) {
            float x = p[t + l * 256];
            s += x; q = fmaf(x, x, q);
        }
        s = warpSum(s); q = warpSum(q);
        if ((t & 31) == 0) { rsm[t >> 5] = s; rqm[t >> 5] = q; }
        __syncthreads();
        if (t == 0) {
            float S = 0.f, Q = 0.f;
            #pragma unroll
            for (int w = 0; w < 8; w++) { S += rsm[w]; Q += rqm[w]; }
            float mean = S * (1.f / 1024.f);
            float var = Q * (1.f / 1024.f) - mean * mean;
            cm[bc] = mean;
            rs[bc] = rsqrtf(fmaxf(var, 0.f) + 1e-5f);
        }
    } else if (blk < 7936) {
        const float* w; ushort_t* wh; ushort_t* wl; int CO, CI, i;
        if (blk < 7168)      { w = w1; wh = w1h; wl = w1l; CO = 256; CI = 1024; i = (blk - 6144) * 256 + t; }
        else if (blk < 7424) { w = w2; wh = w2h; wl = w2l; CO = 256; CI = 256;  i = (blk - 7168) * 256 + t; }
        else                 { w = w3; wh = w3h; wl = w3l; CO = 512; CI = 256;  i = (blk - 7424) * 256 + t; }
        if (i < CO * CI) {
            int oc = i / CI, ci = i - oc * CI;
            #pragma unroll
            for (int k = 0; k < 9; k++) {
                float x = w[(size_t)i * 9 + k];
                ushort_t h, l;
                bsplit(x, h, l);
                size_t o = ((size_t)k * CO + oc) * CI + ci;
                wh[o] = h; wl[o] = l;
            }
        }
    } else {
        int i = (blk - 7936) * 256 + t;
        if (i < 4096) v[i] = 0.f;
    }
}

/* ---------------- Sinkhorn ---------------- */
__global__ __launch_bounds__(256) void u_update(const float* __restrict__ C,
                                                const float* __restrict__ v,
                                                float* __restrict__ u) {
    int b = blockIdx.y, i = blockIdx.x, t = threadIdx.x;
    const float4* C4 = (const float4*)(C + ((size_t)(b << 10) + i) * 1024);
    const float4* V4 = (const float4*)(v + (b << 10));
    float4 c = C4[t], vv = V4[t];
    float x0 = (vv.x - c.x) * INV_EPS;
    float x1 = (vv.y - c.y) * INV_EPS;
    float x2 = (vv.z - c.z) * INV_EPS;
    float x3 = (vv.w - c.w) * INV_EPS;
    float mx = fmaxf(fmaxf(x0, x1), fmaxf(x2, x3));
    __shared__ float redm[8], redq[8];
    mx = warpMax(mx);
    if ((t & 31) == 0) redm[t >> 5] = mx;
    __syncthreads();
    if (t < 32) {
        float z = (t < 8) ? redm[t] : -FLT_MAX;
        #pragma unroll
        for (int o = 4; o; o >>= 1) z = fmaxf(z, __shfl_xor_sync(0xffffffffu, z, o));
        if (t == 0) redm[0] = z;
    }
    __syncthreads();
    float bm = redm[0];
    float s = __expf(x0 - bm) + __expf(x1 - bm) + __expf(x2 - bm) + __expf(x3 - bm);
    s = warpSum(s);
    if ((t & 31) == 0) redq[t >> 5] = s;
    __syncthreads();
    if (t == 0) {
        float z = 0.f;
        #pragma unroll
        for (int q = 0; q < 8; q++) z += redq[q];
        u[(b << 10) + i] = EPS_S * (LOG_MU - (bm + __logf(z)));
    }
}

__global__ __launch_bounds__(256) void v_update(const float* __restrict__ C,
                                                const float* __restrict__ u,
                                                float* __restrict__ v) {
    int b = blockIdx.y;
    int tx = threadIdx.x, ty = threadIdx.y;
    int j = blockIdx.x * 32 + tx;
    const float* p = C + (size_t)b * 1048576 + j;
    const float* ub = u + (b << 10);
    float m0 = -FLT_MAX, s0 = 0.f, m1 = -FLT_MAX, s1 = 0.f;
    float m2 = -FLT_MAX, s2 = 0.f, m3 = -FLT_MAX, s3 = 0.f;
    for (int i = ty; i < 1024; i += 32) {
        float xa = (ub[i] - p[(size_t)i << 10]) * INV_EPS;
        float xb = (ub[i + 8] - p[(size_t)(i + 8) << 10]) * INV_EPS;
        float xc = (ub[i + 16] - p[(size_t)(i + 16) << 10]) * INV_EPS;
        float xd = (ub[i + 24] - p[(size_t)(i + 24) << 10]) * INV_EPS;
        float n0 = fmaxf(m0, xa);
        s0 = s0 * __expf(m0 - n0) + __expf(xa - n0); m0 = n0;
        float n1 = fmaxf(m1, xb);
        s1 = s1 * __expf(m1 - n1) + __expf(xb - n1); m1 = n1;
        float n2 = fmaxf(m2, xc);
        s2 = s2 * __expf(m2 - n2) + __expf(xc - n2); m2 = n2;
        float n3 = fmaxf(m3, xd);
        s3 = s3 * __expf(m3 - n3) + __expf(xd - n3); m3 = n3;
    }
    float ma = fmaxf(fmaxf(m0, m1), fmaxf(m2, m3));
    float ss = s0 * __expf(m0 - ma) + s1 * __expf(m1 - ma)
             + s2 * __expf(m2 - ma) + s3 * __expf(m3 - ma);
    __shared__ float sm[8][32], sq[8][32];
    sm[ty][tx] = ma; sq[ty][tx] = ss;
    __syncthreads();
    if (ty == 0) {
        float M = ma, S = ss;
        #pragma unroll
        for (int q = 1; q < 8; q++) {
            float m2_ = sm[q][tx], s2_ = sq[q][tx];
            float nm = fmaxf(M, m2_);
            S = S * __expf(M - nm) + s2_ * __expf(m2_ - nm);
            M = nm;
        }
        v[(b << 10) + j] = EPS_S * (LOG_MU - (M + __logf(S)));
    }
}

__global__ __launch_bounds__(256) void pi_gen(
    const float* __restrict__ C, const float* __restrict__ u,
    const float* __restrict__ v, ushort_t* __restrict__ ph,
    ushort_t* __restrict__ pl) {
    int b = blockIdx.y, i = blockIdx.x, t = threadIdx.x;
    float ui = u[(b << 10) + i];
    const float2* Crow = (const float2*)(C + ((size_t)(b << 10) + i) * 1024);
    const float2* vrow = (const float2*)(v + (b << 10));
    uint32_t* phr = (uint32_t*)(ph + ((size_t)(b << 10) + i) * 1024);
    uint32_t* plr = (uint32_t*)(pl + ((size_t)(b << 10) + i) * 1024);
    #pragma unroll
    for (int l = 0; l < 2; l++) {
        int j2 = t + l * 256;
        float2 c2 = Crow[j2], v2 = vrow[j2];
        float p0 = __expf((ui + v2.x - c2.x) * INV_EPS) * 1024.f;
        float p1 = __expf((ui + v2.y - c2.y) * INV_EPS) * 1024.f;
        ushort_t h0, l0, h1, l1;
        bsplit(p0, h0, l0);
        bsplit(p1, h1, l1);
        phr[j2] = ((uint32_t)h1 << 16) | h0;
        plr[j2] = ((uint32_t)l1 << 16) | l0;
    }
}

/* ---------------- BatchNorm (NHWC, two-phase, deterministic) --------------- */
__global__ __launch_bounds__(256) void bnpart(const float* __restrict__ x,
                                              float* __restrict__ ps,
                                              float* __restrict__ pq) {
    int slab = blockIdx.x, t = threadIdx.x;   /* 64 slabs x 64 rows */
    float s = 0.f, q = 0.f;
    #pragma unroll
    for (int i = 0; i < 64; i++) {
        float v = x[(size_t)(slab * 64 + i) * 256 + t];
        s += v; q = fmaf(v, v, q);
    }
    ps[slab * 256 + t] = s;
    pq[slab * 256 + t] = q;
}
__global__ void bnfin(const float* __restrict__ ps, const float* __restrict__ pq,
                      const float* __restrict__ g, const float* __restrict__ be,
                      float* __restrict__ scale, float* __restrict__ shift) {
    int c = threadIdx.x;
    float s = 0.f, q = 0.f;
    for (int k = 0; k < 64; k++) { s += ps[k * 256 + c]; q += pq[k * 256 + c]; }
    float mean = s * (1.f / 4096.f);
    float var = q * (1.f / 4096.f) - mean * mean;
    float sc = g[c] * rsqrtf(fmaxf(var, 0.f) + BN_EPS);
    scale[c] = sc;
    shift[c] = be[c] - mean * sc;
}
__global__ __launch_bounds__(256) void bn_split(const float* __restrict__ x,
                                                const float* __restrict__ scale,
                                                const float* __restrict__ shift,
                                                ushort_t* __restrict__ oh,
                                                ushort_t* __restrict__ ol) {
    int i = blockIdx.x * 256 + threadIdx.x;
    int c = i & 255;
    float v = fmaf(x[i], scale[c], shift[c]);
    ushort_t h, l;
    bsplit(v, h, l);
    oh[i] = h; ol[i] = l;
}

/* ---- blend+transpose (blocks 0..2047) merged with dec bias init (2048+) -- */
__global__ __launch_bounds__(256) void blend_T(const float* __restrict__ tn,
                                               const float* __restrict__ an,
                                               const float* __restrict__ content,
                                               const float* __restrict__ cm,
                                               const float* __restrict__ rs,
                                               float* __restrict__ outc,
                                               const float* __restrict__ db,
                                               float* __restrict__ decout) {
    __shared__ float ts[32][33], as_[32][33];
    int bx = blockIdx.x;
    if (bx >= 2048) {
        int i = (bx - 2048) * 256 + threadIdx.x;
        if (i < 4 * 3 * 1024) decout[i] = db[(i >> 10) % 3];
        return;
    }
    int pix0 = (bx & 127) * 32, ch0 = (bx >> 7) * 32;
    int tx = threadIdx.x & 31, ty = threadIdx.x >> 5;
    #pragma unroll
    for (int k = 0; k < 4; k++) {
        int p = pix0 + ty + k * 8;
        ts[ty + k * 8][tx]  = tn[(size_t)p * 512 + ch0 + tx];
        as_[ty + k * 8][tx] = an[(size_t)p * 512 + ch0 + tx];
    }
    __syncthreads();
    int b = pix0 >> 10;
    int pl = pix0 & 1023;
    #pragma unroll
    for (int k = 0; k < 4; k++) {
        int cl = ty + k * 8;
        int gch = b * 512 + ch0 + cl;
        float m = cm[gch], r = rs[gch];
        float c = content[(size_t)gch * 1024 + pl + tx];
        float v = fmaf(as_[tx][cl], (c - m) * r, ts[tx][cl]);
        outc[(size_t)gch * 1024 + pl + tx] = v;
    }
}

/* ---------------- decoder conv: CI-split accumulation ---------------- */
__global__ __launch_bounds__(128) void conv3x3_dec(
    const float* __restrict__ src0, const float* __restrict__ W,
    float* __restrict__ out) {
    constexpr int OCT = 4, SROWS = 4, NT = 128, CIT = 8;
    __shared__ float s_in[CIT][SROWS + 2][34];
    __shared__ float s_w[CIT][9][OCT];
    const int CI = 512, CO = 3;
    int b = blockIdx.x, cg0 = blockIdx.y * 64, r0 = blockIdx.z * SROWS;
    int tid = threadIdx.x;
    int row = tid >> 5, col = tid & 31;
    float acc[OCT];
    #pragma unroll
    for (int o = 0; o < OCT; o++) acc[o] = 0.f;

    const int TOTIN = CIT * (SROWS + 2) * 34;
    const int TW = CIT * 9 * OCT;
    #pragma unroll 1
    for (int ci0 = cg0; ci0 < cg0 + 64; ci0 += CIT) {
        #pragma unroll 1
        for (int idx = tid; idx < TOTIN; idx += NT) {
            int ci = idx / ((SROWS + 2) * 34);
            int rem = idx - ci * ((SROWS + 2) * 34);
            int r = rem / 34, c = rem - r * 34;
            int gy = r0 + r - 1, gx = c - 1;
            float v = 0.f;
            if ((unsigned)gy < 32u && (unsigned)gx < 32u)
                v = src0[((size_t)(b * CI + ci0 + ci) << 10) + (gy << 5) + gx];
            (&s_in[0][0][0])[idx] = v;
        }
        #pragma unroll 1
        for (int idx = tid; idx < TW; idx += NT) {
            int ci = idx / (9 * OCT);
            int rem = idx - ci * (9 * OCT);
            int k = rem / OCT, oc = rem - k * OCT;
            float wv = 0.f;
            if (oc < CO)
                wv = W[((size_t)oc * CI + ci0 + ci) * 9 + k];
            (&s_w[0][0][0])[idx] = wv;
        }
        __syncthreads();
        #pragma unroll 1
        for (int ci = 0; ci < CIT; ci++) {
            #pragma unroll
            for (int ky = 0; ky < 3; ky++)
                #pragma unroll
                for (int kx = 0; kx < 3; kx++) {
                    float4 w4 = *(const float4*)&s_w[ci][ky * 3 + kx][0];
                    float v = s_in[ci][row + ky][col + kx];
                    acc[0] = fmaf(v, w4.x, acc[0]);
                    acc[1] = fmaf(v, w4.y, acc[1]);
                    acc[2] = fmaf(v, w4.z, acc[2]);
                    acc[3] = fmaf(v, w4.w, acc[3]);
                }
        }
        __syncthreads();
    }
    #pragma unroll
    for (int o = 0; o < 3; o++)
        atomicAdd(out + ((size_t)(b * 3 + o) << 10) + (r0 + row) * 32 + col, acc[o]);
}

/* ---------------- host orchestration ---------------- */
extern "C" void kernel_launch(void* const* d_in, const int* in_sizes, int n_in,
                              void* d_out, int out_size) {
    const float* content = (const float*)d_in[0];
    const float* style   = (const float*)d_in[1];
    const float* w1 = (const float*)d_in[2];  const float* b1 = (const float*)d_in[3];
    const float* g1 = (const float*)d_in[4];  const float* be1 = (const float*)d_in[5];
    const float* w2 = (const float*)d_in[6];  const float* b2 = (const float*)d_in[7];
    const float* g2 = (const float*)d_in[8];  const float* be2 = (const float*)d_in[9];
    const float* w3 = (const float*)d_in[10]; const float* b3 = (const float*)d_in[11];
    const float* dw = (const float*)d_in[12]; const float* db = (const float*)d_in[13];
    float* out = (float*)d_out;
    (void)in_sizes; (void)n_in; (void)out_size;

    float *pC, *pu, *pv, *prnx, *prny, *pt, *pa1, *pa2, *palpha, *pcm, *prs,
          *pscale, *pshift, *pps, *ppq;
    ushort_t *pcTh, *pcTl, *psTh, *psTl, *psfh, *psfl, *ppih, *ppil,
             *ptth, *pttl, *pb1h, *pb1l, *pb2h, *pb2l,
             *pw1h, *pw1l, *pw2h, *pw2l, *pw3h, *pw3l;
    cudaGetSymbolAddress((void**)&pC, g_C);
    cudaGetSymbolAddress((void**)&pu, g_u);
    cudaGetSymbolAddress((void**)&pv, g_v);
    cudaGetSymbolAddress((void**)&prnx, g_rnx);
    cudaGetSymbolAddress((void**)&prny, g_rny);
    cudaGetSymbolAddress((void**)&pt, g_t);
    cudaGetSymbolAddress((void**)&pa1, g_a1);
    cudaGetSymbolAddress((void**)&pa2, g_a2);
    cudaGetSymbolAddress((void**)&palpha, g_alpha);
    cudaGetSymbolAddress((void**)&pcm, g_cm);
    cudaGetSymbolAddress((void**)&prs, g_rs);
    cudaGetSymbolAddress((void**)&pscale, g_scale);
    cudaGetSymbolAddress((void**)&pshift, g_shift);
    cudaGetSymbolAddress((void**)&pps, g_ps);
    cudaGetSymbolAddress((void**)&ppq, g_pq);
    cudaGetSymbolAddress((void**)&pcTh, g_cTh);
    cudaGetSymbolAddress((void**)&pcTl, g_cTl);
    cudaGetSymbolAddress((void**)&psTh, g_sTh);
    cudaGetSymbolAddress((void**)&psTl, g_sTl);
    cudaGetSymbolAddress((void**)&psfh, g_sfh);
    cudaGetSymbolAddress((void**)&psfl, g_sfl);
    cudaGetSymbolAddress((void**)&ppih, g_pih);
    cudaGetSymbolAddress((void**)&ppil, g_pil);
    cudaGetSymbolAddress((void**)&ptth, g_tth);
    cudaGetSymbolAddress((void**)&pttl, g_ttl);
    cudaGetSymbolAddress((void**)&pb1h, g_b1h);
    cudaGetSymbolAddress((void**)&pb1l, g_b1l);
    cudaGetSymbolAddress((void**)&pb2h, g_b2h);
    cudaGetSymbolAddress((void**)&pb2l, g_b2l);
    cudaGetSymbolAddress((void**)&pw1h, g_w1h);
    cudaGetSymbolAddress((void**)&pw1l, g_w1l);
    cudaGetSymbolAddress((void**)&pw2h, g_w2h);
    cudaGetSymbolAddress((void**)&pw2l, g_w2l);
    cudaGetSymbolAddress((void**)&pw3h, g_w3h);
    cudaGetSymbolAddress((void**)&pw3l, g_w3l);

    cudaFuncSetAttribute(conv_hmma, cudaFuncAttributeMaxDynamicSharedMemorySize, CONV_SMEM);
    cudaFuncSetAttribute(hmma_gemm<1>, cudaFuncAttributeMaxDynamicSharedMemorySize, GEMM_SMEM);
    cudaFuncSetAttribute(hmma_gemm<2>, cudaFuncAttributeMaxDynamicSharedMemorySize, GEMM_SMEM);

    /* operand prep */
    transpose_split2<<<dim3(32, 16, 8), 256>>>(content, style, pcTh, pcTl, psTh, psTl);
    megaprep<<<7952, 256>>>(style, psfh, psfl, content, pcm, prs,
                            w1, pw1h, pw1l, w2, pw2h, pw2l, w3, pw3h, pw3l, pv);
    rownorm_t2<<<1024, 256>>>(pcTh, pcTl, psTh, psTl, prnx, prny);

    /* cosine-cost matrix (128x128 tiles) */
    hmma_gemm<1><<<dim3(8, 8, 4), 256, GEMM_SMEM>>>(pcTh, pcTl, psTh, psTl,
        1024, 512, 1024, 1024, prnx, prny, pC, nullptr, nullptr);

    /* Sinkhorn, 20 iterations */
    for (int it = 0; it < 20; it++) {
        u_update<<<dim3(1024, 4), 256>>>(pC, pv, pu);
        v_update<<<dim3(32, 4), dim3(32, 8)>>>(pC, pu, pv);
    }

    /* pi, then t = pi @ style^T -> NHWC fp32 + bf16 split */
    pi_gen<<<dim3(1024, 4), 256>>>(pC, pu, pv, ppih, ppil);
    hmma_gemm<2><<<dim3(8, 4, 4), 256, GEMM_SMEM>>>(ppih, ppil, psfh, psfl,
        1024, 1024, 512, 512, nullptr, nullptr, pt, ptth, pttl);

    /* alpha predictor via tensor convs (NHWC) */
    conv_hmma<<<dim3(32, 4), 256, CONV_SMEM>>>(ptth, pttl, pcTh, pcTl, 512, 1024,
        pw1h, pw1l, 256, b1, 1, pa1);
    bnpart<<<64, 256>>>(pa1, pps, ppq);
    bnfin<<<1, 256>>>(pps, ppq, g1, be1, pscale, pshift);
    bn_split<<<4096, 256>>>(pa1, pscale, pshift, pb1h, pb1l);
    conv_hmma<<<dim3(32, 4), 256, CONV_SMEM>>>(pb1h, pb1l, pb1h, pb1l, 256, 256,
        pw2h, pw2l, 256, b2, 1, pa2);
    bnpart<<<64, 256>>>(pa2, pps, ppq);
    bnfin<<<1, 256>>>(pps, ppq, g2, be2, pscale, pshift);
    bn_split<<<4096, 256>>>(pa2, pscale, pshift, pb2h, pb2l);
    conv_hmma<<<dim3(32, 8), 256, CONV_SMEM>>>(pb2h, pb2l, pb2h, pb2l, 256, 256,
        pw3h, pw3l, 512, b3, 0, palpha);

    /* blend (transposed to NCHW) + decoder bias init, then decoder conv */
    blend_T<<<2096, 256>>>(pt, palpha, content, pcm, prs, pC, db, out);
    conv3x3_dec<<<dim3(4, 8, 8), 128>>>(pC, dw, out);
}

// round 16
// speedup vs baseline: 2.4541x; 1.1494x over previous
#include <cuda_runtime.h>
#include <cuda_bf16.h>
#include <cfloat>
#include <cstdint>

#define EPS_S   0.01f
#define INV_EPS 100.0f
#define LOG_MU  -6.93146200f   /* log(1/1024 + 1e-8) */
#define BN_EPS  1e-5f

typedef unsigned short ushort_t;

/* ---------------- scratch (device globals: no allocs allowed) -------------- */
__device__ float g_C[4 * 1024 * 1024];          /* cost matrix; later tblend NCHW */
__device__ float g_CT[4 * 1024 * 1024];         /* transposed cost matrix */
__device__ float g_u[4096], g_v[4096];
__device__ float g_rnx[4096], g_rny[4096];
__device__ float g_t[4 * 1024 * 512];           /* t NHWC fp32 [pix][512] */
__device__ float g_a1[4 * 1024 * 256];
__device__ float g_a2[4 * 1024 * 256];
__device__ float g_alpha[4 * 1024 * 512];
__device__ float g_cm[2048], g_rs[2048];
__device__ float g_scale[512], g_shift[512];
__device__ float g_ps[64 * 256], g_pq[64 * 256];
/* bf16 split buffers */
__device__ ushort_t g_cTh[4 * 1024 * 512], g_cTl[4 * 1024 * 512];
__device__ ushort_t g_sTh[4 * 1024 * 512], g_sTl[4 * 1024 * 512];
__device__ ushort_t g_sfh[4 * 512 * 1024], g_sfl[4 * 512 * 1024];
__device__ ushort_t g_pih[4 * 1024 * 1024], g_pil[4 * 1024 * 1024];
__device__ ushort_t g_tth[4 * 1024 * 512], g_ttl[4 * 1024 * 512];
__device__ ushort_t g_b1h[4 * 1024 * 256], g_b1l[4 * 1024 * 256];
__device__ ushort_t g_b2h[4 * 1024 * 256], g_b2l[4 * 1024 * 256];
__device__ ushort_t g_w1h[9 * 256 * 1024], g_w1l[9 * 256 * 1024];
__device__ ushort_t g_w2h[9 * 256 * 256],  g_w2l[9 * 256 * 256];
__device__ ushort_t g_w3h[9 * 512 * 256],  g_w3l[9 * 512 * 256];

__device__ __forceinline__ uint32_t smem_u32(const void* p) {
    uint32_t a;
    asm("{ .reg .u64 t; cvta.to.shared.u64 t, %1; cvt.u32.u64 %0, t; }"
        : "=r"(a) : "l"(p));
    return a;
}
__device__ __forceinline__ void cp16(uint32_t s, const void* g) {
    asm volatile("cp.async.cg.shared.global [%0], [%1], 16;" :: "r"(s), "l"(g));
}
__device__ __forceinline__ void cp16p(uint32_t s, const void* g, bool ok) {
    int sz = ok ? 16 : 0;
    asm volatile("cp.async.cg.shared.global [%0], [%1], 16, %2;"
                 :: "r"(s), "l"(g), "r"(sz));
}
#define CP_COMMIT() asm volatile("cp.async.commit_group;" ::: "memory")
#define CP_WAIT0()  asm volatile("cp.async.wait_group 0;" ::: "memory")
#define CP_WAIT1()  asm volatile("cp.async.wait_group 1;" ::: "memory")

__device__ __forceinline__ void ldsm_x4(uint32_t& r0, uint32_t& r1,
                                        uint32_t& r2, uint32_t& r3, uint32_t a) {
    asm volatile("ldmatrix.sync.aligned.m8n8.x4.shared.b16 {%0,%1,%2,%3}, [%4];"
                 : "=r"(r0), "=r"(r1), "=r"(r2), "=r"(r3) : "r"(a));
}
__device__ __forceinline__ void mma_bf16(float& d0, float& d1, float& d2, float& d3,
                                         uint32_t a0, uint32_t a1, uint32_t a2, uint32_t a3,
                                         uint32_t b0, uint32_t b1) {
    asm volatile(
        "mma.sync.aligned.m16n8k16.row.col.f32.bf16.bf16.f32 "
        "{%0,%1,%2,%3}, {%4,%5,%6,%7}, {%8,%9}, {%0,%1,%2,%3};"
        : "+f"(d0), "+f"(d1), "+f"(d2), "+f"(d3)
        : "r"(a0), "r"(a1), "r"(a2), "r"(a3), "r"(b0), "r"(b1));
}
__device__ __forceinline__ void bsplit(float v, ushort_t& h, ushort_t& l) {
    __nv_bfloat16 hh = __float2bfloat16(v);
    float rem = v - __bfloat162float(hh);
    __nv_bfloat16 ll = __float2bfloat16(rem);
    h = __bfloat16_as_ushort(hh);
    l = __bfloat16_as_ushort(ll);
}
__device__ __forceinline__ float bf2f(ushort_t x) {
    return __bfloat162float(__ushort_as_bfloat16(x));
}
__device__ __forceinline__ float warpSum(float v) {
    #pragma unroll
    for (int o = 16; o; o >>= 1) v += __shfl_xor_sync(0xffffffffu, v, o);
    return v;
}
__device__ __forceinline__ float warpMax(float v) {
    #pragma unroll
    for (int o = 16; o; o >>= 1) v = fmaxf(v, __shfl_xor_sync(0xffffffffu, v, o));
    return v;
}

/* ============ HMMA bf16 split GEMM, 128x128 tile, cp.async dbuf =========== */
static const int GEMM_SMEM = 81920;
template <int EPI>
__global__ __launch_bounds__(256) void hmma_gemm(
    const ushort_t* __restrict__ Ahi, const ushort_t* __restrict__ Alo,
    const ushort_t* __restrict__ Bhi, const ushort_t* __restrict__ Blo,
    int Mtot, int Ktot, int Nrows, int OS,
    const float* __restrict__ rnx, const float* __restrict__ rny,
    float* __restrict__ out, ushort_t* __restrict__ o2h, ushort_t* __restrict__ o2l) {
    extern __shared__ unsigned char gs[];
    uint32_t sb = smem_u32(gs);
    int tid = threadIdx.x, wid = tid >> 5, lid = tid & 31;
    int b = blockIdx.z, m0 = blockIdx.x * 128, n0 = blockIdx.y * 128;
    int wm = wid & 3, wn = wid >> 2;
    size_t abase = (size_t)b * Mtot * Ktot;
    size_t bbase = (size_t)b * Nrows * Ktot;
    int arow = ((lid >> 3) & 1) * 8 + (lid & 7);
    int akof = (lid >> 4) * 8;
    int brow = (lid & 7) + ((lid >> 4) & 1) * 8;
    int bkof = ((lid >> 3) & 1) * 8;

    float d[2][8][4];
    #pragma unroll
    for (int i = 0; i < 2; i++)
        #pragma unroll
        for (int j = 0; j < 8; j++)
            #pragma unroll
            for (int q = 0; q < 4; q++) d[i][j][q] = 0.f;

#define FILLG(K0, BUF) do {                                                    \
    int k0_ = (K0);                                                            \
    uint32_t aB = sb + (BUF) * 10240;                                          \
    uint32_t alB = sb + 20480 + (BUF) * 10240;                                 \
    uint32_t bB = sb + 40960 + (BUF) * 10240;                                  \
    uint32_t blB = sb + 61440 + (BUF) * 10240;                                 \
    _Pragma("unroll")                                                          \
    for (int l = 0; l < 2; l++) {                                              \
        int idx = tid + l * 256;                                               \
        int r = idx >> 2, seg = idx & 3;                                       \
        cp16(aB + r * 80 + seg * 16,                                           \
             Ahi + abase + (size_t)(m0 + r) * Ktot + k0_ + seg * 8);           \
        cp16(alB + r * 80 + seg * 16,                                          \
             Alo + abase + (size_t)(m0 + r) * Ktot + k0_ + seg * 8);           \
        cp16(bB + r * 80 + seg * 16,                                           \
             Bhi + bbase + (size_t)(n0 + r) * Ktot + k0_ + seg * 8);           \
        cp16(blB + r * 80 + seg * 16,                                          \
             Blo + bbase + (size_t)(n0 + r) * Ktot + k0_ + seg * 8);           \
    }                                                                          \
} while (0)

    int nch = Ktot >> 5;
    FILLG(0, 0);
    CP_COMMIT();
    for (int c = 0; c < nch; c++) {
        int buf = c & 1;
        if (c + 1 < nch) {
            FILLG((c + 1) << 5, (c + 1) & 1);
            CP_COMMIT();
            CP_WAIT1();
        } else {
            CP_WAIT0();
        }
        __syncthreads();
        uint32_t uAh = sb + buf * 10240;
        uint32_t uAl = sb + 20480 + buf * 10240;
        uint32_t uBh = sb + 40960 + buf * 10240;
        uint32_t uBl = sb + 61440 + buf * 10240;
        #pragma unroll
        for (int ks = 0; ks < 2; ks++) {
            int kb = ks * 16;
            uint32_t ah[2][4], al[2][4];
            #pragma unroll
            for (int tm = 0; tm < 2; tm++) {
                uint32_t off = (uint32_t)((wm * 32 + tm * 16 + arow) * 80 + (kb + akof) * 2);
                ldsm_x4(ah[tm][0], ah[tm][1], ah[tm][2], ah[tm][3], uAh + off);
                ldsm_x4(al[tm][0], al[tm][1], al[tm][2], al[tm][3], uAl + off);
            }
            uint32_t bh[8][2], bl[8][2];
            #pragma unroll
            for (int p = 0; p < 4; p++) {
                uint32_t off = (uint32_t)((wn * 64 + p * 16 + brow) * 80 + (kb + bkof) * 2);
                ldsm_x4(bh[2 * p][0], bh[2 * p][1], bh[2 * p + 1][0], bh[2 * p + 1][1], uBh + off);
                ldsm_x4(bl[2 * p][0], bl[2 * p][1], bl[2 * p + 1][0], bl[2 * p + 1][1], uBl + off);
            }
            #pragma unroll
            for (int tm = 0; tm < 2; tm++)
                #pragma unroll
                for (int tn = 0; tn < 8; tn++) {
                    mma_bf16(d[tm][tn][0], d[tm][tn][1], d[tm][tn][2], d[tm][tn][3],
                             ah[tm][0], ah[tm][1], ah[tm][2], ah[tm][3], bh[tn][0], bh[tn][1]);
                    mma_bf16(d[tm][tn][0], d[tm][tn][1], d[tm][tn][2], d[tm][tn][3],
                             ah[tm][0], ah[tm][1], ah[tm][2], ah[tm][3], bl[tn][0], bl[tn][1]);
                    mma_bf16(d[tm][tn][0], d[tm][tn][1], d[tm][tn][2], d[tm][tn][3],
                             al[tm][0], al[tm][1], al[tm][2], al[tm][3], bh[tn][0], bh[tn][1]);
                }
        }
        __syncthreads();
    }
#undef FILLG
    int tq = lid >> 2, tr = lid & 3;
    #pragma unroll
    for (int tm = 0; tm < 2; tm++) {
        #pragma unroll
        for (int half = 0; half < 2; half++) {
            int r = m0 + wm * 32 + tm * 16 + tq + half * 8;
            #pragma unroll
            for (int tn = 0; tn < 8; tn++) {
                int col = n0 + wn * 64 + tn * 8 + 2 * tr;
                float v0 = d[tm][tn][2 * half], v1 = d[tm][tn][2 * half + 1];
                size_t oidx = ((size_t)b * Mtot + r) * OS + col;
                if (EPI == 1) {
                    float rx = rnx[(b << 10) + r];
                    float2 o;
                    o.x = 1.f - rx * rny[(b << 10) + col] * v0;
                    o.y = 1.f - rx * rny[(b << 10) + col + 1] * v1;
                    *(float2*)(out + oidx) = o;
                } else {
                    float2 o; o.x = v0; o.y = v1;
                    *(float2*)(out + oidx) = o;
                    ushort_t h0, l0, h1, l1;
                    bsplit(v0, h0, l0);
                    bsplit(v1, h1, l1);
                    *(uint32_t*)(o2h + oidx) = ((uint32_t)h1 << 16) | h0;
                    *(uint32_t*)(o2l + oidx) = ((uint32_t)l1 << 16) | l0;
                }
            }
        }
    }
}

/* ============ shifted-GEMM tensor conv: weights double-buffered =========== */
static const int CONV_SMEM = 216960;
__global__ __launch_bounds__(256) void conv_hmma(
    const ushort_t* __restrict__ Ah0, const ushort_t* __restrict__ Al0,
    const ushort_t* __restrict__ Ah1, const ushort_t* __restrict__ Al1,
    int csplit, int CI,
    const ushort_t* __restrict__ Wh, const ushort_t* __restrict__ Wl,
    int CO, const float* __restrict__ bias, int relu,
    float* __restrict__ out) {
    extern __shared__ unsigned char cs[];
    uint32_t sbc = smem_u32(cs);
    uint32_t uIh = sbc;
    uint32_t uIl = sbc + 16320;
    int tid = threadIdx.x, wid = tid >> 5, lid = tid & 31;
    int mt = blockIdx.x;
    int b = mt >> 3, r0 = (mt & 7) * 4;
    int n0 = blockIdx.y * 64;
    int wm = wid & 3, wn = wid >> 2;
    int arow = ((lid >> 3) & 1) * 8 + (lid & 7);
    int akof = (lid >> 4) * 8;
    int brow = (lid & 7) + ((lid >> 4) & 1) * 8;
    int bkof = ((lid >> 3) & 1) * 8;
    uint32_t aoff[2];
    #pragma unroll
    for (int tm = 0; tm < 2; tm++) {
        int p = wm * 32 + tm * 16 + arow;
        aoff[tm] = (uint32_t)(((p >> 5) * 34 + (p & 31)) * 80 + akof * 2);
    }
    uint32_t boff = (uint32_t)((wn * 32 + brow) * 80 + bkof * 2);

    float d[2][4][4];
    #pragma unroll
    for (int i = 0; i < 2; i++)
        #pragma unroll
        for (int j = 0; j < 4; j++)
            #pragma unroll
            for (int q = 0; q < 4; q++) d[i][j][q] = 0.f;

#define FILLW(CH, BUF) do {                                                    \
    int ch_ = (CH);                                                            \
    uint32_t wB = sbc + 32640 + (BUF) * 46080;                                 \
    uint32_t wlB = sbc + 124800 + (BUF) * 46080;                               \
    _Pragma("unroll")                                                          \
    for (int l = 0; l < 9; l++) {                                              \
        int idx = tid + l * 256;                                               \
        int tap = idx >> 8, rem = idx & 255, oc = rem >> 2, seg = rem & 3;     \
        size_t woff = ((size_t)(tap * CO + n0 + oc)) * CI + ch_ + seg * 8;     \
        cp16(wB + (tap * 64 + oc) * 80 + seg * 16, Wh + woff);                 \
        cp16(wlB + (tap * 64 + oc) * 80 + seg * 16, Wl + woff);                \
    }                                                                          \
} while (0)

#define FILLI(CH) do {                                                         \
    int ch_ = (CH);                                                            \
    const ushort_t* srcH;                                                      \
    const ushort_t* srcL;                                                      \
    int cw, coff;                                                              \
    if (ch_ < csplit) { srcH = Ah0; srcL = Al0; cw = csplit; coff = ch_; }     \
    else { srcH = Ah1; srcL = Al1; cw = CI - csplit; coff = ch_ - csplit; }    \
    _Pragma("unroll")                                                          \
    for (int l = 0; l < 4; l++) {                                              \
        int idx = tid + l * 256;                                               \
        if (idx < 816) {                                                       \
            int sp = idx >> 2, seg = idx & 3;                                  \
            int srow = sp / 34, scol = sp - srow * 34;                         \
            int gy = r0 - 1 + srow, gx = scol - 1;                             \
            bool ok = ((unsigned)gy < 32u) && ((unsigned)gx < 32u);            \
            size_t off = ok                                                    \
                ? ((size_t)(b * 1024 + (gy << 5) + gx) * cw + coff + seg * 8)  \
                : 0;                                                           \
            cp16p(uIh + sp * 80 + seg * 16, srcH + off, ok);                   \
            cp16p(uIl + sp * 80 + seg * 16, srcL + off, ok);                   \
        }                                                                      \
    }                                                                          \
} while (0)

    int nch = CI >> 5;
    FILLW(0, 0);
    FILLI(0);
    CP_COMMIT();
    CP_WAIT0();
    __syncthreads();
    for (int c = 0; c < nch; c++) {
        int buf = c & 1;
        if (c + 1 < nch) {
            FILLW((c + 1) << 5, (c + 1) & 1);
            CP_COMMIT();
        }
        uint32_t uBh = sbc + 32640 + buf * 46080;
        uint32_t uBl = sbc + 124800 + buf * 46080;
        #pragma unroll 1
        for (int ky = 0; ky < 3; ky++) {
            #pragma unroll
            for (int kx = 0; kx < 3; kx++) {
                uint32_t shoff = (uint32_t)((ky * 34 + kx) * 80);
                uint32_t tapoff = (uint32_t)((ky * 3 + kx) * 5120);
                #pragma unroll
                for (int ks = 0; ks < 2; ks++) {
                    uint32_t kso = (uint32_t)(ks * 32);
                    uint32_t ah[2][4], al[2][4];
                    #pragma unroll
                    for (int tm = 0; tm < 2; tm++) {
                        ldsm_x4(ah[tm][0], ah[tm][1], ah[tm][2], ah[tm][3],
                                uIh + aoff[tm] + shoff + kso);
                        ldsm_x4(al[tm][0], al[tm][1], al[tm][2], al[tm][3],
                                uIl + aoff[tm] + shoff + kso);
                    }
                    uint32_t bh[4][2], bl[4][2];
                    #pragma unroll
                    for (int p = 0; p < 2; p++) {
                        uint32_t off = boff + tapoff + (uint32_t)(p * 1280) + kso;
                        ldsm_x4(bh[2 * p][0], bh[2 * p][1], bh[2 * p + 1][0], bh[2 * p + 1][1],
                                uBh + off);
                        ldsm_x4(bl[2 * p][0], bl[2 * p][1], bl[2 * p + 1][0], bl[2 * p + 1][1],
                                uBl + off);
                    }
                    #pragma unroll
                    for (int tm = 0; tm < 2; tm++)
                        #pragma unroll
                        for (int tn = 0; tn < 4; tn++) {
                            mma_bf16(d[tm][tn][0], d[tm][tn][1], d[tm][tn][2], d[tm][tn][3],
                                     ah[tm][0], ah[tm][1], ah[tm][2], ah[tm][3],
                                     bh[tn][0], bh[tn][1]);
                            mma_bf16(d[tm][tn][0], d[tm][tn][1], d[tm][tn][2], d[tm][tn][3],
                                     ah[tm][0], ah[tm][1], ah[tm][2], ah[tm][3],
                                     bl[tn][0], bl[tn][1]);
                            mma_bf16(d[tm][tn][0], d[tm][tn][1], d[tm][tn][2], d[tm][tn][3],
                                     al[tm][0], al[tm][1], al[tm][2], al[tm][3],
                                     bh[tn][0], bh[tn][1]);
                        }
                }
            }
        }
        __syncthreads();
        if (c + 1 < nch) {
            FILLI((c + 1) << 5);
            CP_COMMIT();
            CP_WAIT0();
        }
        __syncthreads();
    }
#undef FILLW
#undef FILLI
    int tq = lid >> 2, tr = lid & 3;
    #pragma unroll
    for (int tm = 0; tm < 2; tm++) {
        #pragma unroll
        for (int half = 0; half < 2; half++) {
            int pt = wm * 32 + tm * 16 + tq + half * 8;
            size_t prow = (size_t)(b * 1024 + r0 * 32 + pt) * CO;
            #pragma unroll
            for (int tn = 0; tn < 4; tn++) {
                int col = n0 + wn * 32 + tn * 8 + 2 * tr;
                float v0 = d[tm][tn][2 * half] + bias[col];
                float v1 = d[tm][tn][2 * half + 1] + bias[col + 1];
                if (relu) { v0 = fmaxf(v0, 0.f); v1 = fmaxf(v1, 0.f); }
                float2 o; o.x = v0; o.y = v1;
                *(float2*)(out + prow + col) = o;
            }
        }
    }
}

/* ---------------- prep kernels ---------------- */
__global__ __launch_bounds__(256) void transpose_split2(
    const float* __restrict__ xc, const float* __restrict__ xs,
    ushort_t* __restrict__ ohc, ushort_t* __restrict__ olc,
    ushort_t* __restrict__ ohs, ushort_t* __restrict__ ols) {
    __shared__ float tb[32][33];
    int z = blockIdx.z;
    const float* x = (z < 4) ? xc : xs;
    ushort_t* oh = (z < 4) ? ohc : ohs;
    ushort_t* ol = (z < 4) ? olc : ols;
    int b = z & 3;
    int i0 = blockIdx.x * 32, d0 = blockIdx.y * 32;
    int tx = threadIdx.x & 31, ty = threadIdx.x >> 5;
    const float* xb = x + (size_t)b * 512 * 1024;
    #pragma unroll
    for (int k = 0; k < 4; k++)
        tb[ty + k * 8][tx] = xb[(size_t)(d0 + ty + k * 8) * 1024 + i0 + tx];
    __syncthreads();
    #pragma unroll
    for (int k = 0; k < 4; k++) {
        int il = ty + k * 8;
        float v = tb[tx][il];
        ushort_t h, l;
        bsplit(v, h, l);
        size_t o = (size_t)b * 1024 * 512 + (size_t)(i0 + il) * 512 + d0 + tx;
        oh[o] = h; ol[o] = l;
    }
}

/* C -> C^T, tiled (fp32), per batch */
__global__ __launch_bounds__(256) void transC(const float* __restrict__ C,
                                              float* __restrict__ CT) {
    __shared__ float tb[32][33];
    int b = blockIdx.z;
    int i0 = blockIdx.x * 32, j0 = blockIdx.y * 32;
    int tx = threadIdx.x & 31, ty = threadIdx.x >> 5;
    const float* Cb = C + (size_t)b * 1048576;
    float* Tb = CT + (size_t)b * 1048576;
    #pragma unroll
    for (int k = 0; k < 4; k++)
        tb[ty + k * 8][tx] = Cb[(size_t)(i0 + ty + k * 8) * 1024 + j0 + tx];
    __syncthreads();
    #pragma unroll
    for (int k = 0; k < 4; k++)
        Tb[(size_t)(j0 + ty + k * 8) * 1024 + i0 + tx] = tb[tx][ty + k * 8];
}

__global__ __launch_bounds__(256) void rownorm_t2(
    const ushort_t* __restrict__ xh0, const ushort_t* __restrict__ xl0,
    const ushort_t* __restrict__ xh1, const ushort_t* __restrict__ xl1,
    float* __restrict__ rn0, float* __restrict__ rn1) {
    int big = blockIdx.x >= 512;
    const ushort_t* xh = big ? xh1 : xh0;
    const ushort_t* xl = big ? xl1 : xl0;
    float* rn = big ? rn1 : rn0;
    int row = (blockIdx.x & 511) * 8 + (threadIdx.x >> 5);
    int lane = threadIdx.x & 31;
    const uint4* ph = (const uint4*)(xh + (size_t)row * 512);
    const uint4* pl = (const uint4*)(xl + (size_t)row * 512);
    float s = 0.f;
    #pragma unroll
    for (int k = 0; k < 2; k++) {
        uint4 h4 = ph[lane + k * 32], l4 = pl[lane + k * 32];
        const ushort_t* hh = (const ushort_t*)&h4;
        const ushort_t* ll = (const ushort_t*)&l4;
        #pragma unroll
        for (int j = 0; j < 8; j++) {
            float v = bf2f(hh[j]) + bf2f(ll[j]);
            s = fmaf(v, v, s);
        }
    }
    s = warpSum(s);
    if (lane == 0) rn[row] = rsqrtf(s);
}

/* mega-prep: convert_split(style) | cmstd(content) | wprep x3 | zero_v */
__global__ __launch_bounds__(256) void megaprep(
    const float* __restrict__ style, ushort_t* __restrict__ sfh,
    ushort_t* __restrict__ sfl,
    const float* __restrict__ content, float* __restrict__ cm,
    float* __restrict__ rs,
    const float* __restrict__ w1, ushort_t* __restrict__ w1h, ushort_t* __restrict__ w1l,
    const float* __restrict__ w2, ushort_t* __restrict__ w2h, ushort_t* __restrict__ w2l,
    const float* __restrict__ w3, ushort_t* __restrict__ w3h, ushort_t* __restrict__ w3l,
    float* __restrict__ v) {
    __shared__ float rsm[8], rqm[8];
    int blk = blockIdx.x, t = threadIdx.x;
    if (blk < 4096) {
        int i = blk * 256 + t;
        float2 vv = ((const float2*)style)[i];
        ushort_t h0, l0, h1, l1;
        bsplit(vv.x, h0, l0);
        bsplit(vv.y, h1, l1);
        ((uint32_t*)sfh)[i] = ((uint32_t)h1 << 16) | h0;
        ((uint32_t*)sfl)[i] = ((uint32_t)l1 << 16) | l0;
    } else if (blk < 6144) {
        int bc = blk - 4096;
        const float* p = content + ((size_t)bc << 10);
        float s = 0.f, q = 0.f;
        #pragma unroll
        for (int l = 0; l < 4; l++) {
            float x = p[t + l * 256];
            s += x; q = fmaf(x, x, q);
        }
        s = warpSum(s); q = warpSum(q);
        if ((t & 31) == 0) { rsm[t >> 5] = s; rqm[t >> 5] = q; }
        __syncthreads();
        if (t == 0) {
            float S = 0.f, Q = 0.f;
            #pragma unroll
            for (int w = 0; w < 8; w++) { S += rsm[w]; Q += rqm[w]; }
            float mean = S * (1.f / 1024.f);
            float var = Q * (1.f / 1024.f) - mean * mean;
            cm[bc] = mean;
            rs[bc] = rsqrtf(fmaxf(var, 0.f) + 1e-5f);
        }
    } else if (blk < 7936) {
        const float* w; ushort_t* wh; ushort_t* wl; int CO, CI, i;
        if (blk < 7168)      { w = w1; wh = w1h; wl = w1l; CO = 256; CI = 1024; i = (blk - 6144) * 256 + t; }
        else if (blk < 7424) { w = w2; wh = w2h; wl = w2l; CO = 256; CI = 256;  i = (blk - 7168) * 256 + t; }
        else                 { w = w3; wh = w3h; wl = w3l; CO = 512; CI = 256;  i = (blk - 7424) * 256 + t; }
        if (i < CO * CI) {
            int oc = i / CI, ci = i - oc * CI;
            #pragma unroll
            for (int k = 0; k < 9; k++) {
                float x = w[(size_t)i * 9 + k];
                ushort_t h, l;
                bsplit(x, h, l);
                size_t o = ((size_t)k * CO + oc) * CI + ci;
                wh[o] = h; wl[o] = l;
            }
        }
    } else {
        int i = (blk - 7936) * 256 + t;
        if (i < 4096) v[i] = 0.f;
    }
}

/* ---------------- Sinkhorn: one row-LSE kernel used for BOTH passes --------
   out[r] = EPS*(LOG_MU - LSE_c((vec[c] - M[r][c])*INV_EPS)), M row-major.  */
__global__ __launch_bounds__(256) void lse_update(const float* __restrict__ M,
                                                  const float* __restrict__ vec,
                                                  float* __restrict__ out) {
    int b = blockIdx.y, i = blockIdx.x, t = threadIdx.x;
    const float4* C4 = (const float4*)(M + ((size_t)(b << 10) + i) * 1024);
    const float4* V4 = (const float4*)(vec + (b << 10));
    float4 c = C4[t], vv = V4[t];
    float x0 = (vv.x - c.x) * INV_EPS;
    float x1 = (vv.y - c.y) * INV_EPS;
    float x2 = (vv.z - c.z) * INV_EPS;
    float x3 = (vv.w - c.w) * INV_EPS;
    float mx = fmaxf(fmaxf(x0, x1), fmaxf(x2, x3));
    __shared__ float redm[8], redq[8];
    mx = warpMax(mx);
    if ((t & 31) == 0) redm[t >> 5] = mx;
    __syncthreads();
    if (t < 32) {
        float z = (t < 8) ? redm[t] : -FLT_MAX;
        #pragma unroll
        for (int o = 4; o; o >>= 1) z = fmaxf(z, __shfl_xor_sync(0xffffffffu, z, o));
        if (t == 0) redm[0] = z;
    }
    __syncthreads();
    float bm = redm[0];
    float s = __expf(x0 - bm) + __expf(x1 - bm) + __expf(x2 - bm) + __expf(x3 - bm);
    s = warpSum(s);
    if ((t & 31) == 0) redq[t >> 5] = s;
    __syncthreads();
    if (t == 0) {
        float z = 0.f;
        #pragma unroll
        for (int q = 0; q < 8; q++) z += redq[q];
        out[(b << 10) + i] = EPS_S * (LOG_MU - (bm + __logf(z)));
    }
}

__global__ __launch_bounds__(256) void pi_gen(
    const float* __restrict__ C, const float* __restrict__ u,
    const float* __restrict__ v, ushort_t* __restrict__ ph,
    ushort_t* __restrict__ pl) {
    int b = blockIdx.y, i = blockIdx.x, t = threadIdx.x;
    float ui = u[(b << 10) + i];
    const float2* Crow = (const float2*)(C + ((size_t)(b << 10) + i) * 1024);
    const float2* vrow = (const float2*)(v + (b << 10));
    uint32_t* phr = (uint32_t*)(ph + ((size_t)(b << 10) + i) * 1024);
    uint32_t* plr = (uint32_t*)(pl + ((size_t)(b << 10) + i) * 1024);
    #pragma unroll
    for (int l = 0; l < 2; l++) {
        int j2 = t + l * 256;
        float2 c2 = Crow[j2], v2 = vrow[j2];
        float p0 = __expf((ui + v2.x - c2.x) * INV_EPS) * 1024.f;
        float p1 = __expf((ui + v2.y - c2.y) * INV_EPS) * 1024.f;
        ushort_t h0, l0, h1, l1;
        bsplit(p0, h0, l0);
        bsplit(p1, h1, l1);
        phr[j2] = ((uint32_t)h1 << 16) | h0;
        plr[j2] = ((uint32_t)l1 << 16) | l0;
    }
}

/* ---------------- BatchNorm (NHWC, two-phase, deterministic) --------------- */
__global__ __launch_bounds__(256) void bnpart(const float* __restrict__ x,
                                              float* __restrict__ ps,
                                              float* __restrict__ pq) {
    int slab = blockIdx.x, t = threadIdx.x;
    float s = 0.f, q = 0.f;
    #pragma unroll
    for (int i = 0; i < 64; i++) {
        float v = x[(size_t)(slab * 64 + i) * 256 + t];
        s += v; q = fmaf(v, v, q);
    }
    ps[slab * 256 + t] = s;
    pq[slab * 256 + t] = q;
}
__global__ void bnfin(const float* __restrict__ ps, const float* __restrict__ pq,
                      const float* __restrict__ g, const float* __restrict__ be,
                      float* __restrict__ scale, float* __restrict__ shift) {
    int c = threadIdx.x;
    float s = 0.f, q = 0.f;
    for (int k = 0; k < 64; k++) { s += ps[k * 256 + c]; q += pq[k * 256 + c]; }
    float mean = s * (1.f / 4096.f);
    float var = q * (1.f / 4096.f) - mean * mean;
    float sc = g[c] * rsqrtf(fmaxf(var, 0.f) + BN_EPS);
    scale[c] = sc;
    shift[c] = be[c] - mean * sc;
}
__global__ __launch_bounds__(256) void bn_split(const float* __restrict__ x,
                                                const float* __restrict__ scale,
                                                const float* __restrict__ shift,
                                                ushort_t* __restrict__ oh,
                                                ushort_t* __restrict__ ol) {
    int i = blockIdx.x * 256 + threadIdx.x;
    int c = i & 255;
    float v = fmaf(x[i], scale[c], shift[c]);
    ushort_t h, l;
    bsplit(v, h, l);
    oh[i] = h; ol[i] = l;
}

/* ---- blend+transpose (blocks 0..2047) merged with dec bias init (2048+) -- */
__global__ __launch_bounds__(256) void blend_T(const float* __restrict__ tn,
                                               const float* __restrict__ an,
                                               const float* __restrict__ content,
                                               const float* __restrict__ cm,
                                               const float* __restrict__ rs,
                                               float* __restrict__ outc,
                                               const float* __restrict__ db,
                                               float* __restrict__ decout) {
    __shared__ float ts[32][33], as_[32][33];
    int bx = blockIdx.x;
    if (bx >= 2048) {
        int i = (bx - 2048) * 256 + threadIdx.x;
        if (i < 4 * 3 * 1024) decout[i] = db[(i >> 10) % 3];
        return;
    }
    int pix0 = (bx & 127) * 32, ch0 = (bx >> 7) * 32;
    int tx = threadIdx.x & 31, ty = threadIdx.x >> 5;
    #pragma unroll
    for (int k = 0; k < 4; k++) {
        int p = pix0 + ty + k * 8;
        ts[ty + k * 8][tx]  = tn[(size_t)p * 512 + ch0 + tx];
        as_[ty + k * 8][tx] = an[(size_t)p * 512 + ch0 + tx];
    }
    __syncthreads();
    int b = pix0 >> 10;
    int pl = pix0 & 1023;
    #pragma unroll
    for (int k = 0; k < 4; k++) {
        int cl = ty + k * 8;
        int gch = b * 512 + ch0 + cl;
        float m = cm[gch], r = rs[gch];
        float c = content[(size_t)gch * 1024 + pl + tx];
        float v = fmaf(as_[tx][cl], (c - m) * r, ts[tx][cl]);
        outc[(size_t)gch * 1024 + pl + tx] = v;
    }
}

/* ---------------- decoder conv: CI-split accumulation ---------------- */
__global__ __launch_bounds__(128) void conv3x3_dec(
    const float* __restrict__ src0, const float* __restrict__ W,
    float* __restrict__ out) {
    constexpr int OCT = 4, SROWS = 4, NT = 128, CIT = 8;
    __shared__ float s_in[CIT][SROWS + 2][34];
    __shared__ float s_w[CIT][9][OCT];
    const int CI = 512, CO = 3;
    int b = blockIdx.x, cg0 = blockIdx.y * 64, r0 = blockIdx.z * SROWS;
    int tid = threadIdx.x;
    int row = tid >> 5, col = tid & 31;
    float acc[OCT];
    #pragma unroll
    for (int o = 0; o < OCT; o++) acc[o] = 0.f;

    const int TOTIN = CIT * (SROWS + 2) * 34;
    const int TW = CIT * 9 * OCT;
    #pragma unroll 1
    for (int ci0 = cg0; ci0 < cg0 + 64; ci0 += CIT) {
        #pragma unroll 1
        for (int idx = tid; idx < TOTIN; idx += NT) {
            int ci = idx / ((SROWS + 2) * 34);
            int rem = idx - ci * ((SROWS + 2) * 34);
            int r = rem / 34, c = rem - r * 34;
            int gy = r0 + r - 1, gx = c - 1;
            float v = 0.f;
            if ((unsigned)gy < 32u && (unsigned)gx < 32u)
                v = src0[((size_t)(b * CI + ci0 + ci) << 10) + (gy << 5) + gx];
            (&s_in[0][0][0])[idx] = v;
        }
        #pragma unroll 1
        for (int idx = tid; idx < TW; idx += NT) {
            int ci = idx / (9 * OCT);
            int rem = idx - ci * (9 * OCT);
            int k = rem / OCT, oc = rem - k * OCT;
            float wv = 0.f;
            if (oc < CO)
                wv = W[((size_t)oc * CI + ci0 + ci) * 9 + k];
            (&s_w[0][0][0])[idx] = wv;
        }
        __syncthreads();
        #pragma unroll 1
        for (int ci = 0; ci < CIT; ci++) {
            #pragma unroll
            for (int ky = 0; ky < 3; ky++)
                #pragma unroll
                for (int kx = 0; kx < 3; kx++) {
                    float4 w4 = *(const float4*)&s_w[ci][ky * 3 + kx][0];
                    float v = s_in[ci][row + ky][col + kx];
                    acc[0] = fmaf(v, w4.x, acc[0]);
                    acc[1] = fmaf(v, w4.y, acc[1]);
                    acc[2] = fmaf(v, w4.z, acc[2]);
                    acc[3] = fmaf(v, w4.w, acc[3]);
                }
        }
        __syncthreads();
    }
    #pragma unroll
    for (int o = 0; o < 3; o++)
        atomicAdd(out + ((size_t)(b * 3 + o) << 10) + (r0 + row) * 32 + col, acc[o]);
}

/* ---------------- host orchestration ---------------- */
extern "C" void kernel_launch(void* const* d_in, const int* in_sizes, int n_in,
                              void* d_out, int out_size) {
    const float* content = (const float*)d_in[0];
    const float* style   = (const float*)d_in[1];
    const float* w1 = (const float*)d_in[2];  const float* b1 = (const float*)d_in[3];
    const float* g1 = (const float*)d_in[4];  const float* be1 = (const float*)d_in[5];
    const float* w2 = (const float*)d_in[6];  const float* b2 = (const float*)d_in[7];
    const float* g2 = (const float*)d_in[8];  const float* be2 = (const float*)d_in[9];
    const float* w3 = (const float*)d_in[10]; const float* b3 = (const float*)d_in[11];
    const float* dw = (const float*)d_in[12]; const float* db = (const float*)d_in[13];
    float* out = (float*)d_out;
    (void)in_sizes; (void)n_in; (void)out_size;

    float *pC, *pCT, *pu, *pv, *prnx, *prny, *pt, *pa1, *pa2, *palpha, *pcm, *prs,
          *pscale, *pshift, *pps, *ppq;
    ushort_t *pcTh, *pcTl, *psTh, *psTl, *psfh, *psfl, *ppih, *ppil,
             *ptth, *pttl, *pb1h, *pb1l, *pb2h, *pb2l,
             *pw1h, *pw1l, *pw2h, *pw2l, *pw3h, *pw3l;
    cudaGetSymbolAddress((void**)&pC, g_C);
    cudaGetSymbolAddress((void**)&pCT, g_CT);
    cudaGetSymbolAddress((void**)&pu, g_u);
    cudaGetSymbolAddress((void**)&pv, g_v);
    cudaGetSymbolAddress((void**)&prnx, g_rnx);
    cudaGetSymbolAddress((void**)&prny, g_rny);
    cudaGetSymbolAddress((void**)&pt, g_t);
    cudaGetSymbolAddress((void**)&pa1, g_a1);
    cudaGetSymbolAddress((void**)&pa2, g_a2);
    cudaGetSymbolAddress((void**)&palpha, g_alpha);
    cudaGetSymbolAddress((void**)&pcm, g_cm);
    cudaGetSymbolAddress((void**)&prs, g_rs);
    cudaGetSymbolAddress((void**)&pscale, g_scale);
    cudaGetSymbolAddress((void**)&pshift, g_shift);
    cudaGetSymbolAddress((void**)&pps, g_ps);
    cudaGetSymbolAddress((void**)&ppq, g_pq);
    cudaGetSymbolAddress((void**)&pcTh, g_cTh);
    cudaGetSymbolAddress((void**)&pcTl, g_cTl);
    cudaGetSymbolAddress((void**)&psTh, g_sTh);
    cudaGetSymbolAddress((void**)&psTl, g_sTl);
    cudaGetSymbolAddress((void**)&psfh, g_sfh);
    cudaGetSymbolAddress((void**)&psfl, g_sfl);
    cudaGetSymbolAddress((void**)&ppih, g_pih);
    cudaGetSymbolAddress((void**)&ppil, g_pil);
    cudaGetSymbolAddress((void**)&ptth, g_tth);
    cudaGetSymbolAddress((void**)&pttl, g_ttl);
    cudaGetSymbolAddress((void**)&pb1h, g_b1h);
    cudaGetSymbolAddress((void**)&pb1l, g_b1l);
    cudaGetSymbolAddress((void**)&pb2h, g_b2h);
    cudaGetSymbolAddress((void**)&pb2l, g_b2l);
    cudaGetSymbolAddress((void**)&pw1h, g_w1h);
    cudaGetSymbolAddress((void**)&pw1l, g_w1l);
    cudaGetSymbolAddress((void**)&pw2h, g_w2h);
    cudaGetSymbolAddress((void**)&pw2l, g_w2l);
    cudaGetSymbolAddress((void**)&pw3h, g_w3h);
    cudaGetSymbolAddress((void**)&pw3l, g_w3l);

    cudaFuncSetAttribute(conv_hmma, cudaFuncAttributeMaxDynamicSharedMemorySize, CONV_SMEM);
    cudaFuncSetAttribute(hmma_gemm<1>, cudaFuncAttributeMaxDynamicSharedMemorySize, GEMM_SMEM);
    cudaFuncSetAttribute(hmma_gemm<2>, cudaFuncAttributeMaxDynamicSharedMemorySize, GEMM_SMEM);

    /* operand prep */
    transpose_split2<<<dim3(32, 16, 8), 256>>>(content, style, pcTh, pcTl, psTh, psTl);
    megaprep<<<7952, 256>>>(style, psfh, psfl, content, pcm, prs,
                            w1, pw1h, pw1l, w2, pw2h, pw2l, w3, pw3h, pw3l, pv);
    rownorm_t2<<<1024, 256>>>(pcTh, pcTl, psTh, psTl, prnx, prny);

    /* cosine-cost matrix (128x128 tiles), then C^T for the v-pass */
    hmma_gemm<1><<<dim3(8, 8, 4), 256, GEMM_SMEM>>>(pcTh, pcTl, psTh, psTl,
        1024, 512, 1024, 1024, prnx, prny, pC, nullptr, nullptr);
    transC<<<dim3(32, 32, 4), 256>>>(pC, pCT);

    /* Sinkhorn, 20 iterations — both passes row-major LSE */
    for (int it = 0; it < 20; it++) {
        lse_update<<<dim3(1024, 4), 256>>>(pC, pv, pu);    /* u pass */
        lse_update<<<dim3(1024, 4), 256>>>(pCT, pu, pv);   /* v pass */
    }

    /* pi, then t = pi @ style^T -> NHWC fp32 + bf16 split */
    pi_gen<<<dim3(1024, 4), 256>>>(pC, pu, pv, ppih, ppil);
    hmma_gemm<2><<<dim3(8, 4, 4), 256, GEMM_SMEM>>>(ppih, ppil, psfh, psfl,
        1024, 1024, 512, 512, nullptr, nullptr, pt, ptth, pttl);

    /* alpha predictor via tensor convs (NHWC) */
    conv_hmma<<<dim3(32, 4), 256, CONV_SMEM>>>(ptth, pttl, pcTh, pcTl, 512, 1024,
        pw1h, pw1l, 256, b1, 1, pa1);
    bnpart<<<64, 256>>>(pa1, pps, ppq);
    bnfin<<<1, 256>>>(pps, ppq, g1, be1, pscale, pshift);
    bn_split<<<4096, 256>>>(pa1, pscale, pshift, pb1h, pb1l);
    conv_hmma<<<dim3(32, 4), 256, CONV_SMEM>>>(pb1h, pb1l, pb1h, pb1l, 256, 256,
        pw2h, pw2l, 256, b2, 1, pa2);
    bnpart<<<64, 256>>>(pa2, pps, ppq);
    bnfin<<<1, 256>>>(pps, ppq, g2, be2, pscale, pshift);
    bn_split<<<4096, 256>>>(pa2, pscale, pshift, pb2h, pb2l);
    conv_hmma<<<dim3(32, 8), 256, CONV_SMEM>>>(pb2h, pb2l, pb2h, pb2l, 256, 256,
        pw3h, pw3l, 512, b3, 0, palpha);

    /* blend (transposed to NCHW) + decoder bias init, then decoder conv */
    blend_T<<<2096, 256>>>(pt, palpha, content, pcm, prs, pC, db, out);
    conv3x3_dec<<<dim3(4, 8, 8), 128>>>(pC, dw, out);
}

// round 17
// speedup vs baseline: 2.7083x; 1.1036x over previous
#include <cuda_runtime.h>
#include <cuda_bf16.h>
#include <cfloat>
#include <cstdint>

#define EPS_S   0.01f
#define INV_EPS 100.0f
#define LOG_MU  -6.93146200f   /* log(1/1024 + 1e-8) */
#define BN_EPS  1e-5f

typedef unsigned short ushort_t;

/* ---------------- scratch (device globals: no allocs allowed) -------------- */
__device__ float g_C[4 * 1024 * 1024];          /* cost matrix; later tblend NCHW */
__device__ float g_CT[4 * 1024 * 1024];         /* transposed cost matrix */
__device__ float g_u[4096], g_v[4096];
__device__ float g_rnx[4096], g_rny[4096];
__device__ float g_t[4 * 1024 * 512];           /* t NHWC fp32 [pix][512] */
__device__ float g_a1[4 * 1024 * 256];
__device__ float g_a2[4 * 1024 * 256];
__device__ float g_alpha[4 * 1024 * 512];
__device__ float g_cm[2048], g_rs[2048];
__device__ float g_scale[512], g_shift[512];
__device__ float g_ps[64 * 256], g_pq[64 * 256];
/* bf16 split buffers */
__device__ ushort_t g_cTh[4 * 1024 * 512], g_cTl[4 * 1024 * 512];
__device__ ushort_t g_sTh[4 * 1024 * 512], g_sTl[4 * 1024 * 512];
__device__ ushort_t g_sfh[4 * 512 * 1024], g_sfl[4 * 512 * 1024];
__device__ ushort_t g_pih[4 * 1024 * 1024], g_pil[4 * 1024 * 1024];
__device__ ushort_t g_tth[4 * 1024 * 512], g_ttl[4 * 1024 * 512];
__device__ ushort_t g_b1h[4 * 1024 * 256], g_b1l[4 * 1024 * 256];
__device__ ushort_t g_b2h[4 * 1024 * 256], g_b2l[4 * 1024 * 256];
__device__ ushort_t g_w1h[9 * 256 * 1024], g_w1l[9 * 256 * 1024];
__device__ ushort_t g_w2h[9 * 256 * 256],  g_w2l[9 * 256 * 256];
__device__ ushort_t g_w3h[9 * 512 * 256],  g_w3l[9 * 512 * 256];

__device__ __forceinline__ uint32_t smem_u32(const void* p) {
    uint32_t a;
    asm("{ .reg .u64 t; cvta.to.shared.u64 t, %1; cvt.u32.u64 %0, t; }"
        : "=r"(a) : "l"(p));
    return a;
}
__device__ __forceinline__ void cp16(uint32_t s, const void* g) {
    asm volatile("cp.async.cg.shared.global [%0], [%1], 16;" :: "r"(s), "l"(g));
}
__device__ __forceinline__ void cp16p(uint32_t s, const void* g, bool ok) {
    int sz = ok ? 16 : 0;
    asm volatile("cp.async.cg.shared.global [%0], [%1], 16, %2;"
                 :: "r"(s), "l"(g), "r"(sz));
}
#define CP_COMMIT() asm volatile("cp.async.commit_group;" ::: "memory")
#define CP_WAIT0()  asm volatile("cp.async.wait_group 0;" ::: "memory")
#define CP_WAIT1()  asm volatile("cp.async.wait_group 1;" ::: "memory")

__device__ __forceinline__ void ldsm_x4(uint32_t& r0, uint32_t& r1,
                                        uint32_t& r2, uint32_t& r3, uint32_t a) {
    asm volatile("ldmatrix.sync.aligned.m8n8.x4.shared.b16 {%0,%1,%2,%3}, [%4];"
                 : "=r"(r0), "=r"(r1), "=r"(r2), "=r"(r3) : "r"(a));
}
__device__ __forceinline__ void mma_bf16(float& d0, float& d1, float& d2, float& d3,
                                         uint32_t a0, uint32_t a1, uint32_t a2, uint32_t a3,
                                         uint32_t b0, uint32_t b1) {
    asm volatile(
        "mma.sync.aligned.m16n8k16.row.col.f32.bf16.bf16.f32 "
        "{%0,%1,%2,%3}, {%4,%5,%6,%7}, {%8,%9}, {%0,%1,%2,%3};"
        : "+f"(d0), "+f"(d1), "+f"(d2), "+f"(d3)
        : "r"(a0), "r"(a1), "r"(a2), "r"(a3), "r"(b0), "r"(b1));
}
__device__ __forceinline__ void bsplit(float v, ushort_t& h, ushort_t& l) {
    __nv_bfloat16 hh = __float2bfloat16(v);
    float rem = v - __bfloat162float(hh);
    __nv_bfloat16 ll = __float2bfloat16(rem);
    h = __bfloat16_as_ushort(hh);
    l = __bfloat16_as_ushort(ll);
}
__device__ __forceinline__ float bf2f(ushort_t x) {
    return __bfloat162float(__ushort_as_bfloat16(x));
}
__device__ __forceinline__ float warpSum(float v) {
    #pragma unroll
    for (int o = 16; o; o >>= 1) v += __shfl_xor_sync(0xffffffffu, v, o);
    return v;
}
__device__ __forceinline__ float warpMax(float v) {
    #pragma unroll
    for (int o = 16; o; o >>= 1) v = fmaxf(v, __shfl_xor_sync(0xffffffffu, v, o));
    return v;
}

/* ============ HMMA bf16 split GEMM, 128x128 tile, K-chunk 64, dbuf ========
   Row stride 144 B (72 bf16): rows land on distinct 16B phases mod 128.
   smem: Ah[2]@0 (18432 ea), Al[2]@36864, Bh[2]@73728, Bl[2]@110592.        */
static const int GEMM_SMEM = 147456;
template <int EPI>
__global__ __launch_bounds__(256) void hmma_gemm(
    const ushort_t* __restrict__ Ahi, const ushort_t* __restrict__ Alo,
    const ushort_t* __restrict__ Bhi, const ushort_t* __restrict__ Blo,
    int Mtot, int Ktot, int Nrows, int OS,
    const float* __restrict__ rnx, const float* __restrict__ rny,
    float* __restrict__ out, ushort_t* __restrict__ o2h, ushort_t* __restrict__ o2l) {
    extern __shared__ unsigned char gs[];
    uint32_t sb = smem_u32(gs);
    int tid = threadIdx.x, wid = tid >> 5, lid = tid & 31;
    int b = blockIdx.z, m0 = blockIdx.x * 128, n0 = blockIdx.y * 128;
    int wm = wid & 3, wn = wid >> 2;
    size_t abase = (size_t)b * Mtot * Ktot;
    size_t bbase = (size_t)b * Nrows * Ktot;
    int arow = ((lid >> 3) & 1) * 8 + (lid & 7);
    int akof = (lid >> 4) * 8;
    int brow = (lid & 7) + ((lid >> 4) & 1) * 8;
    int bkof = ((lid >> 3) & 1) * 8;

    float d[2][8][4];
    #pragma unroll
    for (int i = 0; i < 2; i++)
        #pragma unroll
        for (int j = 0; j < 8; j++)
            #pragma unroll
            for (int q = 0; q < 4; q++) d[i][j][q] = 0.f;

#define FILLG(K0, BUF) do {                                                    \
    int k0_ = (K0);                                                            \
    uint32_t aB = sb + (BUF) * 18432;                                          \
    uint32_t alB = sb + 36864 + (BUF) * 18432;                                 \
    uint32_t bB = sb + 73728 + (BUF) * 18432;                                  \
    uint32_t blB = sb + 110592 + (BUF) * 18432;                                \
    _Pragma("unroll")                                                          \
    for (int l = 0; l < 4; l++) {                                              \
        int idx = tid + l * 256;                                               \
        int r = idx >> 3, seg = idx & 7;                                       \
        cp16(aB + r * 144 + seg * 16,                                          \
             Ahi + abase + (size_t)(m0 + r) * Ktot + k0_ + seg * 8);           \
        cp16(alB + r * 144 + seg * 16,                                         \
             Alo + abase + (size_t)(m0 + r) * Ktot + k0_ + seg * 8);           \
        cp16(bB + r * 144 + seg * 16,                                          \
             Bhi + bbase + (size_t)(n0 + r) * Ktot + k0_ + seg * 8);           \
        cp16(blB + r * 144 + seg * 16,                                         \
             Blo + bbase + (size_t)(n0 + r) * Ktot + k0_ + seg * 8);           \
    }                                                                          \
} while (0)

    int nch = Ktot >> 6;
    FILLG(0, 0);
    CP_COMMIT();
    for (int c = 0; c < nch; c++) {
        int buf = c & 1;
        if (c + 1 < nch) {
            FILLG((c + 1) << 6, (c + 1) & 1);
            CP_COMMIT();
            CP_WAIT1();
        } else {
            CP_WAIT0();
        }
        __syncthreads();
        uint32_t uAh = sb + buf * 18432;
        uint32_t uAl = sb + 36864 + buf * 18432;
        uint32_t uBh = sb + 73728 + buf * 18432;
        uint32_t uBl = sb + 110592 + buf * 18432;
        #pragma unroll
        for (int ks = 0; ks < 4; ks++) {
            int kb = ks * 16;
            uint32_t ah[2][4], al[2][4];
            #pragma unroll
            for (int tm = 0; tm < 2; tm++) {
                uint32_t off = (uint32_t)((wm * 32 + tm * 16 + arow) * 144 + (kb + akof) * 2);
                ldsm_x4(ah[tm][0], ah[tm][1], ah[tm][2], ah[tm][3], uAh + off);
                ldsm_x4(al[tm][0], al[tm][1], al[tm][2], al[tm][3], uAl + off);
            }
            uint32_t bh[8][2], bl[8][2];
            #pragma unroll
            for (int p = 0; p < 4; p++) {
                uint32_t off = (uint32_t)((wn * 64 + p * 16 + brow) * 144 + (kb + bkof) * 2);
                ldsm_x4(bh[2 * p][0], bh[2 * p][1], bh[2 * p + 1][0], bh[2 * p + 1][1], uBh + off);
                ldsm_x4(bl[2 * p][0], bl[2 * p][1], bl[2 * p + 1][0], bl[2 * p + 1][1], uBl + off);
            }
            #pragma unroll
            for (int tm = 0; tm < 2; tm++)
                #pragma unroll
                for (int tn = 0; tn < 8; tn++) {
                    mma_bf16(d[tm][tn][0], d[tm][tn][1], d[tm][tn][2], d[tm][tn][3],
                             ah[tm][0], ah[tm][1], ah[tm][2], ah[tm][3], bh[tn][0], bh[tn][1]);
                    mma_bf16(d[tm][tn][0], d[tm][tn][1], d[tm][tn][2], d[tm][tn][3],
                             ah[tm][0], ah[tm][1], ah[tm][2], ah[tm][3], bl[tn][0], bl[tn][1]);
                    mma_bf16(d[tm][tn][0], d[tm][tn][1], d[tm][tn][2], d[tm][tn][3],
                             al[tm][0], al[tm][1], al[tm][2], al[tm][3], bh[tn][0], bh[tn][1]);
                }
        }
        __syncthreads();
    }
#undef FILLG
    int tq = lid >> 2, tr = lid & 3;
    #pragma unroll
    for (int tm = 0; tm < 2; tm++) {
        #pragma unroll
        for (int half = 0; half < 2; half++) {
            int r = m0 + wm * 32 + tm * 16 + tq + half * 8;
            #pragma unroll
            for (int tn = 0; tn < 8; tn++) {
                int col = n0 + wn * 64 + tn * 8 + 2 * tr;
                float v0 = d[tm][tn][2 * half], v1 = d[tm][tn][2 * half + 1];
                size_t oidx = ((size_t)b * Mtot + r) * OS + col;
                if (EPI == 1) {
                    float rx = rnx[(b << 10) + r];
                    float2 o;
                    o.x = 1.f - rx * rny[(b << 10) + col] * v0;
                    o.y = 1.f - rx * rny[(b << 10) + col + 1] * v1;
                    *(float2*)(out + oidx) = o;
                } else {
                    float2 o; o.x = v0; o.y = v1;
                    *(float2*)(out + oidx) = o;
                    ushort_t h0, l0, h1, l1;
                    bsplit(v0, h0, l0);
                    bsplit(v1, h1, l1);
                    *(uint32_t*)(o2h + oidx) = ((uint32_t)h1 << 16) | h0;
                    *(uint32_t*)(o2l + oidx) = ((uint32_t)l1 << 16) | l0;
                }
            }
        }
    }
}

/* ============ shifted-GEMM tensor conv: weights double-buffered =========== */
static const int CONV_SMEM = 216960;
__global__ __launch_bounds__(256) void conv_hmma(
    const ushort_t* __restrict__ Ah0, const ushort_t* __restrict__ Al0,
    const ushort_t* __restrict__ Ah1, const ushort_t* __restrict__ Al1,
    int csplit, int CI,
    const ushort_t* __restrict__ Wh, const ushort_t* __restrict__ Wl,
    int CO, const float* __restrict__ bias, int relu,
    float* __restrict__ out) {
    extern __shared__ unsigned char cs[];
    uint32_t sbc = smem_u32(cs);
    uint32_t uIh = sbc;
    uint32_t uIl = sbc + 16320;
    int tid = threadIdx.x, wid = tid >> 5, lid = tid & 31;
    int mt = blockIdx.x;
    int b = mt >> 3, r0 = (mt & 7) * 4;
    int n0 = blockIdx.y * 64;
    int wm = wid & 3, wn = wid >> 2;
    int arow = ((lid >> 3) & 1) * 8 + (lid & 7);
    int akof = (lid >> 4) * 8;
    int brow = (lid & 7) + ((lid >> 4) & 1) * 8;
    int bkof = ((lid >> 3) & 1) * 8;
    uint32_t aoff[2];
    #pragma unroll
    for (int tm = 0; tm < 2; tm++) {
        int p = wm * 32 + tm * 16 + arow;
        aoff[tm] = (uint32_t)(((p >> 5) * 34 + (p & 31)) * 80 + akof * 2);
    }
    uint32_t boff = (uint32_t)((wn * 32 + brow) * 80 + bkof * 2);

    float d[2][4][4];
    #pragma unroll
    for (int i = 0; i < 2; i++)
        #pragma unroll
        for (int j = 0; j < 4; j++)
            #pragma unroll
            for (int q = 0; q < 4; q++) d[i][j][q] = 0.f;

#define FILLW(CH, BUF) do {                                                    \
    int ch_ = (CH);                                                            \
    uint32_t wB = sbc + 32640 + (BUF) * 46080;                                 \
    uint32_t wlB = sbc + 124800 + (BUF) * 46080;                               \
    _Pragma("unroll")                                                          \
    for (int l = 0; l < 9; l++) {                                              \
        int idx = tid + l * 256;                                               \
        int tap = idx >> 8, rem = idx & 255, oc = rem >> 2, seg = rem & 3;     \
        size_t woff = ((size_t)(tap * CO + n0 + oc)) * CI + ch_ + seg * 8;     \
        cp16(wB + (tap * 64 + oc) * 80 + seg * 16, Wh + woff);                 \
        cp16(wlB + (tap * 64 + oc) * 80 + seg * 16, Wl + woff);                \
    }                                                                          \
} while (0)

#define FILLI(CH) do {                                                         \
    int ch_ = (CH);                                                            \
    const ushort_t* srcH;                                                      \
    const ushort_t* srcL;                                                      \
    int cw, coff;                                                              \
    if (ch_ < csplit) { srcH = Ah0; srcL = Al0; cw = csplit; coff = ch_; }     \
    else { srcH = Ah1; srcL = Al1; cw = CI - csplit; coff = ch_ - csplit; }    \
    _Pragma("unroll")                                                          \
    for (int l = 0; l < 4; l++) {                                              \
        int idx = tid + l * 256;                                               \
        if (idx < 816) {                                                       \
            int sp = idx >> 2, seg = idx & 3;                                  \
            int srow = sp / 34, scol = sp - srow * 34;                         \
            int gy = r0 - 1 + srow, gx = scol - 1;                             \
            bool ok = ((unsigned)gy < 32u) && ((unsigned)gx < 32u);            \
            size_t off = ok                                                    \
                ? ((size_t)(b * 1024 + (gy << 5) + gx) * cw + coff + seg * 8)  \
                : 0;                                                           \
            cp16p(uIh + sp * 80 + seg * 16, srcH + off, ok);                   \
            cp16p(uIl + sp * 80 + seg * 16, srcL + off, ok);                   \
        }                                                                      \
    }                                                                          \
} while (0)

    int nch = CI >> 5;
    FILLW(0, 0);
    FILLI(0);
    CP_COMMIT();
    CP_WAIT0();
    __syncthreads();
    for (int c = 0; c < nch; c++) {
        int buf = c & 1;
        if (c + 1 < nch) {
            FILLW((c + 1) << 5, (c + 1) & 1);
            CP_COMMIT();
        }
        uint32_t uBh = sbc + 32640 + buf * 46080;
        uint32_t uBl = sbc + 124800 + buf * 46080;
        #pragma unroll 1
        for (int ky = 0; ky < 3; ky++) {
            #pragma unroll
            for (int kx = 0; kx < 3; kx++) {
                uint32_t shoff = (uint32_t)((ky * 34 + kx) * 80);
                uint32_t tapoff = (uint32_t)((ky * 3 + kx) * 5120);
                #pragma unroll
                for (int ks = 0; ks < 2; ks++) {
                    uint32_t kso = (uint32_t)(ks * 32);
                    uint32_t ah[2][4], al[2][4];
                    #pragma unroll
                    for (int tm = 0; tm < 2; tm++) {
                        ldsm_x4(ah[tm][0], ah[tm][1], ah[tm][2], ah[tm][3],
                                uIh + aoff[tm] + shoff + kso);
                        ldsm_x4(al[tm][0], al[tm][1], al[tm][2], al[tm][3],
                                uIl + aoff[tm] + shoff + kso);
                    }
                    uint32_t bh[4][2], bl[4][2];
                    #pragma unroll
                    for (int p = 0; p < 2; p++) {
                        uint32_t off = boff + tapoff + (uint32_t)(p * 1280) + kso;
                        ldsm_x4(bh[2 * p][0], bh[2 * p][1], bh[2 * p + 1][0], bh[2 * p + 1][1],
                                uBh + off);
                        ldsm_x4(bl[2 * p][0], bl[2 * p][1], bl[2 * p + 1][0], bl[2 * p + 1][1],
                                uBl + off);
                    }
                    #pragma unroll
                    for (int tm = 0; tm < 2; tm++)
                        #pragma unroll
                        for (int tn = 0; tn < 4; tn++) {
                            mma_bf16(d[tm][tn][0], d[tm][tn][1], d[tm][tn][2], d[tm][tn][3],
                                     ah[tm][0], ah[tm][1], ah[tm][2], ah[tm][3],
                                     bh[tn][0], bh[tn][1]);
                            mma_bf16(d[tm][tn][0], d[tm][tn][1], d[tm][tn][2], d[tm][tn][3],
                                     ah[tm][0], ah[tm][1], ah[tm][2], ah[tm][3],
                                     bl[tn][0], bl[tn][1]);
                            mma_bf16(d[tm][tn][0], d[tm][tn][1], d[tm][tn][2], d[tm][tn][3],
                                     al[tm][0], al[tm][1], al[tm][2], al[tm][3],
                                     bh[tn][0], bh[tn][1]);
                        }
                }
            }
        }
        __syncthreads();
        if (c + 1 < nch) {
            FILLI((c + 1) << 5);
            CP_COMMIT();
            CP_WAIT0();
        }
        __syncthreads();
    }
#undef FILLW
#undef FILLI
    int tq = lid >> 2, tr = lid & 3;
    #pragma unroll
    for (int tm = 0; tm < 2; tm++) {
        #pragma unroll
        for (int half = 0; half < 2; half++) {
            int pt = wm * 32 + tm * 16 + tq + half * 8;
            size_t prow = (size_t)(b * 1024 + r0 * 32 + pt) * CO;
            #pragma unroll
            for (int tn = 0; tn < 4; tn++) {
                int col = n0 + wn * 32 + tn * 8 + 2 * tr;
                float v0 = d[tm][tn][2 * half] + bias[col];
                float v1 = d[tm][tn][2 * half + 1] + bias[col + 1];
                if (relu) { v0 = fmaxf(v0, 0.f); v1 = fmaxf(v1, 0.f); }
                float2 o; o.x = v0; o.y = v1;
                *(float2*)(out + prow + col) = o;
            }
        }
    }
}

/* ---------------- prep kernels ---------------- */
/* C -> C^T, tiled (fp32), per batch */
__global__ __launch_bounds__(256) void transC(const float* __restrict__ C,
                                              float* __restrict__ CT) {
    __shared__ float tb[32][33];
    int b = blockIdx.z;
    int i0 = blockIdx.x * 32, j0 = blockIdx.y * 32;
    int tx = threadIdx.x & 31, ty = threadIdx.x >> 5;
    const float* Cb = C + (size_t)b * 1048576;
    float* Tb = CT + (size_t)b * 1048576;
    #pragma unroll
    for (int k = 0; k < 4; k++)
        tb[ty + k * 8][tx] = Cb[(size_t)(i0 + ty + k * 8) * 1024 + j0 + tx];
    __syncthreads();
    #pragma unroll
    for (int k = 0; k < 4; k++)
        Tb[(size_t)(j0 + ty + k * 8) * 1024 + i0 + tx] = tb[tx][ty + k * 8];
}

__global__ __launch_bounds__(256) void rownorm_t2(
    const ushort_t* __restrict__ xh0, const ushort_t* __restrict__ xl0,
    const ushort_t* __restrict__ xh1, const ushort_t* __restrict__ xl1,
    float* __restrict__ rn0, float* __restrict__ rn1) {
    int big = blockIdx.x >= 512;
    const ushort_t* xh = big ? xh1 : xh0;
    const ushort_t* xl = big ? xl1 : xl0;
    float* rn = big ? rn1 : rn0;
    int row = (blockIdx.x & 511) * 8 + (threadIdx.x >> 5);
    int lane = threadIdx.x & 31;
    const uint4* ph = (const uint4*)(xh + (size_t)row * 512);
    const uint4* pl = (const uint4*)(xl + (size_t)row * 512);
    float s = 0.f;
    #pragma unroll
    for (int k = 0; k < 2; k++) {
        uint4 h4 = ph[lane + k * 32], l4 = pl[lane + k * 32];
        const ushort_t* hh = (const ushort_t*)&h4;
        const ushort_t* ll = (const ushort_t*)&l4;
        #pragma unroll
        for (int j = 0; j < 8; j++) {
            float v = bf2f(hh[j]) + bf2f(ll[j]);
            s = fmaf(v, v, s);
        }
    }
    s = warpSum(s);
    if (lane == 0) rn[row] = rsqrtf(s);
}

/* mega-prep: convert_split(style) | cmstd | wprep x3 | zero_v | transpose-split */
__global__ __launch_bounds__(256) void megaprep(
    const float* __restrict__ style, ushort_t* __restrict__ sfh,
    ushort_t* __restrict__ sfl,
    const float* __restrict__ content, float* __restrict__ cm,
    float* __restrict__ rs,
    const float* __restrict__ w1, ushort_t* __restrict__ w1h, ushort_t* __restrict__ w1l,
    const float* __restrict__ w2, ushort_t* __restrict__ w2h, ushort_t* __restrict__ w2l,
    const float* __restrict__ w3, ushort_t* __restrict__ w3h, ushort_t* __restrict__ w3l,
    float* __restrict__ v,
    ushort_t* __restrict__ cTh, ushort_t* __restrict__ cTl,
    ushort_t* __restrict__ sTh, ushort_t* __restrict__ sTl) {
    __shared__ float rsm[8], rqm[8];
    __shared__ float tb[32][33];
    int blk = blockIdx.x, t = threadIdx.x;
    if (blk < 4096) {
        int i = blk * 256 + t;
        float2 vv = ((const float2*)style)[i];
        ushort_t h0, l0, h1, l1;
        bsplit(vv.x, h0, l0);
        bsplit(vv.y, h1, l1);
        ((uint32_t*)sfh)[i] = ((uint32_t)h1 << 16) | h0;
        ((uint32_t*)sfl)[i] = ((uint32_t)l1 << 16) | l0;
    } else if (blk < 6144) {
        int bc = blk - 4096;
        const float* p = content + ((size_t)bc << 10);
        float s = 0.f, q = 0.f;
        #pragma unroll
        for (int l = 0; l < 4; l++) {
            float x = p[t + l * 256];
            s += x; q = fmaf(x, x, q);
        }
        s = warpSum(s); q = warpSum(q);
        if ((t & 31) == 0) { rsm[t >> 5] = s; rqm[t >> 5] = q; }
        __syncthreads();
        if (t == 0) {
            float S = 0.f, Q = 0.f;
            #pragma unroll
            for (int w = 0; w < 8; w++) { S += rsm[w]; Q += rqm[w]; }
            float mean = S * (1.f / 1024.f);
            float var = Q * (1.f / 1024.f) - mean * mean;
            cm[bc] = mean;
            rs[bc] = rsqrtf(fmaxf(var, 0.f) + 1e-5f);
        }
    } else if (blk < 7936) {
        const float* w; ushort_t* wh; ushort_t* wl; int CO, CI, i;
        if (blk < 7168)      { w = w1; wh = w1h; wl = w1l; CO = 256; CI = 1024; i = (blk - 6144) * 256 + t; }
        else if (blk < 7424) { w = w2; wh = w2h; wl = w2l; CO = 256; CI = 256;  i = (blk - 7168) * 256 + t; }
        else                 { w = w3; wh = w3h; wl = w3l; CO = 512; CI = 256;  i = (blk - 7424) * 256 + t; }
        if (i < CO * CI) {
            int oc = i / CI, ci = i - oc * CI;
            #pragma unroll
            for (int k = 0; k < 9; k++) {
                float x = w[(size_t)i * 9 + k];
                ushort_t h, l;
                bsplit(x, h, l);
                size_t o = ((size_t)k * CO + oc) * CI + ci;
                wh[o] = h; wl[o] = l;
            }
        }
    } else if (blk < 7952) {
        int i = (blk - 7936) * 256 + t;
        if (i < 4096) v[i] = 0.f;
    } else {
        /* transpose-split: 4096 blocks, z = range/512 (0-3 content, 4-7 style) */
        int r = blk - 7952;
        int z = r >> 9, rem = r & 511;
        const float* x = (z < 4) ? content : style;
        ushort_t* oh = (z < 4) ? cTh : sTh;
        ushort_t* ol = (z < 4) ? cTl : sTl;
        int b = z & 3;
        int i0 = (rem & 31) * 32, d0 = (rem >> 5) * 32;
        int tx = t & 31, ty = t >> 5;
        const float* xb = x + (size_t)b * 512 * 1024;
        #pragma unroll
        for (int k = 0; k < 4; k++)
            tb[ty + k * 8][tx] = xb[(size_t)(d0 + ty + k * 8) * 1024 + i0 + tx];
        __syncthreads();
        #pragma unroll
        for (int k = 0; k < 4; k++) {
            int il = ty + k * 8;
            float vv = tb[tx][il];
            ushort_t h, l;
            bsplit(vv, h, l);
            size_t o = (size_t)b * 1024 * 512 + (size_t)(i0 + il) * 512 + d0 + tx;
            oh[o] = h; ol[o] = l;
        }
    }
}

/* ---------------- Sinkhorn: row-LSE, 2 rows per block ----------------------
   out[r] = EPS*(LOG_MU - LSE_c((vec[c] - M[r][c])*INV_EPS)), M row-major.  */
__global__ __launch_bounds__(256) void lse_update(const float* __restrict__ M,
                                                  const float* __restrict__ vec,
                                                  float* __restrict__ out) {
    int b = blockIdx.y;
    int g = threadIdx.x >> 7;           /* row group 0/1 */
    int t = threadIdx.x & 127;
    int i = blockIdx.x * 2 + g;
    const float4* C4 = (const float4*)(M + ((size_t)(b << 10) + i) * 1024);
    const float4* V4 = (const float4*)(vec + (b << 10));
    float4 c0 = C4[t], v0 = V4[t];
    float4 c1 = C4[t + 128], v1 = V4[t + 128];
    float x0 = (v0.x - c0.x) * INV_EPS;
    float x1 = (v0.y - c0.y) * INV_EPS;
    float x2 = (v0.z - c0.z) * INV_EPS;
    float x3 = (v0.w - c0.w) * INV_EPS;
    float x4 = (v1.x - c1.x) * INV_EPS;
    float x5 = (v1.y - c1.y) * INV_EPS;
    float x6 = (v1.z - c1.z) * INV_EPS;
    float x7 = (v1.w - c1.w) * INV_EPS;
    float mx = fmaxf(fmaxf(fmaxf(x0, x1), fmaxf(x2, x3)),
                     fmaxf(fmaxf(x4, x5), fmaxf(x6, x7)));
    __shared__ float redm[2][4], redq[2][4];
    mx = warpMax(mx);
    if ((t & 31) == 0) redm[g][t >> 5] = mx;
    __syncthreads();
    float bm = fmaxf(fmaxf(redm[g][0], redm[g][1]), fmaxf(redm[g][2], redm[g][3]));
    float s = __expf(x0 - bm) + __expf(x1 - bm) + __expf(x2 - bm) + __expf(x3 - bm)
            + __expf(x4 - bm) + __expf(x5 - bm) + __expf(x6 - bm) + __expf(x7 - bm);
    s = warpSum(s);
    if ((t & 31) == 0) redq[g][t >> 5] = s;
    __syncthreads();
    if (t == 0) {
        float z = redq[g][0] + redq[g][1] + redq[g][2] + redq[g][3];
        out[(b << 10) + i] = EPS_S * (LOG_MU - (bm + __logf(z)));
    }
}

__global__ __launch_bounds__(256) void pi_gen(
    const float* __restrict__ C, const float* __restrict__ u,
    const float* __restrict__ v, ushort_t* __restrict__ ph,
    ushort_t* __restrict__ pl) {
    int b = blockIdx.y, i = blockIdx.x, t = threadIdx.x;
    float ui = u[(b << 10) + i];
    const float2* Crow = (const float2*)(C + ((size_t)(b << 10) + i) * 1024);
    const float2* vrow = (const float2*)(v + (b << 10));
    uint32_t* phr = (uint32_t*)(ph + ((size_t)(b << 10) + i) * 1024);
    uint32_t* plr = (uint32_t*)(pl + ((size_t)(b << 10) + i) * 1024);
    #pragma unroll
    for (int l = 0; l < 2; l++) {
        int j2 = t + l * 256;
        float2 c2 = Crow[j2], v2 = vrow[j2];
        float p0 = __expf((ui + v2.x - c2.x) * INV_EPS) * 1024.f;
        float p1 = __expf((ui + v2.y - c2.y) * INV_EPS) * 1024.f;
        ushort_t h0, l0, h1, l1;
        bsplit(p0, h0, l0);
        bsplit(p1, h1, l1);
        phr[j2] = ((uint32_t)h1 << 16) | h0;
        plr[j2] = ((uint32_t)l1 << 16) | l0;
    }
}

/* ---------------- BatchNorm (NHWC, two-phase, deterministic) --------------- */
__global__ __launch_bounds__(256) void bnpart(const float* __restrict__ x,
                                              float* __restrict__ ps,
                                              float* __restrict__ pq) {
    int slab = blockIdx.x, t = threadIdx.x;
    float s = 0.f, q = 0.f;
    #pragma unroll
    for (int i = 0; i < 64; i++) {
        float v = x[(size_t)(slab * 64 + i) * 256 + t];
        s += v; q = fmaf(v, v, q);
    }
    ps[slab * 256 + t] = s;
    pq[slab * 256 + t] = q;
}
__global__ void bnfin(const float* __restrict__ ps, const float* __restrict__ pq,
                      const float* __restrict__ g, const float* __restrict__ be,
                      float* __restrict__ scale, float* __restrict__ shift) {
    int c = threadIdx.x;
    float s = 0.f, q = 0.f;
    for (int k = 0; k < 64; k++) { s += ps[k * 256 + c]; q += pq[k * 256 + c]; }
    float mean = s * (1.f / 4096.f);
    float var = q * (1.f / 4096.f) - mean * mean;
    float sc = g[c] * rsqrtf(fmaxf(var, 0.f) + BN_EPS);
    scale[c] = sc;
    shift[c] = be[c] - mean * sc;
}
__global__ __launch_bounds__(256) void bn_split(const float* __restrict__ x,
                                                const float* __restrict__ scale,
                                                const float* __restrict__ shift,
                                                ushort_t* __restrict__ oh,
                                                ushort_t* __restrict__ ol) {
    int i = blockIdx.x * 256 + threadIdx.x;
    int c = i & 255;
    float v = fmaf(x[i], scale[c], shift[c]);
    ushort_t h, l;
    bsplit(v, h, l);
    oh[i] = h; ol[i] = l;
}

/* ---- blend+transpose (blocks 0..2047) merged with dec bias init (2048+) -- */
__global__ __launch_bounds__(256) void blend_T(const float* __restrict__ tn,
                                               const float* __restrict__ an,
                                               const float* __restrict__ content,
                                               const float* __restrict__ cm,
                                               const float* __restrict__ rs,
                                               float* __restrict__ outc,
                                               const float* __restrict__ db,
                                               float* __restrict__ decout) {
    __shared__ float ts[32][33], as_[32][33];
    int bx = blockIdx.x;
    if (bx >= 2048) {
        int i = (bx - 2048) * 256 + threadIdx.x;
        if (i < 4 * 3 * 1024) decout[i] = db[(i >> 10) % 3];
        return;
    }
    int pix0 = (bx & 127) * 32, ch0 = (bx >> 7) * 32;
    int tx = threadIdx.x & 31, ty = threadIdx.x >> 5;
    #pragma unroll
    for (int k = 0; k < 4; k++) {
        int p = pix0 + ty + k * 8;
        ts[ty + k * 8][tx]  = tn[(size_t)p * 512 + ch0 + tx];
        as_[ty + k * 8][tx] = an[(size_t)p * 512 + ch0 + tx];
    }
    __syncthreads();
    int b = pix0 >> 10;
    int pl = pix0 & 1023;
    #pragma unroll
    for (int k = 0; k < 4; k++) {
        int cl = ty + k * 8;
        int gch = b * 512 + ch0 + cl;
        float m = cm[gch], r = rs[gch];
        float c = content[(size_t)gch * 1024 + pl + tx];
        float v = fmaf(as_[tx][cl], (c - m) * r, ts[tx][cl]);
        outc[(size_t)gch * 1024 + pl + tx] = v;
    }
}

/* ---------------- decoder conv: CI-split accumulation ---------------- */
__global__ __launch_bounds__(128) void conv3x3_dec(
    const float* __restrict__ src0, const float* __restrict__ W,
    float* __restrict__ out) {
    constexpr int OCT = 4, SROWS = 4, NT = 128, CIT = 8;
    __shared__ float s_in[CIT][SROWS + 2][34];
    __shared__ float s_w[CIT][9][OCT];
    const int CI = 512, CO = 3;
    int b = blockIdx.x, cg0 = blockIdx.y * 64, r0 = blockIdx.z * SROWS;
    int tid = threadIdx.x;
    int row = tid >> 5, col = tid & 31;
    float acc[OCT];
    #pragma unroll
    for (int o = 0; o < OCT; o++) acc[o] = 0.f;

    const int TOTIN = CIT * (SROWS + 2) * 34;
    const int TW = CIT * 9 * OCT;
    #pragma unroll 1
    for (int ci0 = cg0; ci0 < cg0 + 64; ci0 += CIT) {
        #pragma unroll 1
        for (int idx = tid; idx < TOTIN; idx += NT) {
            int ci = idx / ((SROWS + 2) * 34);
            int rem = idx - ci * ((SROWS + 2) * 34);
            int r = rem / 34, c = rem - r * 34;
            int gy = r0 + r - 1, gx = c - 1;
            float v = 0.f;
            if ((unsigned)gy < 32u && (unsigned)gx < 32u)
                v = src0[((size_t)(b * CI + ci0 + ci) << 10) + (gy << 5) + gx];
            (&s_in[0][0][0])[idx] = v;
        }
        #pragma unroll 1
        for (int idx = tid; idx < TW; idx += NT) {
            int ci = idx / (9 * OCT);
            int rem = idx - ci * (9 * OCT);
            int k = rem / OCT, oc = rem - k * OCT;
            float wv = 0.f;
            if (oc < CO)
                wv = W[((size_t)oc * CI + ci0 + ci) * 9 + k];
            (&s_w[0][0][0])[idx] = wv;
        }
        __syncthreads();
        #pragma unroll 1
        for (int ci = 0; ci < CIT; ci++) {
            #pragma unroll
            for (int ky = 0; ky < 3; ky++)
                #pragma unroll
                for (int kx = 0; kx < 3; kx++) {
                    float4 w4 = *(const float4*)&s_w[ci][ky * 3 + kx][0];
                    float v = s_in[ci][row + ky][col + kx];
                    acc[0] = fmaf(v, w4.x, acc[0]);
                    acc[1] = fmaf(v, w4.y, acc[1]);
                    acc[2] = fmaf(v, w4.z, acc[2]);
                    acc[3] = fmaf(v, w4.w, acc[3]);
                }
        }
        __syncthreads();
    }
    #pragma unroll
    for (int o = 0; o < 3; o++)
        atomicAdd(out + ((size_t)(b * 3 + o) << 10) + (r0 + row) * 32 + col, acc[o]);
}

/* ---------------- host orchestration ---------------- */
extern "C" void kernel_launch(void* const* d_in, const int* in_sizes, int n_in,
                              void* d_out, int out_size) {
    const float* content = (const float*)d_in[0];
    const float* style   = (const float*)d_in[1];
    const float* w1 = (const float*)d_in[2];  const float* b1 = (const float*)d_in[3];
    const float* g1 = (const float*)d_in[4];  const float* be1 = (const float*)d_in[5];
    const float* w2 = (const float*)d_in[6];  const float* b2 = (const float*)d_in[7];
    const float* g2 = (const float*)d_in[8];  const float* be2 = (const float*)d_in[9];
    const float* w3 = (const float*)d_in[10]; const float* b3 = (const float*)d_in[11];
    const float* dw = (const float*)d_in[12]; const float* db = (const float*)d_in[13];
    float* out = (float*)d_out;
    (void)in_sizes; (void)n_in; (void)out_size;

    float *pC, *pCT, *pu, *pv, *prnx, *prny, *pt, *pa1, *pa2, *palpha, *pcm, *prs,
          *pscale, *pshift, *pps, *ppq;
    ushort_t *pcTh, *pcTl, *psTh, *psTl, *psfh, *psfl, *ppih, *ppil,
             *ptth, *pttl, *pb1h, *pb1l, *pb2h, *pb2l,
             *pw1h, *pw1l, *pw2h, *pw2l, *pw3h, *pw3l;
    cudaGetSymbolAddress((void**)&pC, g_C);
    cudaGetSymbolAddress((void**)&pCT, g_CT);
    cudaGetSymbolAddress((void**)&pu, g_u);
    cudaGetSymbolAddress((void**)&pv, g_v);
    cudaGetSymbolAddress((void**)&prnx, g_rnx);
    cudaGetSymbolAddress((void**)&prny, g_rny);
    cudaGetSymbolAddress((void**)&pt, g_t);
    cudaGetSymbolAddress((void**)&pa1, g_a1);
    cudaGetSymbolAddress((void**)&pa2, g_a2);
    cudaGetSymbolAddress((void**)&palpha, g_alpha);
    cudaGetSymbolAddress((void**)&pcm, g_cm);
    cudaGetSymbolAddress((void**)&prs, g_rs);
    cudaGetSymbolAddress((void**)&pscale, g_scale);
    cudaGetSymbolAddress((void**)&pshift, g_shift);
    cudaGetSymbolAddress((void**)&pps, g_ps);
    cudaGetSymbolAddress((void**)&ppq, g_pq);
    cudaGetSymbolAddress((void**)&pcTh, g_cTh);
    cudaGetSymbolAddress((void**)&pcTl, g_cTl);
    cudaGetSymbolAddress((void**)&psTh, g_sTh);
    cudaGetSymbolAddress((void**)&psTl, g_sTl);
    cudaGetSymbolAddress((void**)&psfh, g_sfh);
    cudaGetSymbolAddress((void**)&psfl, g_sfl);
    cudaGetSymbolAddress((void**)&ppih, g_pih);
    cudaGetSymbolAddress((void**)&ppil, g_pil);
    cudaGetSymbolAddress((void**)&ptth, g_tth);
    cudaGetSymbolAddress((void**)&pttl, g_ttl);
    cudaGetSymbolAddress((void**)&pb1h, g_b1h);
    cudaGetSymbolAddress((void**)&pb1l, g_b1l);
    cudaGetSymbolAddress((void**)&pb2h, g_b2h);
    cudaGetSymbolAddress((void**)&pb2l, g_b2l);
    cudaGetSymbolAddress((void**)&pw1h, g_w1h);
    cudaGetSymbolAddress((void**)&pw1l, g_w1l);
    cudaGetSymbolAddress((void**)&pw2h, g_w2h);
    cudaGetSymbolAddress((void**)&pw2l, g_w2l);
    cudaGetSymbolAddress((void**)&pw3h, g_w3h);
    cudaGetSymbolAddress((void**)&pw3l, g_w3l);

    cudaFuncSetAttribute(conv_hmma, cudaFuncAttributeMaxDynamicSharedMemorySize, CONV_SMEM);
    cudaFuncSetAttribute(hmma_gemm<1>, cudaFuncAttributeMaxDynamicSharedMemorySize, GEMM_SMEM);
    cudaFuncSetAttribute(hmma_gemm<2>, cudaFuncAttributeMaxDynamicSharedMemorySize, GEMM_SMEM);

    /* operand prep (transpose-split merged into megaprep) */
    megaprep<<<12048, 256>>>(style, psfh, psfl, content, pcm, prs,
                             w1, pw1h, pw1l, w2, pw2h, pw2l, w3, pw3h, pw3l, pv,
                             pcTh, pcTl, psTh, psTl);
    rownorm_t2<<<1024, 256>>>(pcTh, pcTl, psTh, psTl, prnx, prny);

    /* cosine-cost matrix (128x128 tiles, K-chunk 64), then C^T for v-pass */
    hmma_gemm<1><<<dim3(8, 8, 4), 256, GEMM_SMEM>>>(pcTh, pcTl, psTh, psTl,
        1024, 512, 1024, 1024, prnx, prny, pC, nullptr, nullptr);
    transC<<<dim3(32, 32, 4), 256>>>(pC, pCT);

    /* Sinkhorn, 20 iterations — both passes row-major LSE, 2 rows/block */
    for (int it = 0; it < 20; it++) {
        lse_update<<<dim3(512, 4), 256>>>(pC, pv, pu);    /* u pass */
        lse_update<<<dim3(512, 4), 256>>>(pCT, pu, pv);   /* v pass */
    }

    /* pi, then t = pi @ style^T -> NHWC fp32 + bf16 split */
    pi_gen<<<dim3(1024, 4), 256>>>(pC, pu, pv, ppih, ppil);
    hmma_gemm<2><<<dim3(8, 4, 4), 256, GEMM_SMEM>>>(ppih, ppil, psfh, psfl,
        1024, 1024, 512, 512, nullptr, nullptr, pt, ptth, pttl);

    /* alpha predictor via tensor convs (NHWC) */
    conv_hmma<<<dim3(32, 4), 256, CONV_SMEM>>>(ptth, pttl, pcTh, pcTl, 512, 1024,
        pw1h, pw1l, 256, b1, 1, pa1);
    bnpart<<<64, 256>>>(pa1, pps, ppq);
    bnfin<<<1, 256>>>(pps, ppq, g1, be1, pscale, pshift);
    bn_split<<<4096, 256>>>(pa1, pscale, pshift, pb1h, pb1l);
    conv_hmma<<<dim3(32, 4), 256, CONV_SMEM>>>(pb1h, pb1l, pb1h, pb1l, 256, 256,
        pw2h, pw2l, 256, b2, 1, pa2);
    bnpart<<<64, 256>>>(pa2, pps, ppq);
    bnfin<<<1, 256>>>(pps, ppq, g2, be2, pscale, pshift);
    bn_split<<<4096, 256>>>(pa2, pscale, pshift, pb2h, pb2l);
    conv_hmma<<<dim3(32, 8), 256, CONV_SMEM>>>(pb2h, pb2l, pb2h, pb2l, 256, 256,
        pw3h, pw3l, 512, b3, 0, palpha);

    /* blend (transposed to NCHW) + decoder bias init, then decoder conv */
    blend_T<<<2096, 256>>>(pt, palpha, content, pcm, prs, pC, db, out);
    conv3x3_dec<<<dim3(4, 8, 8), 128>>>(pC, dw, out);
}